// round 4
// baseline (speedup 1.0000x reference)
#include <cuda_runtime.h>
#include <cstdint>

#define NN 50000
#define NE 800000
#define INC 128
#define HD 256
#define NG 1024
#define BN_EPS 1e-5f
#define NB 196   // ceil(NN/256)

// ---------------- scratch (device globals: allocation-free) ----------------
__device__ int   g_deg[NN];
__device__ int   g_rowptr[NN];
__device__ int   g_cursor[NN];
__device__ int   g_bsum[NB];
__device__ int   g_srcs[NE];          // edge sources bucketed by dst
__device__ float g_dinv[NN];
__device__ float g_h[(size_t)NN * HD];
__device__ float g_u[(size_t)NN * HD];
__device__ float g_pool[NG * HD];
__device__ float g_z[NG * HD];
__device__ float g_sum[HD];
__device__ float g_sqs[HD];
__device__ float g_bnA[HD];
__device__ float g_bnB[HD];

// ---------------- degree / CSR setup ----------------
__global__ void zero_deg_kernel() {
    int i = blockIdx.x * blockDim.x + threadIdx.x;
    if (i < NN) { g_deg[i] = 0; g_cursor[i] = 0; }
}

__global__ void edge_deg_kernel(const int* __restrict__ dst) {
    int e = blockIdx.x * blockDim.x + threadIdx.x;
    if (e < NE) atomicAdd(&g_deg[dst[e]], 1);
}

__global__ void make_dinv_kernel() {
    int i = blockIdx.x * blockDim.x + threadIdx.x;
    if (i < NN) g_dinv[i] = rsqrtf((float)(g_deg[i] + 1));  // +1 self-loop
}

// scan pass 1: per-block scan of deg -> local exclusive rowptr, block totals
__global__ void scan1_kernel() {
    __shared__ int sh[256];
    int tid = threadIdx.x;
    int i = blockIdx.x * 256 + tid;
    int v = (i < NN) ? g_deg[i] : 0;
    sh[tid] = v;
    __syncthreads();
#pragma unroll
    for (int off = 1; off < 256; off <<= 1) {
        int t = (tid >= off) ? sh[tid - off] : 0;
        __syncthreads();
        sh[tid] += t;
        __syncthreads();
    }
    if (i < NN) g_rowptr[i] = sh[tid] - v;          // local exclusive
    if (tid == 255) g_bsum[blockIdx.x] = sh[255];   // block total
}

// scan pass 2: exclusive scan of block totals (single block)
__global__ void scan2_kernel() {
    __shared__ int sh[256];
    int tid = threadIdx.x;
    int v = (tid < NB) ? g_bsum[tid] : 0;
    sh[tid] = v;
    __syncthreads();
#pragma unroll
    for (int off = 1; off < 256; off <<= 1) {
        int t = (tid >= off) ? sh[tid - off] : 0;
        __syncthreads();
        sh[tid] += t;
        __syncthreads();
    }
    if (tid < NB) g_bsum[tid] = sh[tid] - v;        // exclusive block offset
}

// scan pass 3: add block offsets
__global__ void scan3_kernel() {
    int i = blockIdx.x * 256 + threadIdx.x;
    if (i < NN) g_rowptr[i] += g_bsum[blockIdx.x];
}

// bucket edges by dst (int atomics only; within-bucket order nondeterminism
// only permutes fp-sum order -> ~1e-7 noise, far under 1e-3 tolerance)
__global__ void bucket_kernel(const int* __restrict__ src,
                              const int* __restrict__ dst) {
    int e = blockIdx.x * blockDim.x + threadIdx.x;
    if (e >= NE) return;
    int d = dst[e];
    int pos = atomicAdd(&g_cursor[d], 1);
    g_srcs[g_rowptr[d] + pos] = src[e];
}

// ---------------- SGEMM: C[M,256] = A[M,K] @ B[K,256] (+ epilogues) --------
// MODE 0: C = A@B + bias
// MODE 1: C = (A@B) * g_dinv[row]
template <int MODE>
__global__ void __launch_bounds__(256) sgemm256(
    const float* __restrict__ A, const float* __restrict__ B,
    const float* __restrict__ bias, float* __restrict__ C, int M, int K)
{
    __shared__ float As[16][128];
    __shared__ float Bs[16][64];
    const int m0 = blockIdx.x * 128;
    const int n0 = blockIdx.y * 64;
    const int tid = threadIdx.x;
    const int tmg = tid >> 4;   // 0..15 -> 8 rows each
    const int tng = tid & 15;   // 0..15 -> 4 cols each

    float acc[8][4];
#pragma unroll
    for (int i = 0; i < 8; i++)
#pragma unroll
        for (int j = 0; j < 4; j++) acc[i][j] = 0.f;

    for (int k0 = 0; k0 < K; k0 += 16) {
#pragma unroll
        for (int t = 0; t < 2; t++) {
            int idx = tid + t * 256;
            int row = idx >> 2;
            int kv  = (idx & 3) << 2;
            float4 a;
            if (m0 + row < M)
                a = *(const float4*)(A + (size_t)(m0 + row) * K + k0 + kv);
            else
                a = make_float4(0.f, 0.f, 0.f, 0.f);
            As[kv + 0][row] = a.x;
            As[kv + 1][row] = a.y;
            As[kv + 2][row] = a.z;
            As[kv + 3][row] = a.w;
        }
        {
            int row = tid >> 4;
            int c4  = (tid & 15) << 2;
            *(float4*)&Bs[row][c4] =
                *(const float4*)(B + (size_t)(k0 + row) * HD + n0 + c4);
        }
        __syncthreads();
#pragma unroll
        for (int k = 0; k < 16; k++) {
            float4 a0 = *(const float4*)&As[k][tmg * 8];
            float4 a1 = *(const float4*)&As[k][tmg * 8 + 4];
            float4 bb = *(const float4*)&Bs[k][tng * 4];
            float av[8] = {a0.x, a0.y, a0.z, a0.w, a1.x, a1.y, a1.z, a1.w};
            float bv[4] = {bb.x, bb.y, bb.z, bb.w};
#pragma unroll
            for (int i = 0; i < 8; i++)
#pragma unroll
                for (int j = 0; j < 4; j++) acc[i][j] += av[i] * bv[j];
        }
        __syncthreads();
    }

    const int n = n0 + tng * 4;
#pragma unroll
    for (int i = 0; i < 8; i++) {
        int m = m0 + tmg * 8 + i;
        if (m >= M) break;
        float4 v = make_float4(acc[i][0], acc[i][1], acc[i][2], acc[i][3]);
        if (MODE == 0) {
            float4 b4 = *(const float4*)(bias + n);
            v.x += b4.x; v.y += b4.y; v.z += b4.z; v.w += b4.w;
        } else {
            float s = g_dinv[m];
            v.x *= s; v.y *= s; v.z *= s; v.w *= s;
        }
        *(float4*)(C + (size_t)m * HD + n) = v;
    }
}

// ---------------- aggregation: h[d] = (u[d] + sum u[src]) * dinv[d] + b ----
// One warp per destination node; register accumulators, no float atomics.
__global__ void __launch_bounds__(256) aggregate_kernel(const float* __restrict__ bias) {
    int node = blockIdx.x * 8 + (threadIdx.x >> 5);
    int lane = threadIdx.x & 31;
    if (node >= NN) return;

    const float4* up = (const float4*)g_u;
    float4 a0 = up[(size_t)node * 64 + lane];        // channels [lane*4, +4)
    float4 a1 = up[(size_t)node * 64 + 32 + lane];   // channels [128+lane*4, +4)

    int beg = g_rowptr[node];
    int end = beg + g_deg[node];
    for (int j = beg; j < end; j++) {
        int s = g_srcs[j];
        float4 b0 = up[(size_t)s * 64 + lane];
        float4 b1 = up[(size_t)s * 64 + 32 + lane];
        a0.x += b0.x; a0.y += b0.y; a0.z += b0.z; a0.w += b0.w;
        a1.x += b1.x; a1.y += b1.y; a1.z += b1.z; a1.w += b1.w;
    }

    float dv = g_dinv[node];
    float4 bb0 = ((const float4*)bias)[lane];
    float4 bb1 = ((const float4*)bias)[32 + lane];
    a0.x = a0.x * dv + bb0.x; a0.y = a0.y * dv + bb0.y;
    a0.z = a0.z * dv + bb0.z; a0.w = a0.w * dv + bb0.w;
    a1.x = a1.x * dv + bb1.x; a1.y = a1.y * dv + bb1.y;
    a1.z = a1.z * dv + bb1.z; a1.w = a1.w * dv + bb1.w;

    float4* hp = (float4*)g_h;
    hp[(size_t)node * 64 + lane] = a0;
    hp[(size_t)node * 64 + 32 + lane] = a1;
}

// ---------------- BN ----------------
__global__ void zero_stats_kernel() {
    int c = threadIdx.x;
    g_sum[c] = 0.f;
    g_sqs[c] = 0.f;
}

__global__ void __launch_bounds__(256) stats_cols_kernel(const float* __restrict__ X, int rows) {
    int c  = threadIdx.x;
    int r0 = blockIdx.x * 64;
    int r1 = min(r0 + 64, rows);
    float s = 0.f, s2 = 0.f;
    for (int r = r0; r < r1; r++) {
        float v = X[(size_t)r * HD + c];
        s += v;
        s2 += v * v;
    }
    atomicAdd(&g_sum[c], s);
    atomicAdd(&g_sqs[c], s2);
}

__global__ void bn_prep_kernel(const float* __restrict__ gamma,
                               const float* __restrict__ beta, float invN) {
    int c = threadIdx.x;
    float mu  = g_sum[c] * invN;
    float var = fmaxf(g_sqs[c] * invN - mu * mu, 0.f);
    float a   = gamma[c] * rsqrtf(var + BN_EPS);
    g_bnA[c] = a;
    g_bnB[c] = beta[c] - mu * a;
}

__global__ void __launch_bounds__(256) bn_apply_relu(float* __restrict__ X, int n4) {
    int i = blockIdx.x * 256 + threadIdx.x;
    if (i >= n4) return;
    int c4 = i & 63;
    float4 a = *(const float4*)&g_bnA[c4 * 4];
    float4 b = *(const float4*)&g_bnB[c4 * 4];
    float4 v = ((float4*)X)[i];
    v.x = fmaxf(v.x * a.x + b.x, 0.f);
    v.y = fmaxf(v.y * a.y + b.y, 0.f);
    v.z = fmaxf(v.z * a.z + b.z, 0.f);
    v.w = fmaxf(v.w * a.w + b.w, 0.f);
    ((float4*)X)[i] = v;
}

// ---------------- pooling (batch sorted -> binary search, no atomics) ------
__global__ void __launch_bounds__(256) pool_kernel(const int* __restrict__ batch) {
    int g = blockIdx.x;
    __shared__ int s_lo, s_hi;
    if (threadIdx.x < 2) {
        int key = g + threadIdx.x;
        int lo = 0, hi = NN;
        while (lo < hi) {
            int mid = (lo + hi) >> 1;
            if (batch[mid] < key) lo = mid + 1; else hi = mid;
        }
        if (threadIdx.x == 0) s_lo = lo; else s_hi = lo;
    }
    __syncthreads();
    int lo = s_lo, hi = s_hi;
    int c = threadIdx.x;
    float s = 0.f;
    for (int r = lo; r < hi; r++) s += g_h[(size_t)r * HD + c];
    float cnt = (float)(hi - lo);
    g_pool[g * HD + c] = s / fmaxf(cnt, 1.f);
}

// ---------------- head: out[g] = dot(z[g,:], W2) + b2 ----------------------
__global__ void __launch_bounds__(256) head_kernel(const float* __restrict__ W2,
                                                   const float* __restrict__ b2,
                                                   float* __restrict__ out) {
    int g    = (int)((blockIdx.x * 256 + threadIdx.x) >> 5);
    int lane = threadIdx.x & 31;
    if (g >= NG) return;
    const float4* zp = (const float4*)&g_z[(size_t)g * HD];
    const float4* wp = (const float4*)W2;
    float4 z0 = zp[lane], w0 = wp[lane];
    float4 z1 = zp[lane + 32], w1 = wp[lane + 32];
    float s = z0.x * w0.x + z0.y * w0.y + z0.z * w0.z + z0.w * w0.w +
              z1.x * w1.x + z1.y * w1.y + z1.z * w1.z + z1.w * w1.w;
#pragma unroll
    for (int o = 16; o > 0; o >>= 1) s += __shfl_xor_sync(0xffffffffu, s, o);
    if (lane == 0) out[g] = s + b2[0];
}

// ---------------- launch ----------------
extern "C" void kernel_launch(void* const* d_in, const int* in_sizes, int n_in,
                              void* d_out, int out_size)
{
    (void)in_sizes; (void)n_in; (void)out_size;
    const float* x        = (const float*)d_in[0];
    const int*   ei       = (const int*)d_in[1];     // int32! (JAX x64 disabled)
    const int*   batch    = (const int*)d_in[2];     // int32!
    const float* W_emb    = (const float*)d_in[3];
    const float* b_emb    = (const float*)d_in[4];
    const float* W_conv   = (const float*)d_in[5];
    const float* b_conv   = (const float*)d_in[6];
    const float* bn_gamma = (const float*)d_in[7];
    const float* bn_beta  = (const float*)d_in[8];
    const float* W1       = (const float*)d_in[9];
    const float* b1       = (const float*)d_in[10];
    const float* g2       = (const float*)d_in[11];
    const float* bt2      = (const float*)d_in[12];
    const float* W2       = (const float*)d_in[13];
    const float* b2       = (const float*)d_in[14];
    float*       out      = (float*)d_out;

    const int* src = ei;
    const int* dst = ei + NE;

    float *p_h, *p_u, *p_pool, *p_z;
    cudaGetSymbolAddress((void**)&p_h,    g_h);
    cudaGetSymbolAddress((void**)&p_u,    g_u);
    cudaGetSymbolAddress((void**)&p_pool, g_pool);
    cudaGetSymbolAddress((void**)&p_z,    g_z);

    // CSR setup
    zero_deg_kernel<<<(NN + 255) / 256, 256>>>();
    edge_deg_kernel<<<(NE + 255) / 256, 256>>>(dst);
    scan1_kernel<<<NB, 256>>>();
    scan2_kernel<<<1, 256>>>();
    scan3_kernel<<<NB, 256>>>();
    make_dinv_kernel<<<(NN + 255) / 256, 256>>>();
    bucket_kernel<<<(NE + 255) / 256, 256>>>(src, dst);

    // embedding: h = x @ W_emb + b_emb
    sgemm256<0><<<dim3((NN + 127) / 128, HD / 64), 256>>>(
        x, W_emb, b_emb, p_h, NN, INC);

    // GCN layers
    for (int l = 0; l < 3; l++) {
        sgemm256<1><<<dim3((NN + 127) / 128, HD / 64), 256>>>(
            p_h, W_conv + (size_t)l * HD * HD, nullptr, p_u, NN, HD);
        aggregate_kernel<<<(NN + 7) / 8, 256>>>(b_conv + (size_t)l * HD);
        zero_stats_kernel<<<1, HD>>>();
        stats_cols_kernel<<<(NN + 63) / 64, 256>>>(p_h, NN);
        bn_prep_kernel<<<1, HD>>>(bn_gamma + (size_t)l * HD,
                                  bn_beta + (size_t)l * HD, 1.0f / NN);
        bn_apply_relu<<<(NN * (HD / 4) + 255) / 256, 256>>>(p_h, NN * (HD / 4));
    }

    // pooling
    pool_kernel<<<NG, HD>>>(batch);

    // MLP head
    sgemm256<0><<<dim3((NG + 127) / 128, HD / 64), 256>>>(
        p_pool, W1, b1, p_z, NG, HD);
    zero_stats_kernel<<<1, HD>>>();
    stats_cols_kernel<<<(NG + 63) / 64, 256>>>(p_z, NG);
    bn_prep_kernel<<<1, HD>>>(g2, bt2, 1.0f / NG);
    bn_apply_relu<<<(NG * (HD / 4) + 255) / 256, 256>>>(p_z, NG * (HD / 4));
    head_kernel<<<(NG * 32 + 255) / 256, 256>>>(W2, b2, out);
}

// round 7
// speedup vs baseline: 1.0996x; 1.0996x over previous
#include <cuda_runtime.h>
#include <cstdint>

#define NN 50000
#define NE 800000
#define INC 128
#define HD 256
#define NG 1024
#define BN_EPS 1e-5f
#define NB 196   // ceil(NN/256)

// ---------------- scratch (device globals: allocation-free) ----------------
__device__ int   g_deg[NN];
__device__ int   g_rowptr[NN];
__device__ int   g_cursor[NN];
__device__ int   g_bsum[NB];
__device__ int   g_srcs[NE];          // edge sources bucketed by dst
__device__ float g_dinv[NN];
__device__ float g_h[(size_t)NN * HD];
__device__ float g_u[(size_t)NN * HD];
__device__ float g_pool[NG * HD];
__device__ float g_z[NG * HD];
__device__ float g_sum[HD];
__device__ float g_sqs[HD];
__device__ float g_bnA[HD];
__device__ float g_bnB[HD];

// ---------------- f32x2 helpers (sm_100+ packed fp32) ----------------
__device__ __forceinline__ unsigned long long ffma2(
    unsigned long long a, unsigned long long b, unsigned long long c) {
    unsigned long long d;
    asm("fma.rn.f32x2 %0, %1, %2, %3;" : "=l"(d) : "l"(a), "l"(b), "l"(c));
    return d;
}
__device__ __forceinline__ unsigned long long pack2(float a) {
    unsigned long long p;
    asm("mov.b64 %0, {%1, %1};" : "=l"(p) : "f"(a));
    return p;
}
__device__ __forceinline__ float2 unpack2(unsigned long long u) {
    float2 f;
    asm("mov.b64 {%0, %1}, %2;" : "=f"(f.x), "=f"(f.y) : "l"(u));
    return f;
}

// ---------------- degree / CSR setup ----------------
__global__ void zero_deg_kernel() {
    int i = blockIdx.x * blockDim.x + threadIdx.x;
    if (i < NN) { g_deg[i] = 0; g_cursor[i] = 0; }
}

__global__ void edge_deg_kernel(const int* __restrict__ dst) {
    int e = blockIdx.x * blockDim.x + threadIdx.x;
    if (e < NE) atomicAdd(&g_deg[dst[e]], 1);
}

__global__ void make_dinv_kernel() {
    int i = blockIdx.x * blockDim.x + threadIdx.x;
    if (i < NN) g_dinv[i] = rsqrtf((float)(g_deg[i] + 1));  // +1 self-loop
}

__global__ void scan1_kernel() {
    __shared__ int sh[256];
    int tid = threadIdx.x;
    int i = blockIdx.x * 256 + tid;
    int v = (i < NN) ? g_deg[i] : 0;
    sh[tid] = v;
    __syncthreads();
#pragma unroll
    for (int off = 1; off < 256; off <<= 1) {
        int t = (tid >= off) ? sh[tid - off] : 0;
        __syncthreads();
        sh[tid] += t;
        __syncthreads();
    }
    if (i < NN) g_rowptr[i] = sh[tid] - v;
    if (tid == 255) g_bsum[blockIdx.x] = sh[255];
}

__global__ void scan2_kernel() {
    __shared__ int sh[256];
    int tid = threadIdx.x;
    int v = (tid < NB) ? g_bsum[tid] : 0;
    sh[tid] = v;
    __syncthreads();
#pragma unroll
    for (int off = 1; off < 256; off <<= 1) {
        int t = (tid >= off) ? sh[tid - off] : 0;
        __syncthreads();
        sh[tid] += t;
        __syncthreads();
    }
    if (tid < NB) g_bsum[tid] = sh[tid] - v;
}

__global__ void scan3_kernel() {
    int i = blockIdx.x * 256 + threadIdx.x;
    if (i < NN) g_rowptr[i] += g_bsum[blockIdx.x];
}

__global__ void bucket_kernel(const int* __restrict__ src,
                              const int* __restrict__ dst) {
    int e = blockIdx.x * blockDim.x + threadIdx.x;
    if (e >= NE) return;
    int d = dst[e];
    int pos = atomicAdd(&g_cursor[d], 1);
    g_srcs[g_rowptr[d] + pos] = src[e];
}

// ---------------- GEMM: C[M,256] = A'[M,K] @ B[K,256] via fma.rn.f32x2 ----
// A' = BN_IN ? relu(bnA[k]*A + bnB[k]) : A       (fused BN+ReLU of prev layer)
// C  = DINV_OUT ? (A'@B)*dinv[row] : A'@B + bias
// 128x128 tile, 128 threads, 16x8 microtile (4 f32x2 col-pairs per thread).
#define ASTRIDE 132
template <bool BN_IN, bool DINV_OUT>
__global__ void __launch_bounds__(128, 2) gemm2(
    const float* __restrict__ A, const float* __restrict__ B,
    const float* __restrict__ bias, float* __restrict__ C, int M, int K)
{
    __shared__ float As[16 * ASTRIDE];
    __shared__ float Bs[16 * ASTRIDE];
    const int m0 = blockIdx.x * 128;
    const int n0 = blockIdx.y * 128;
    const int tid = threadIdx.x;
    const int tn = tid & 15;    // 16 threads x 8 cols  = 128 n
    const int tm = tid >> 4;    // 8  threads x 16 rows = 128 m

    unsigned long long acc[16][4];
#pragma unroll
    for (int i = 0; i < 16; i++)
#pragma unroll
        for (int j = 0; j < 4; j++) acc[i][j] = 0ull;

    for (int k0 = 0; k0 < K; k0 += 16) {
        // A tile: 128 rows x 16 k, transposed into As[k*ASTRIDE + m]
#pragma unroll
        for (int t = 0; t < 4; t++) {
            int idx = tid + t * 128;
            int row = idx >> 2;
            int kv  = (idx & 3) << 2;
            float4 a;
            if (m0 + row < M)
                a = *(const float4*)(A + (size_t)(m0 + row) * K + k0 + kv);
            else
                a = make_float4(0.f, 0.f, 0.f, 0.f);
            if (BN_IN) {
                float4 s = *(const float4*)&g_bnA[k0 + kv];
                float4 o = *(const float4*)&g_bnB[k0 + kv];
                a.x = fmaxf(fmaf(a.x, s.x, o.x), 0.f);
                a.y = fmaxf(fmaf(a.y, s.y, o.y), 0.f);
                a.z = fmaxf(fmaf(a.z, s.z, o.z), 0.f);
                a.w = fmaxf(fmaf(a.w, s.w, o.w), 0.f);
            }
            As[(kv + 0) * ASTRIDE + row] = a.x;
            As[(kv + 1) * ASTRIDE + row] = a.y;
            As[(kv + 2) * ASTRIDE + row] = a.z;
            As[(kv + 3) * ASTRIDE + row] = a.w;
        }
        // B tile: 16 k x 128 n
#pragma unroll
        for (int t = 0; t < 4; t++) {
            int idx = tid + t * 128;
            int r  = idx >> 5;
            int c4 = (idx & 31) << 2;
            *(float4*)&Bs[r * ASTRIDE + c4] =
                *(const float4*)(B + (size_t)(k0 + r) * HD + n0 + c4);
        }
        __syncthreads();
#pragma unroll
        for (int k = 0; k < 16; k++) {
            ulonglong2 b01 = *(const ulonglong2*)&Bs[k * ASTRIDE + tn * 8];
            ulonglong2 b23 = *(const ulonglong2*)&Bs[k * ASTRIDE + tn * 8 + 4];
            unsigned long long bv0 = b01.x, bv1 = b01.y, bv2 = b23.x, bv3 = b23.y;
#pragma unroll
            for (int q = 0; q < 4; q++) {
                float4 av = *(const float4*)&As[k * ASTRIDE + tm * 16 + q * 4];
                unsigned long long p;
                p = pack2(av.x);
                acc[q*4+0][0] = ffma2(p, bv0, acc[q*4+0][0]);
                acc[q*4+0][1] = ffma2(p, bv1, acc[q*4+0][1]);
                acc[q*4+0][2] = ffma2(p, bv2, acc[q*4+0][2]);
                acc[q*4+0][3] = ffma2(p, bv3, acc[q*4+0][3]);
                p = pack2(av.y);
                acc[q*4+1][0] = ffma2(p, bv0, acc[q*4+1][0]);
                acc[q*4+1][1] = ffma2(p, bv1, acc[q*4+1][1]);
                acc[q*4+1][2] = ffma2(p, bv2, acc[q*4+1][2]);
                acc[q*4+1][3] = ffma2(p, bv3, acc[q*4+1][3]);
                p = pack2(av.z);
                acc[q*4+2][0] = ffma2(p, bv0, acc[q*4+2][0]);
                acc[q*4+2][1] = ffma2(p, bv1, acc[q*4+2][1]);
                acc[q*4+2][2] = ffma2(p, bv2, acc[q*4+2][2]);
                acc[q*4+2][3] = ffma2(p, bv3, acc[q*4+2][3]);
                p = pack2(av.w);
                acc[q*4+3][0] = ffma2(p, bv0, acc[q*4+3][0]);
                acc[q*4+3][1] = ffma2(p, bv1, acc[q*4+3][1]);
                acc[q*4+3][2] = ffma2(p, bv2, acc[q*4+3][2]);
                acc[q*4+3][3] = ffma2(p, bv3, acc[q*4+3][3]);
            }
        }
        __syncthreads();
    }

    const int n = n0 + tn * 8;
    float4 bb0, bb1;
    if (!DINV_OUT) {
        bb0 = *(const float4*)(bias + n);
        bb1 = *(const float4*)(bias + n + 4);
    }
#pragma unroll
    for (int i = 0; i < 16; i++) {
        int m = m0 + tm * 16 + i;
        if (m < M) {
            float2 p0 = unpack2(acc[i][0]);
            float2 p1 = unpack2(acc[i][1]);
            float2 p2 = unpack2(acc[i][2]);
            float2 p3 = unpack2(acc[i][3]);
            float4 v0 = make_float4(p0.x, p0.y, p1.x, p1.y);
            float4 v1 = make_float4(p2.x, p2.y, p3.x, p3.y);
            if (DINV_OUT) {
                float s = g_dinv[m];
                v0.x *= s; v0.y *= s; v0.z *= s; v0.w *= s;
                v1.x *= s; v1.y *= s; v1.z *= s; v1.w *= s;
            } else {
                v0.x += bb0.x; v0.y += bb0.y; v0.z += bb0.z; v0.w += bb0.w;
                v1.x += bb1.x; v1.y += bb1.y; v1.z += bb1.z; v1.w += bb1.w;
            }
            *(float4*)(C + (size_t)m * HD + n)     = v0;
            *(float4*)(C + (size_t)m * HD + n + 4) = v1;
        }
    }
}

// ---- aggregation + fused BN stats: h_raw[d] = (u[d]+sum u[src])*dinv + b --
// 8 warps/block, 8 nodes/warp; register stat partials -> smem -> global.
__global__ void __launch_bounds__(256) aggregate_kernel(const float* __restrict__ bias) {
    __shared__ float ssum[HD];
    __shared__ float ssqs[HD];
    for (int i = threadIdx.x; i < HD; i += 256) { ssum[i] = 0.f; ssqs[i] = 0.f; }
    __syncthreads();

    int warp = threadIdx.x >> 5;
    int lane = threadIdx.x & 31;
    int base = blockIdx.x * 64 + warp * 8;

    float4 bb0 = ((const float4*)bias)[lane];
    float4 bb1 = ((const float4*)bias)[32 + lane];
    float4 s0 = make_float4(0,0,0,0), q0 = s0, s1 = s0, q1 = s0;

    const float4* up = (const float4*)g_u;
    float4* hp = (float4*)g_h;

    for (int nidx = 0; nidx < 8; nidx++) {
        int node = base + nidx;
        if (node >= NN) break;
        float4 a0 = up[(size_t)node * 64 + lane];
        float4 a1 = up[(size_t)node * 64 + 32 + lane];
        int beg = g_rowptr[node];
        int end = beg + g_deg[node];
        for (int j = beg; j < end; j++) {
            int s = g_srcs[j];
            float4 b0 = up[(size_t)s * 64 + lane];
            float4 b1 = up[(size_t)s * 64 + 32 + lane];
            a0.x += b0.x; a0.y += b0.y; a0.z += b0.z; a0.w += b0.w;
            a1.x += b1.x; a1.y += b1.y; a1.z += b1.z; a1.w += b1.w;
        }
        float dv = g_dinv[node];
        a0.x = fmaf(a0.x, dv, bb0.x); a0.y = fmaf(a0.y, dv, bb0.y);
        a0.z = fmaf(a0.z, dv, bb0.z); a0.w = fmaf(a0.w, dv, bb0.w);
        a1.x = fmaf(a1.x, dv, bb1.x); a1.y = fmaf(a1.y, dv, bb1.y);
        a1.z = fmaf(a1.z, dv, bb1.z); a1.w = fmaf(a1.w, dv, bb1.w);
        hp[(size_t)node * 64 + lane]      = a0;
        hp[(size_t)node * 64 + 32 + lane] = a1;
        s0.x += a0.x; s0.y += a0.y; s0.z += a0.z; s0.w += a0.w;
        q0.x += a0.x*a0.x; q0.y += a0.y*a0.y; q0.z += a0.z*a0.z; q0.w += a0.w*a0.w;
        s1.x += a1.x; s1.y += a1.y; s1.z += a1.z; s1.w += a1.w;
        q1.x += a1.x*a1.x; q1.y += a1.y*a1.y; q1.z += a1.z*a1.z; q1.w += a1.w*a1.w;
    }

    int c0 = lane * 4, c1 = 128 + lane * 4;
    atomicAdd(&ssum[c0+0], s0.x); atomicAdd(&ssum[c0+1], s0.y);
    atomicAdd(&ssum[c0+2], s0.z); atomicAdd(&ssum[c0+3], s0.w);
    atomicAdd(&ssum[c1+0], s1.x); atomicAdd(&ssum[c1+1], s1.y);
    atomicAdd(&ssum[c1+2], s1.z); atomicAdd(&ssum[c1+3], s1.w);
    atomicAdd(&ssqs[c0+0], q0.x); atomicAdd(&ssqs[c0+1], q0.y);
    atomicAdd(&ssqs[c0+2], q0.z); atomicAdd(&ssqs[c0+3], q0.w);
    atomicAdd(&ssqs[c1+0], q1.x); atomicAdd(&ssqs[c1+1], q1.y);
    atomicAdd(&ssqs[c1+2], q1.z); atomicAdd(&ssqs[c1+3], q1.w);
    __syncthreads();
    atomicAdd(&g_sum[threadIdx.x], ssum[threadIdx.x]);
    atomicAdd(&g_sqs[threadIdx.x], ssqs[threadIdx.x]);
}

// ---------------- BN ----------------
__global__ void zero_stats_kernel() {
    int c = threadIdx.x;
    g_sum[c] = 0.f;
    g_sqs[c] = 0.f;
}

__global__ void __launch_bounds__(256) stats_cols_kernel(const float* __restrict__ X, int rows) {
    int c  = threadIdx.x;
    int r0 = blockIdx.x * 64;
    int r1 = min(r0 + 64, rows);
    float s = 0.f, s2 = 0.f;
    for (int r = r0; r < r1; r++) {
        float v = X[(size_t)r * HD + c];
        s += v;
        s2 += v * v;
    }
    atomicAdd(&g_sum[c], s);
    atomicAdd(&g_sqs[c], s2);
}

__global__ void bn_prep_kernel(const float* __restrict__ gamma,
                               const float* __restrict__ beta, float invN) {
    int c = threadIdx.x;
    float mu  = g_sum[c] * invN;
    float var = fmaxf(g_sqs[c] * invN - mu * mu, 0.f);
    float a   = gamma[c] * rsqrtf(var + BN_EPS);
    g_bnA[c] = a;
    g_bnB[c] = beta[c] - mu * a;
}

__global__ void __launch_bounds__(256) bn_apply_relu(float* __restrict__ X, int n4) {
    int i = blockIdx.x * 256 + threadIdx.x;
    if (i >= n4) return;
    int c4 = i & 63;
    float4 a = *(const float4*)&g_bnA[c4 * 4];
    float4 b = *(const float4*)&g_bnB[c4 * 4];
    float4 v = ((float4*)X)[i];
    v.x = fmaxf(fmaf(v.x, a.x, b.x), 0.f);
    v.y = fmaxf(fmaf(v.y, a.y, b.y), 0.f);
    v.z = fmaxf(fmaf(v.z, a.z, b.z), 0.f);
    v.w = fmaxf(fmaf(v.w, a.w, b.w), 0.f);
    ((float4*)X)[i] = v;
}

// ---- pooling with fused BN+ReLU of the last conv layer (batch sorted) ----
__global__ void __launch_bounds__(256) pool_kernel(const int* __restrict__ batch) {
    int g = blockIdx.x;
    __shared__ int s_lo, s_hi;
    if (threadIdx.x < 2) {
        int key = g + threadIdx.x;
        int lo = 0, hi = NN;
        while (lo < hi) {
            int mid = (lo + hi) >> 1;
            if (batch[mid] < key) lo = mid + 1; else hi = mid;
        }
        if (threadIdx.x == 0) s_lo = lo; else s_hi = lo;
    }
    __syncthreads();
    int lo = s_lo, hi = s_hi;
    int c = threadIdx.x;
    float a = g_bnA[c], b = g_bnB[c];
    float s = 0.f;
    for (int r = lo; r < hi; r++)
        s += fmaxf(fmaf(g_h[(size_t)r * HD + c], a, b), 0.f);
    float cnt = (float)(hi - lo);
    g_pool[g * HD + c] = s / fmaxf(cnt, 1.f);
}

// ---------------- head: out[g] = dot(z[g,:], W2) + b2 ----------------------
__global__ void __launch_bounds__(256) head_kernel(const float* __restrict__ W2,
                                                   const float* __restrict__ b2,
                                                   float* __restrict__ out) {
    int g    = (int)((blockIdx.x * 256 + threadIdx.x) >> 5);
    int lane = threadIdx.x & 31;
    if (g >= NG) return;
    const float4* zp = (const float4*)&g_z[(size_t)g * HD];
    const float4* wp = (const float4*)W2;
    float4 z0 = zp[lane], w0 = wp[lane];
    float4 z1 = zp[lane + 32], w1 = wp[lane + 32];
    float s = z0.x * w0.x + z0.y * w0.y + z0.z * w0.z + z0.w * w0.w +
              z1.x * w1.x + z1.y * w1.y + z1.z * w1.z + z1.w * w1.w;
#pragma unroll
    for (int o = 16; o > 0; o >>= 1) s += __shfl_xor_sync(0xffffffffu, s, o);
    if (lane == 0) out[g] = s + b2[0];
}

// ---------------- launch ----------------
extern "C" void kernel_launch(void* const* d_in, const int* in_sizes, int n_in,
                              void* d_out, int out_size)
{
    (void)in_sizes; (void)n_in; (void)out_size;
    const float* x        = (const float*)d_in[0];
    const int*   ei       = (const int*)d_in[1];     // int32 (JAX x64 disabled)
    const int*   batch    = (const int*)d_in[2];
    const float* W_emb    = (const float*)d_in[3];
    const float* b_emb    = (const float*)d_in[4];
    const float* W_conv   = (const float*)d_in[5];
    const float* b_conv   = (const float*)d_in[6];
    const float* bn_gamma = (const float*)d_in[7];
    const float* bn_beta  = (const float*)d_in[8];
    const float* W1       = (const float*)d_in[9];
    const float* b1       = (const float*)d_in[10];
    const float* g2       = (const float*)d_in[11];
    const float* bt2      = (const float*)d_in[12];
    const float* W2       = (const float*)d_in[13];
    const float* b2       = (const float*)d_in[14];
    float*       out      = (float*)d_out;

    const int* src = ei;
    const int* dst = ei + NE;

    float *p_h, *p_u, *p_pool, *p_z;
    cudaGetSymbolAddress((void**)&p_h,    g_h);
    cudaGetSymbolAddress((void**)&p_u,    g_u);
    cudaGetSymbolAddress((void**)&p_pool, g_pool);
    cudaGetSymbolAddress((void**)&p_z,    g_z);

    const dim3 gemm_grid((NN + 127) / 128, HD / 128);   // 391 x 2

    // CSR setup
    zero_deg_kernel<<<(NN + 255) / 256, 256>>>();
    edge_deg_kernel<<<(NE + 255) / 256, 256>>>(dst);
    scan1_kernel<<<NB, 256>>>();
    scan2_kernel<<<1, 256>>>();
    scan3_kernel<<<NB, 256>>>();
    make_dinv_kernel<<<(NN + 255) / 256, 256>>>();
    bucket_kernel<<<(NE + 255) / 256, 256>>>(src, dst);

    // embedding: h = x @ W_emb + b_emb
    gemm2<false, false><<<gemm_grid, 128>>>(x, W_emb, b_emb, p_h, NN, INC);

    // GCN layers: gemm (BN of prev layer fused into A-load for l>0),
    // aggregate writes raw conv output + accumulates BN stats, bn_prep folds.
    for (int l = 0; l < 3; l++) {
        if (l == 0)
            gemm2<false, true><<<gemm_grid, 128>>>(
                p_h, W_conv, nullptr, p_u, NN, HD);
        else
            gemm2<true, true><<<gemm_grid, 128>>>(
                p_h, W_conv + (size_t)l * HD * HD, nullptr, p_u, NN, HD);
        zero_stats_kernel<<<1, HD>>>();
        aggregate_kernel<<<(NN + 63) / 64, 256>>>(b_conv + (size_t)l * HD);
        bn_prep_kernel<<<1, HD>>>(bn_gamma + (size_t)l * HD,
                                  bn_beta + (size_t)l * HD, 1.0f / NN);
    }

    // pooling (applies layer-2 BN+ReLU on the fly)
    pool_kernel<<<NG, HD>>>(batch);

    // MLP head
    gemm2<false, false><<<dim3(NG / 128, HD / 128), 128>>>(
        p_pool, W1, b1, p_z, NG, HD);
    zero_stats_kernel<<<1, HD>>>();
    stats_cols_kernel<<<(NG + 63) / 64, 256>>>(p_z, NG);
    bn_prep_kernel<<<1, HD>>>(g2, bt2, 1.0f / NG);
    bn_apply_relu<<<(NG * (HD / 4) + 255) / 256, 256>>>(p_z, NG * (HD / 4));
    head_kernel<<<(NG * 32 + 255) / 256, 256>>>(W2, b2, out);
}

// round 9
// speedup vs baseline: 1.4225x; 1.2937x over previous
#include <cuda_runtime.h>
#include <cuda_bf16.h>
#include <cstdint>

#define NN 50000
#define MPAD 50048          // 391 * 128
#define NE 800000
#define INC 128
#define HD 256
#define NG 1024
#define BN_EPS 1e-5f
#define NB 196              // ceil(NN/256)

// ---------------- scratch (device globals: allocation-free) ----------------
__device__ int   g_deg[NN];
__device__ int   g_rowptr[NN];
__device__ int   g_cursor[NN];
__device__ int   g_bsum[NB];
__device__ int   g_srcs[NE];
__device__ float g_dinv[NN];
__device__ float g_h[(size_t)MPAD * HD];
__device__ float g_u[(size_t)MPAD * HD];
__device__ float g_pool[NG * HD];
__device__ float g_z[NG * HD];
__device__ float g_sum[HD];
__device__ float g_sqs[HD];
__device__ float g_bnA[HD];
__device__ float g_bnB[HD];
__device__ __nv_bfloat16 g_Ah[(size_t)MPAD * HD];
__device__ __nv_bfloat16 g_Al[(size_t)MPAD * HD];
__device__ __nv_bfloat16 g_Bh[HD * HD];
__device__ __nv_bfloat16 g_Bl[HD * HD];

// ---------------- degree / CSR setup ----------------
__global__ void zero_deg_kernel() {
    int i = blockIdx.x * blockDim.x + threadIdx.x;
    if (i < NN) { g_deg[i] = 0; g_cursor[i] = 0; }
}
__global__ void edge_deg_kernel(const int* __restrict__ dst) {
    int e = blockIdx.x * blockDim.x + threadIdx.x;
    if (e < NE) atomicAdd(&g_deg[dst[e]], 1);
}
__global__ void make_dinv_kernel() {
    int i = blockIdx.x * blockDim.x + threadIdx.x;
    if (i < NN) g_dinv[i] = rsqrtf((float)(g_deg[i] + 1));
}
__global__ void scan1_kernel() {
    __shared__ int sh[256];
    int tid = threadIdx.x;
    int i = blockIdx.x * 256 + tid;
    int v = (i < NN) ? g_deg[i] : 0;
    sh[tid] = v;
    __syncthreads();
#pragma unroll
    for (int off = 1; off < 256; off <<= 1) {
        int t = (tid >= off) ? sh[tid - off] : 0;
        __syncthreads();
        sh[tid] += t;
        __syncthreads();
    }
    if (i < NN) g_rowptr[i] = sh[tid] - v;
    if (tid == 255) g_bsum[blockIdx.x] = sh[255];
}
__global__ void scan2_kernel() {
    __shared__ int sh[256];
    int tid = threadIdx.x;
    int v = (tid < NB) ? g_bsum[tid] : 0;
    sh[tid] = v;
    __syncthreads();
#pragma unroll
    for (int off = 1; off < 256; off <<= 1) {
        int t = (tid >= off) ? sh[tid - off] : 0;
        __syncthreads();
        sh[tid] += t;
        __syncthreads();
    }
    if (tid < NB) g_bsum[tid] = sh[tid] - v;
}
__global__ void scan3_kernel() {
    int i = blockIdx.x * 256 + threadIdx.x;
    if (i < NN) g_rowptr[i] += g_bsum[blockIdx.x];
}
__global__ void bucket_kernel(const int* __restrict__ src,
                              const int* __restrict__ dst) {
    int e = blockIdx.x * blockDim.x + threadIdx.x;
    if (e >= NE) return;
    int d = dst[e];
    int pos = atomicAdd(&g_cursor[d], 1);
    g_srcs[g_rowptr[d] + pos] = src[e];
}

// ------- split fp32 -> (hi, lo) bf16, optional fused BN+ReLU, zero-pad -----
__global__ void __launch_bounds__(256) split_kernel(
    const float* __restrict__ X, int rows_src, int n4, int total4, int bn)
{
    int idx = blockIdx.x * 256 + threadIdx.x;
    if (idx >= total4) return;
    int row = idx / n4;
    float4 v = make_float4(0.f, 0.f, 0.f, 0.f);
    if (row < rows_src) {
        v = ((const float4*)X)[idx];
        if (bn) {
            int c4 = (idx % n4) * 4;
            float4 a = *(const float4*)&g_bnA[c4];
            float4 b = *(const float4*)&g_bnB[c4];
            v.x = fmaxf(fmaf(v.x, a.x, b.x), 0.f);
            v.y = fmaxf(fmaf(v.y, a.y, b.y), 0.f);
            v.z = fmaxf(fmaf(v.z, a.z, b.z), 0.f);
            v.w = fmaxf(fmaf(v.w, a.w, b.w), 0.f);
        }
    }
    __nv_bfloat16 hx = __float2bfloat16(v.x), hy = __float2bfloat16(v.y);
    __nv_bfloat16 hz = __float2bfloat16(v.z), hw = __float2bfloat16(v.w);
    __nv_bfloat16 lx = __float2bfloat16(v.x - __bfloat162float(hx));
    __nv_bfloat16 ly = __float2bfloat16(v.y - __bfloat162float(hy));
    __nv_bfloat16 lz = __float2bfloat16(v.z - __bfloat162float(hz));
    __nv_bfloat16 lw = __float2bfloat16(v.w - __bfloat162float(hw));
    ((__nv_bfloat162*)g_Ah)[idx * 2 + 0] = __nv_bfloat162(hx, hy);
    ((__nv_bfloat162*)g_Ah)[idx * 2 + 1] = __nv_bfloat162(hz, hw);
    ((__nv_bfloat162*)g_Al)[idx * 2 + 0] = __nv_bfloat162(lx, ly);
    ((__nv_bfloat162*)g_Al)[idx * 2 + 1] = __nv_bfloat162(lz, lw);
}

// ------- split + transpose weights: W[K, 256] -> Bh/Bl[n=256][k=K] --------
__global__ void __launch_bounds__(256) splitW_kernel(
    const float* __restrict__ W, int K)
{
    int idx = blockIdx.x * 256 + threadIdx.x;
    int k = idx >> 8;
    int n = idx & 255;
    if (k >= K) return;
    float v = W[k * HD + n];
    __nv_bfloat16 h = __float2bfloat16(v);
    __nv_bfloat16 l = __float2bfloat16(v - __bfloat162float(h));
    g_Bh[n * K + k] = h;
    g_Bl[n * K + k] = l;
}

// -------- warp-MMA GEMM: C[M,256] = (Ah+Al)[M,K] @ (Bh+Bl)^T --------------
// mma.sync.m16n8k16 bf16, fp32 accum; 3-product Markidis split.
// CTA 256 thr = 8 warps (4m x 2n), tile 128x128, K chunked by 64.
// EPI 0: C = A@B + bias      EPI 1: C = (A@B) * g_dinv[row]
__device__ __forceinline__ void mma16816(float* d,
    uint32_t a0, uint32_t a1, uint32_t a2, uint32_t a3,
    uint32_t b0, uint32_t b1)
{
    asm volatile(
        "mma.sync.aligned.m16n8k16.row.col.f32.bf16.bf16.f32 "
        "{%0,%1,%2,%3}, {%4,%5,%6,%7}, {%8,%9}, {%0,%1,%2,%3};"
        : "+f"(d[0]), "+f"(d[1]), "+f"(d[2]), "+f"(d[3])
        : "r"(a0), "r"(a1), "r"(a2), "r"(a3), "r"(b0), "r"(b1));
}

#define SROW 72                        // bf16 stride (144B rows; conflict-free)
#define MG_TS (128 * SROW)
#define MG_SMEM (4 * MG_TS * 2)        // 73728 bytes

template <int EPI>
__global__ void __launch_bounds__(256) mgemm(
    const __nv_bfloat16* __restrict__ Ah, const __nv_bfloat16* __restrict__ Al,
    const __nv_bfloat16* __restrict__ Bh, const __nv_bfloat16* __restrict__ Bl,
    const float* __restrict__ bias, float* __restrict__ C, int M, int K)
{
    extern __shared__ __nv_bfloat16 sm[];
    __nv_bfloat16* sAh = sm;
    __nv_bfloat16* sAl = sm + MG_TS;
    __nv_bfloat16* sBh = sm + 2 * MG_TS;
    __nv_bfloat16* sBl = sm + 3 * MG_TS;

    const int tid  = threadIdx.x;
    const int lane = tid & 31;
    const int warp = tid >> 5;
    const int wm   = warp & 3;      // 4 m-warps x 32 rows
    const int wn   = warp >> 2;     // 2 n-warps x 64 cols
    const int m0   = blockIdx.x * 128;
    const int n0   = blockIdx.y * 128;
    const int lr   = lane >> 2;           // 0..7
    const int lc   = (lane & 3) * 2;      // 0,2,4,6

    float acc[2][8][4];
#pragma unroll
    for (int i = 0; i < 2; i++)
#pragma unroll
        for (int j = 0; j < 8; j++)
#pragma unroll
            for (int q = 0; q < 4; q++) acc[i][j][q] = 0.f;

    for (int k0 = 0; k0 < K; k0 += 64) {
#pragma unroll
        for (int t = 0; t < 4; t++) {
            int idx = tid + t * 256;       // 0..1023
            int row = idx >> 3;            // 0..127
            int seg = idx & 7;             // 16B segments (8 per 64-bf16 row)
            size_t ga = (size_t)(m0 + row) * K + k0 + seg * 8;
            size_t gb = (size_t)(n0 + row) * K + k0 + seg * 8;
            uint32_t so = row * (SROW * 2) + seg * 16;
            *(uint4*)((char*)sAh + so) = *(const uint4*)(Ah + ga);
            *(uint4*)((char*)sAl + so) = *(const uint4*)(Al + ga);
            *(uint4*)((char*)sBh + so) = *(const uint4*)(Bh + gb);
            *(uint4*)((char*)sBl + so) = *(const uint4*)(Bl + gb);
        }
        __syncthreads();
#pragma unroll
        for (int ks = 0; ks < 4; ks++) {
            const int kk = ks * 16 + lc;
            uint32_t ah[2][4], al[2][4], bh[8][2], bl[8][2];
#pragma unroll
            for (int mi = 0; mi < 2; mi++) {
                int r = wm * 32 + mi * 16 + lr;
                ah[mi][0] = *(const uint32_t*)&sAh[r * SROW + kk];
                ah[mi][1] = *(const uint32_t*)&sAh[(r + 8) * SROW + kk];
                ah[mi][2] = *(const uint32_t*)&sAh[r * SROW + kk + 8];
                ah[mi][3] = *(const uint32_t*)&sAh[(r + 8) * SROW + kk + 8];
                al[mi][0] = *(const uint32_t*)&sAl[r * SROW + kk];
                al[mi][1] = *(const uint32_t*)&sAl[(r + 8) * SROW + kk];
                al[mi][2] = *(const uint32_t*)&sAl[r * SROW + kk + 8];
                al[mi][3] = *(const uint32_t*)&sAl[(r + 8) * SROW + kk + 8];
            }
#pragma unroll
            for (int ni = 0; ni < 8; ni++) {
                int n = wn * 64 + ni * 8 + lr;
                bh[ni][0] = *(const uint32_t*)&sBh[n * SROW + kk];
                bh[ni][1] = *(const uint32_t*)&sBh[n * SROW + kk + 8];
                bl[ni][0] = *(const uint32_t*)&sBl[n * SROW + kk];
                bl[ni][1] = *(const uint32_t*)&sBl[n * SROW + kk + 8];
            }
#pragma unroll
            for (int mi = 0; mi < 2; mi++)
#pragma unroll
                for (int ni = 0; ni < 8; ni++) {
                    mma16816(acc[mi][ni], ah[mi][0], ah[mi][1], ah[mi][2], ah[mi][3],
                             bh[ni][0], bh[ni][1]);
                    mma16816(acc[mi][ni], ah[mi][0], ah[mi][1], ah[mi][2], ah[mi][3],
                             bl[ni][0], bl[ni][1]);
                    mma16816(acc[mi][ni], al[mi][0], al[mi][1], al[mi][2], al[mi][3],
                             bh[ni][0], bh[ni][1]);
                }
        }
        __syncthreads();
    }

    // epilogue: c0,c1 -> row r; c2,c3 -> row r+8; cols (lc, lc+1)
    const int rb = m0 + wm * 32;
    const int cb = n0 + wn * 64;
#pragma unroll
    for (int mi = 0; mi < 2; mi++) {
#pragma unroll
        for (int half = 0; half < 2; half++) {
            int r = rb + mi * 16 + lr + half * 8;
            if (r >= M) continue;
            float sc = (EPI == 1) ? g_dinv[r] : 0.f;
#pragma unroll
            for (int ni = 0; ni < 8; ni++) {
                int c = cb + ni * 8 + lc;
                float v0 = acc[mi][ni][half * 2 + 0];
                float v1 = acc[mi][ni][half * 2 + 1];
                if (EPI == 0) { v0 += bias[c]; v1 += bias[c + 1]; }
                else          { v0 *= sc;      v1 *= sc; }
                *(float2*)(C + (size_t)r * HD + c) = make_float2(v0, v1);
            }
        }
    }
}

// ---- aggregation + fused BN stats: h[d] = (u[d]+sum u[src])*dinv + b -----
// 2 warps per node (128 channels each); register partials -> smem -> global.
__global__ void __launch_bounds__(256) aggregate_kernel(const float* __restrict__ bias) {
    __shared__ float ssum[HD];
    __shared__ float ssqs[HD];
    for (int i = threadIdx.x; i < HD; i += 256) { ssum[i] = 0.f; ssqs[i] = 0.f; }
    __syncthreads();

    int wp   = threadIdx.x >> 6;
    int half = (threadIdx.x >> 5) & 1;
    int lane = threadIdx.x & 31;
    int base = blockIdx.x * 32 + wp * 8;

    const float4* up = (const float4*)g_u + half * 32;
    float4* hp = (float4*)g_h + half * 32;
    float4 bb = ((const float4*)bias)[half * 32 + lane];
    float4 s = make_float4(0, 0, 0, 0), q = s;

    for (int nidx = 0; nidx < 8; nidx++) {
        int node = base + nidx;
        if (node >= NN) break;
        float4 a = up[(size_t)node * 64 + lane];
        int beg = g_rowptr[node];
        int end = beg + g_deg[node];
        for (int j = beg; j < end; j++) {
            int sc = g_srcs[j];
            float4 b = up[(size_t)sc * 64 + lane];
            a.x += b.x; a.y += b.y; a.z += b.z; a.w += b.w;
        }
        float dv = g_dinv[node];
        a.x = fmaf(a.x, dv, bb.x); a.y = fmaf(a.y, dv, bb.y);
        a.z = fmaf(a.z, dv, bb.z); a.w = fmaf(a.w, dv, bb.w);
        hp[(size_t)node * 64 + lane] = a;
        s.x += a.x; s.y += a.y; s.z += a.z; s.w += a.w;
        q.x += a.x*a.x; q.y += a.y*a.y; q.z += a.z*a.z; q.w += a.w*a.w;
    }

    int c = half * 128 + lane * 4;
    atomicAdd(&ssum[c+0], s.x); atomicAdd(&ssum[c+1], s.y);
    atomicAdd(&ssum[c+2], s.z); atomicAdd(&ssum[c+3], s.w);
    atomicAdd(&ssqs[c+0], q.x); atomicAdd(&ssqs[c+1], q.y);
    atomicAdd(&ssqs[c+2], q.z); atomicAdd(&ssqs[c+3], q.w);
    __syncthreads();
    atomicAdd(&g_sum[threadIdx.x], ssum[threadIdx.x]);
    atomicAdd(&g_sqs[threadIdx.x], ssqs[threadIdx.x]);
}

// ---------------- BN ----------------
__global__ void zero_stats_kernel() {
    int c = threadIdx.x;
    g_sum[c] = 0.f;
    g_sqs[c] = 0.f;
}
__global__ void __launch_bounds__(256) stats_cols_kernel(const float* __restrict__ X, int rows) {
    int c  = threadIdx.x;
    int r0 = blockIdx.x * 64;
    int r1 = min(r0 + 64, rows);
    float s = 0.f, s2 = 0.f;
    for (int r = r0; r < r1; r++) {
        float v = X[(size_t)r * HD + c];
        s += v;
        s2 += v * v;
    }
    atomicAdd(&g_sum[c], s);
    atomicAdd(&g_sqs[c], s2);
}
__global__ void bn_prep_kernel(const float* __restrict__ gamma,
                               const float* __restrict__ beta, float invN) {
    int c = threadIdx.x;
    float mu  = g_sum[c] * invN;
    float var = fmaxf(g_sqs[c] * invN - mu * mu, 0.f);
    float a   = gamma[c] * rsqrtf(var + BN_EPS);
    g_bnA[c] = a;
    g_bnB[c] = beta[c] - mu * a;
}
__global__ void __launch_bounds__(256) bn_apply_relu(float* __restrict__ X, int n4) {
    int i = blockIdx.x * 256 + threadIdx.x;
    if (i >= n4) return;
    int c4 = i & 63;
    float4 a = *(const float4*)&g_bnA[c4 * 4];
    float4 b = *(const float4*)&g_bnB[c4 * 4];
    float4 v = ((float4*)X)[i];
    v.x = fmaxf(fmaf(v.x, a.x, b.x), 0.f);
    v.y = fmaxf(fmaf(v.y, a.y, b.y), 0.f);
    v.z = fmaxf(fmaf(v.z, a.z, b.z), 0.f);
    v.w = fmaxf(fmaf(v.w, a.w, b.w), 0.f);
    ((float4*)X)[i] = v;
}

// ---- pooling with fused BN+ReLU of the last conv layer (batch sorted) ----
__global__ void __launch_bounds__(256) pool_kernel(const int* __restrict__ batch) {
    int g = blockIdx.x;
    __shared__ int s_lo, s_hi;
    if (threadIdx.x < 2) {
        int key = g + threadIdx.x;
        int lo = 0, hi = NN;
        while (lo < hi) {
            int mid = (lo + hi) >> 1;
            if (batch[mid] < key) lo = mid + 1; else hi = mid;
        }
        if (threadIdx.x == 0) s_lo = lo; else s_hi = lo;
    }
    __syncthreads();
    int lo = s_lo, hi = s_hi;
    int c = threadIdx.x;
    float a = g_bnA[c], b = g_bnB[c];
    float s = 0.f;
    for (int r = lo; r < hi; r++)
        s += fmaxf(fmaf(g_h[(size_t)r * HD + c], a, b), 0.f);
    float cnt = (float)(hi - lo);
    g_pool[g * HD + c] = s / fmaxf(cnt, 1.f);
}

// ---------------- head ----------------
__global__ void __launch_bounds__(256) head_kernel(const float* __restrict__ W2,
                                                   const float* __restrict__ b2,
                                                   float* __restrict__ out) {
    int g    = (int)((blockIdx.x * 256 + threadIdx.x) >> 5);
    int lane = threadIdx.x & 31;
    if (g >= NG) return;
    const float4* zp = (const float4*)&g_z[(size_t)g * HD];
    const float4* wp = (const float4*)W2;
    float4 z0 = zp[lane], w0 = wp[lane];
    float4 z1 = zp[lane + 32], w1 = wp[lane + 32];
    float s = z0.x * w0.x + z0.y * w0.y + z0.z * w0.z + z0.w * w0.w +
              z1.x * w1.x + z1.y * w1.y + z1.z * w1.z + z1.w * w1.w;
#pragma unroll
    for (int o = 16; o > 0; o >>= 1) s += __shfl_xor_sync(0xffffffffu, s, o);
    if (lane == 0) out[g] = s + b2[0];
}

// ---------------- launch ----------------
extern "C" void kernel_launch(void* const* d_in, const int* in_sizes, int n_in,
                              void* d_out, int out_size)
{
    (void)in_sizes; (void)n_in; (void)out_size;
    const float* x        = (const float*)d_in[0];
    const int*   ei       = (const int*)d_in[1];
    const int*   batch    = (const int*)d_in[2];
    const float* W_emb    = (const float*)d_in[3];
    const float* b_emb    = (const float*)d_in[4];
    const float* W_conv   = (const float*)d_in[5];
    const float* b_conv   = (const float*)d_in[6];
    const float* bn_gamma = (const float*)d_in[7];
    const float* bn_beta  = (const float*)d_in[8];
    const float* W1       = (const float*)d_in[9];
    const float* b1       = (const float*)d_in[10];
    const float* g2       = (const float*)d_in[11];
    const float* bt2      = (const float*)d_in[12];
    const float* W2       = (const float*)d_in[13];
    const float* b2       = (const float*)d_in[14];
    float*       out      = (float*)d_out;

    const int* src = ei;
    const int* dst = ei + NE;

    float *p_h, *p_u, *p_pool, *p_z;
    __nv_bfloat16 *p_Ah, *p_Al, *p_Bh, *p_Bl;
    cudaGetSymbolAddress((void**)&p_h,    g_h);
    cudaGetSymbolAddress((void**)&p_u,    g_u);
    cudaGetSymbolAddress((void**)&p_pool, g_pool);
    cudaGetSymbolAddress((void**)&p_z,    g_z);
    cudaGetSymbolAddress((void**)&p_Ah,   g_Ah);
    cudaGetSymbolAddress((void**)&p_Al,   g_Al);
    cudaGetSymbolAddress((void**)&p_Bh,   g_Bh);
    cudaGetSymbolAddress((void**)&p_Bl,   g_Bl);

    cudaFuncSetAttribute(mgemm<0>, cudaFuncAttributeMaxDynamicSharedMemorySize, MG_SMEM);
    cudaFuncSetAttribute(mgemm<1>, cudaFuncAttributeMaxDynamicSharedMemorySize, MG_SMEM);

    // CSR setup
    zero_deg_kernel<<<(NN + 255) / 256, 256>>>();
    edge_deg_kernel<<<(NE + 255) / 256, 256>>>(dst);
    scan1_kernel<<<NB, 256>>>();
    scan2_kernel<<<1, 256>>>();
    scan3_kernel<<<NB, 256>>>();
    make_dinv_kernel<<<(NN + 255) / 256, 256>>>();
    bucket_kernel<<<(NE + 255) / 256, 256>>>(src, dst);

    const dim3 GR(MPAD / 128, 2);   // 391 x 2

    // embedding: h = x @ W_emb + b_emb  (K=128)
    {
        int tot4 = MPAD * (INC / 4);
        split_kernel<<<(tot4 + 255) / 256, 256>>>(x, NN, INC / 4, tot4, 0);
        splitW_kernel<<<INC, 256>>>(W_emb, INC);
        mgemm<0><<<GR, 256, MG_SMEM>>>(p_Ah, p_Al, p_Bh, p_Bl, b_emb, p_h, NN, INC);
    }

    // GCN layers
    for (int l = 0; l < 3; l++) {
        int tot4 = MPAD * (HD / 4);
        split_kernel<<<(tot4 + 255) / 256, 256>>>(p_h, NN, HD / 4, tot4, l > 0 ? 1 : 0);
        splitW_kernel<<<HD, 256>>>(W_conv + (size_t)l * HD * HD, HD);
        mgemm<1><<<GR, 256, MG_SMEM>>>(p_Ah, p_Al, p_Bh, p_Bl, nullptr, p_u, NN, HD);
        zero_stats_kernel<<<1, HD>>>();
        aggregate_kernel<<<(NN + 31) / 32, 256>>>(b_conv + (size_t)l * HD);
        bn_prep_kernel<<<1, HD>>>(bn_gamma + (size_t)l * HD,
                                  bn_beta + (size_t)l * HD, 1.0f / NN);
    }

    // pooling (applies layer-2 BN+ReLU on the fly)
    pool_kernel<<<NG, HD>>>(batch);

    // MLP head: z = pool @ W1 + b1  (M=1024, K=256)
    {
        int tot4 = NG * (HD / 4);
        split_kernel<<<(tot4 + 255) / 256, 256>>>(p_pool, NG, HD / 4, tot4, 0);
        splitW_kernel<<<HD, 256>>>(W1, HD);
        mgemm<0><<<dim3(NG / 128, 2), 256, MG_SMEM>>>(p_Ah, p_Al, p_Bh, p_Bl, b1, p_z, NG, HD);
    }
    zero_stats_kernel<<<1, HD>>>();
    stats_cols_kernel<<<(NG + 63) / 64, 256>>>(p_z, NG);
    bn_prep_kernel<<<1, HD>>>(g2, bt2, 1.0f / NG);
    bn_apply_relu<<<(NG * (HD / 4) + 255) / 256, 256>>>(p_z, NG * (HD / 4));
    head_kernel<<<(NG * 32 + 255) / 256, 256>>>(W2, b2, out);
}

// round 10
// speedup vs baseline: 1.4279x; 1.0037x over previous
#include <cuda_runtime.h>
#include <cuda_bf16.h>
#include <cstdint>

#define NN 50000
#define MPAD 50048          // 391 * 128
#define NE 800000
#define INC 128
#define HD 256
#define NG 1024
#define BN_EPS 1e-5f
#define NB 196              // ceil(NN/256)

// ---------------- scratch (device globals: allocation-free) ----------------
__device__ int   g_deg[NN];
__device__ int   g_rowptr[NN];
__device__ int   g_cursor[NN];
__device__ int   g_bsum[NB];
__device__ int   g_srcs[NE];
__device__ float g_dinv[NN];
__device__ float g_h[(size_t)MPAD * HD];
__device__ float g_u[(size_t)MPAD * HD];
__device__ float g_pool[NG * HD];
__device__ float g_z[NG * HD];
__device__ float g_sum[HD];
__device__ float g_sqs[HD];
__device__ float g_bnA[HD];
__device__ float g_bnB[HD];
__device__ __nv_bfloat16 g_Bh[HD * HD];
__device__ __nv_bfloat16 g_Bl[HD * HD];

// ---------------- degree / CSR setup ----------------
__global__ void zero_deg_kernel() {
    int i = blockIdx.x * blockDim.x + threadIdx.x;
    if (i < NN) { g_deg[i] = 0; g_cursor[i] = 0; }
}
__global__ void edge_deg_kernel(const int* __restrict__ dst) {
    int e = blockIdx.x * blockDim.x + threadIdx.x;
    if (e < NE) atomicAdd(&g_deg[dst[e]], 1);
}
__global__ void make_dinv_kernel() {
    int i = blockIdx.x * blockDim.x + threadIdx.x;
    if (i < NN) g_dinv[i] = rsqrtf((float)(g_deg[i] + 1));
}
__global__ void scan1_kernel() {
    __shared__ int sh[256];
    int tid = threadIdx.x;
    int i = blockIdx.x * 256 + tid;
    int v = (i < NN) ? g_deg[i] : 0;
    sh[tid] = v;
    __syncthreads();
#pragma unroll
    for (int off = 1; off < 256; off <<= 1) {
        int t = (tid >= off) ? sh[tid - off] : 0;
        __syncthreads();
        sh[tid] += t;
        __syncthreads();
    }
    if (i < NN) g_rowptr[i] = sh[tid] - v;
    if (tid == 255) g_bsum[blockIdx.x] = sh[255];
}
__global__ void scan2_kernel() {
    __shared__ int sh[256];
    int tid = threadIdx.x;
    int v = (tid < NB) ? g_bsum[tid] : 0;
    sh[tid] = v;
    __syncthreads();
#pragma unroll
    for (int off = 1; off < 256; off <<= 1) {
        int t = (tid >= off) ? sh[tid - off] : 0;
        __syncthreads();
        sh[tid] += t;
        __syncthreads();
    }
    if (tid < NB) g_bsum[tid] = sh[tid] - v;
}
__global__ void scan3_kernel() {
    int i = blockIdx.x * 256 + threadIdx.x;
    if (i < NN) g_rowptr[i] += g_bsum[blockIdx.x];
}
__global__ void bucket_kernel(const int* __restrict__ src,
                              const int* __restrict__ dst) {
    int e = blockIdx.x * blockDim.x + threadIdx.x;
    if (e >= NE) return;
    int d = dst[e];
    int pos = atomicAdd(&g_cursor[d], 1);
    g_srcs[g_rowptr[d] + pos] = src[e];
}

// ------- split + transpose weights: W[K, 256] -> Bh/Bl[n=256][k=K] --------
__global__ void __launch_bounds__(256) splitW_kernel(
    const float* __restrict__ W, int K)
{
    int idx = blockIdx.x * 256 + threadIdx.x;
    int k = idx >> 8;
    int n = idx & 255;
    if (k >= K) return;
    float v = W[k * HD + n];
    __nv_bfloat16 h = __float2bfloat16(v);
    __nv_bfloat16 l = __float2bfloat16(v - __bfloat162float(h));
    g_Bh[n * K + k] = h;
    g_Bl[n * K + k] = l;
}

// -------- warp-MMA GEMM: C[M,256] = A'[M,K] @ (Bh+Bl)^T -------------------
// A fp32; loader applies optional BN+ReLU (prev layer) and splits hi/lo bf16
// into smem (Markidis). mma.sync.m16n8k16 bf16, fp32 accum, 3 products.
// CTA 256 thr = 8 warps (4m x 2n), tile 128x128, K chunked by 64.
// EPI 0: C = A'@B + bias      EPI 1: C = (A'@B) * g_dinv[row]
__device__ __forceinline__ void mma16816(float* d,
    uint32_t a0, uint32_t a1, uint32_t a2, uint32_t a3,
    uint32_t b0, uint32_t b1)
{
    asm volatile(
        "mma.sync.aligned.m16n8k16.row.col.f32.bf16.bf16.f32 "
        "{%0,%1,%2,%3}, {%4,%5,%6,%7}, {%8,%9}, {%0,%1,%2,%3};"
        : "+f"(d[0]), "+f"(d[1]), "+f"(d[2]), "+f"(d[3])
        : "r"(a0), "r"(a1), "r"(a2), "r"(a3), "r"(b0), "r"(b1));
}

#define SROW 72                        // bf16 stride (144B rows)
#define MG_TS (128 * SROW)
#define MG_SMEM (4 * MG_TS * 2)        // 73728 bytes

template <int EPI, int BN_IN>
__global__ void __launch_bounds__(256) mgemm(
    const float* __restrict__ A,
    const __nv_bfloat16* __restrict__ Bh, const __nv_bfloat16* __restrict__ Bl,
    const float* __restrict__ bias, float* __restrict__ C, int M, int K)
{
    extern __shared__ __nv_bfloat16 sm[];
    __nv_bfloat16* sAh = sm;
    __nv_bfloat16* sAl = sm + MG_TS;
    __nv_bfloat16* sBh = sm + 2 * MG_TS;
    __nv_bfloat16* sBl = sm + 3 * MG_TS;

    const int tid  = threadIdx.x;
    const int lane = tid & 31;
    const int warp = tid >> 5;
    const int wm   = warp & 3;
    const int wn   = warp >> 2;
    const int m0   = blockIdx.x * 128;
    const int n0   = blockIdx.y * 128;
    const int lr   = lane >> 2;
    const int lc   = (lane & 3) * 2;

    float acc[2][8][4];
#pragma unroll
    for (int i = 0; i < 2; i++)
#pragma unroll
        for (int j = 0; j < 8; j++)
#pragma unroll
            for (int q = 0; q < 4; q++) acc[i][j][q] = 0.f;

    for (int k0 = 0; k0 < K; k0 += 64) {
        // A tile: 128 rows x 64 fp32 -> BN/ReLU -> hi/lo bf16 smem
#pragma unroll
        for (int t = 0; t < 8; t++) {
            int idx = tid + t * 256;       // 0..2047
            int row = idx >> 4;            // 0..127
            int seg = idx & 15;            // 16B fp32 segments (4 floats)
            int gcol = k0 + seg * 4;
            float4 v = make_float4(0.f, 0.f, 0.f, 0.f);
            if (m0 + row < M)
                v = *(const float4*)(A + (size_t)(m0 + row) * K + gcol);
            if (BN_IN) {
                float4 a = *(const float4*)&g_bnA[gcol];
                float4 b = *(const float4*)&g_bnB[gcol];
                v.x = fmaxf(fmaf(v.x, a.x, b.x), 0.f);
                v.y = fmaxf(fmaf(v.y, a.y, b.y), 0.f);
                v.z = fmaxf(fmaf(v.z, a.z, b.z), 0.f);
                v.w = fmaxf(fmaf(v.w, a.w, b.w), 0.f);
            }
            __nv_bfloat16 hx = __float2bfloat16(v.x), hy = __float2bfloat16(v.y);
            __nv_bfloat16 hz = __float2bfloat16(v.z), hw = __float2bfloat16(v.w);
            __nv_bfloat16 lx = __float2bfloat16(v.x - __bfloat162float(hx));
            __nv_bfloat16 ly = __float2bfloat16(v.y - __bfloat162float(hy));
            __nv_bfloat16 lz = __float2bfloat16(v.z - __bfloat162float(hz));
            __nv_bfloat16 lw = __float2bfloat16(v.w - __bfloat162float(hw));
            int so = row * SROW + seg * 4;
            *(__nv_bfloat162*)&sAh[so]     = __nv_bfloat162(hx, hy);
            *(__nv_bfloat162*)&sAh[so + 2] = __nv_bfloat162(hz, hw);
            *(__nv_bfloat162*)&sAl[so]     = __nv_bfloat162(lx, ly);
            *(__nv_bfloat162*)&sAl[so + 2] = __nv_bfloat162(lz, lw);
        }
        // B tiles (pre-split bf16): 128 rows x 64 bf16 each
#pragma unroll
        for (int t = 0; t < 4; t++) {
            int idx = tid + t * 256;
            int row = idx >> 3;
            int seg = idx & 7;
            size_t gb = (size_t)(n0 + row) * K + k0 + seg * 8;
            uint32_t so = row * (SROW * 2) + seg * 16;
            *(uint4*)((char*)sBh + so) = *(const uint4*)(Bh + gb);
            *(uint4*)((char*)sBl + so) = *(const uint4*)(Bl + gb);
        }
        __syncthreads();
#pragma unroll
        for (int ks = 0; ks < 4; ks++) {
            const int kk = ks * 16 + lc;
            uint32_t ah[2][4], al[2][4], bh[8][2], bl[8][2];
#pragma unroll
            for (int mi = 0; mi < 2; mi++) {
                int r = wm * 32 + mi * 16 + lr;
                ah[mi][0] = *(const uint32_t*)&sAh[r * SROW + kk];
                ah[mi][1] = *(const uint32_t*)&sAh[(r + 8) * SROW + kk];
                ah[mi][2] = *(const uint32_t*)&sAh[r * SROW + kk + 8];
                ah[mi][3] = *(const uint32_t*)&sAh[(r + 8) * SROW + kk + 8];
                al[mi][0] = *(const uint32_t*)&sAl[r * SROW + kk];
                al[mi][1] = *(const uint32_t*)&sAl[(r + 8) * SROW + kk];
                al[mi][2] = *(const uint32_t*)&sAl[r * SROW + kk + 8];
                al[mi][3] = *(const uint32_t*)&sAl[(r + 8) * SROW + kk + 8];
            }
#pragma unroll
            for (int ni = 0; ni < 8; ni++) {
                int n = wn * 64 + ni * 8 + lr;
                bh[ni][0] = *(const uint32_t*)&sBh[n * SROW + kk];
                bh[ni][1] = *(const uint32_t*)&sBh[n * SROW + kk + 8];
                bl[ni][0] = *(const uint32_t*)&sBl[n * SROW + kk];
                bl[ni][1] = *(const uint32_t*)&sBl[n * SROW + kk + 8];
            }
#pragma unroll
            for (int mi = 0; mi < 2; mi++)
#pragma unroll
                for (int ni = 0; ni < 8; ni++) {
                    mma16816(acc[mi][ni], ah[mi][0], ah[mi][1], ah[mi][2], ah[mi][3],
                             bh[ni][0], bh[ni][1]);
                    mma16816(acc[mi][ni], ah[mi][0], ah[mi][1], ah[mi][2], ah[mi][3],
                             bl[ni][0], bl[ni][1]);
                    mma16816(acc[mi][ni], al[mi][0], al[mi][1], al[mi][2], al[mi][3],
                             bh[ni][0], bh[ni][1]);
                }
        }
        __syncthreads();
    }

    const int rb = m0 + wm * 32;
    const int cb = n0 + wn * 64;
#pragma unroll
    for (int mi = 0; mi < 2; mi++) {
#pragma unroll
        for (int half = 0; half < 2; half++) {
            int r = rb + mi * 16 + lr + half * 8;
            if (r >= M) continue;
            float sc = (EPI == 1) ? g_dinv[r] : 0.f;
#pragma unroll
            for (int ni = 0; ni < 8; ni++) {
                int c = cb + ni * 8 + lc;
                float v0 = acc[mi][ni][half * 2 + 0];
                float v1 = acc[mi][ni][half * 2 + 1];
                if (EPI == 0) { v0 += bias[c]; v1 += bias[c + 1]; }
                else          { v0 *= sc;      v1 *= sc; }
                *(float2*)(C + (size_t)r * HD + c) = make_float2(v0, v1);
            }
        }
    }
}

// ---- aggregation + fused BN stats: h[d] = (u[d]+sum u[src])*dinv + b -----
__global__ void __launch_bounds__(256) aggregate_kernel(const float* __restrict__ bias) {
    __shared__ float ssum[HD];
    __shared__ float ssqs[HD];
    for (int i = threadIdx.x; i < HD; i += 256) { ssum[i] = 0.f; ssqs[i] = 0.f; }
    __syncthreads();

    int wp   = threadIdx.x >> 6;
    int half = (threadIdx.x >> 5) & 1;
    int lane = threadIdx.x & 31;
    int base = blockIdx.x * 32 + wp * 8;

    const float4* up = (const float4*)g_u + half * 32;
    float4* hp = (float4*)g_h + half * 32;
    float4 bb = ((const float4*)bias)[half * 32 + lane];
    float4 s = make_float4(0, 0, 0, 0), q = s;

    for (int nidx = 0; nidx < 8; nidx++) {
        int node = base + nidx;
        if (node >= NN) break;
        float4 a = up[(size_t)node * 64 + lane];
        int beg = g_rowptr[node];
        int end = beg + g_deg[node];
        for (int j = beg; j < end; j++) {
            int sc = g_srcs[j];
            float4 b = up[(size_t)sc * 64 + lane];
            a.x += b.x; a.y += b.y; a.z += b.z; a.w += b.w;
        }
        float dv = g_dinv[node];
        a.x = fmaf(a.x, dv, bb.x); a.y = fmaf(a.y, dv, bb.y);
        a.z = fmaf(a.z, dv, bb.z); a.w = fmaf(a.w, dv, bb.w);
        hp[(size_t)node * 64 + lane] = a;
        s.x += a.x; s.y += a.y; s.z += a.z; s.w += a.w;
        q.x += a.x*a.x; q.y += a.y*a.y; q.z += a.z*a.z; q.w += a.w*a.w;
    }

    int c = half * 128 + lane * 4;
    atomicAdd(&ssum[c+0], s.x); atomicAdd(&ssum[c+1], s.y);
    atomicAdd(&ssum[c+2], s.z); atomicAdd(&ssum[c+3], s.w);
    atomicAdd(&ssqs[c+0], q.x); atomicAdd(&ssqs[c+1], q.y);
    atomicAdd(&ssqs[c+2], q.z); atomicAdd(&ssqs[c+3], q.w);
    __syncthreads();
    atomicAdd(&g_sum[threadIdx.x], ssum[threadIdx.x]);
    atomicAdd(&g_sqs[threadIdx.x], ssqs[threadIdx.x]);
}

// ---------------- BN ----------------
__global__ void zero_stats_kernel() {
    int c = threadIdx.x;
    g_sum[c] = 0.f;
    g_sqs[c] = 0.f;
}
__global__ void __launch_bounds__(256) stats_cols_kernel(const float* __restrict__ X, int rows) {
    int c  = threadIdx.x;
    int r0 = blockIdx.x * 64;
    int r1 = min(r0 + 64, rows);
    float s = 0.f, s2 = 0.f;
    for (int r = r0; r < r1; r++) {
        float v = X[(size_t)r * HD + c];
        s += v;
        s2 += v * v;
    }
    atomicAdd(&g_sum[c], s);
    atomicAdd(&g_sqs[c], s2);
}
__global__ void bn_prep_kernel(const float* __restrict__ gamma,
                               const float* __restrict__ beta, float invN) {
    int c = threadIdx.x;
    float mu  = g_sum[c] * invN;
    float var = fmaxf(g_sqs[c] * invN - mu * mu, 0.f);
    float a   = gamma[c] * rsqrtf(var + BN_EPS);
    g_bnA[c] = a;
    g_bnB[c] = beta[c] - mu * a;
}
__global__ void __launch_bounds__(256) bn_apply_relu(float* __restrict__ X, int n4) {
    int i = blockIdx.x * 256 + threadIdx.x;
    if (i >= n4) return;
    int c4 = i & 63;
    float4 a = *(const float4*)&g_bnA[c4 * 4];
    float4 b = *(const float4*)&g_bnB[c4 * 4];
    float4 v = ((float4*)X)[i];
    v.x = fmaxf(fmaf(v.x, a.x, b.x), 0.f);
    v.y = fmaxf(fmaf(v.y, a.y, b.y), 0.f);
    v.z = fmaxf(fmaf(v.z, a.z, b.z), 0.f);
    v.w = fmaxf(fmaf(v.w, a.w, b.w), 0.f);
    ((float4*)X)[i] = v;
}

// ---- pooling with fused BN+ReLU of the last conv layer (batch sorted) ----
__global__ void __launch_bounds__(256) pool_kernel(const int* __restrict__ batch) {
    int g = blockIdx.x;
    __shared__ int s_lo, s_hi;
    if (threadIdx.x < 2) {
        int key = g + threadIdx.x;
        int lo = 0, hi = NN;
        while (lo < hi) {
            int mid = (lo + hi) >> 1;
            if (batch[mid] < key) lo = mid + 1; else hi = mid;
        }
        if (threadIdx.x == 0) s_lo = lo; else s_hi = lo;
    }
    __syncthreads();
    int lo = s_lo, hi = s_hi;
    int c = threadIdx.x;
    float a = g_bnA[c], b = g_bnB[c];
    float s = 0.f;
    for (int r = lo; r < hi; r++)
        s += fmaxf(fmaf(g_h[(size_t)r * HD + c], a, b), 0.f);
    float cnt = (float)(hi - lo);
    g_pool[g * HD + c] = s / fmaxf(cnt, 1.f);
}

// ---------------- head ----------------
__global__ void __launch_bounds__(256) head_kernel(const float* __restrict__ W2,
                                                   const float* __restrict__ b2,
                                                   float* __restrict__ out) {
    int g    = (int)((blockIdx.x * 256 + threadIdx.x) >> 5);
    int lane = threadIdx.x & 31;
    if (g >= NG) return;
    const float4* zp = (const float4*)&g_z[(size_t)g * HD];
    const float4* wp = (const float4*)W2;
    float4 z0 = zp[lane], w0 = wp[lane];
    float4 z1 = zp[lane + 32], w1 = wp[lane + 32];
    float s = z0.x * w0.x + z0.y * w0.y + z0.z * w0.z + z0.w * w0.w +
              z1.x * w1.x + z1.y * w1.y + z1.z * w1.z + z1.w * w1.w;
#pragma unroll
    for (int o = 16; o > 0; o >>= 1) s += __shfl_xor_sync(0xffffffffu, s, o);
    if (lane == 0) out[g] = s + b2[0];
}

// ---------------- launch ----------------
extern "C" void kernel_launch(void* const* d_in, const int* in_sizes, int n_in,
                              void* d_out, int out_size)
{
    (void)in_sizes; (void)n_in; (void)out_size;
    const float* x        = (const float*)d_in[0];
    const int*   ei       = (const int*)d_in[1];
    const int*   batch    = (const int*)d_in[2];
    const float* W_emb    = (const float*)d_in[3];
    const float* b_emb    = (const float*)d_in[4];
    const float* W_conv   = (const float*)d_in[5];
    const float* b_conv   = (const float*)d_in[6];
    const float* bn_gamma = (const float*)d_in[7];
    const float* bn_beta  = (const float*)d_in[8];
    const float* W1       = (const float*)d_in[9];
    const float* b1       = (const float*)d_in[10];
    const float* g2       = (const float*)d_in[11];
    const float* bt2      = (const float*)d_in[12];
    const float* W2       = (const float*)d_in[13];
    const float* b2       = (const float*)d_in[14];
    float*       out      = (float*)d_out;

    const int* src = ei;
    const int* dst = ei + NE;

    float *p_h, *p_u, *p_pool, *p_z;
    __nv_bfloat16 *p_Bh, *p_Bl;
    cudaGetSymbolAddress((void**)&p_h,    g_h);
    cudaGetSymbolAddress((void**)&p_u,    g_u);
    cudaGetSymbolAddress((void**)&p_pool, g_pool);
    cudaGetSymbolAddress((void**)&p_z,    g_z);
    cudaGetSymbolAddress((void**)&p_Bh,   g_Bh);
    cudaGetSymbolAddress((void**)&p_Bl,   g_Bl);

    cudaFuncSetAttribute(mgemm<0,0>, cudaFuncAttributeMaxDynamicSharedMemorySize, MG_SMEM);
    cudaFuncSetAttribute(mgemm<1,0>, cudaFuncAttributeMaxDynamicSharedMemorySize, MG_SMEM);
    cudaFuncSetAttribute(mgemm<1,1>, cudaFuncAttributeMaxDynamicSharedMemorySize, MG_SMEM);

    // CSR setup
    zero_deg_kernel<<<(NN + 255) / 256, 256>>>();
    edge_deg_kernel<<<(NE + 255) / 256, 256>>>(dst);
    scan1_kernel<<<NB, 256>>>();
    scan2_kernel<<<1, 256>>>();
    scan3_kernel<<<NB, 256>>>();
    make_dinv_kernel<<<(NN + 255) / 256, 256>>>();
    bucket_kernel<<<(NE + 255) / 256, 256>>>(src, dst);

    const dim3 GR(MPAD / 128, 2);   // 391 x 2

    // embedding: h = x @ W_emb + b_emb  (K=128, A=x fp32 direct)
    splitW_kernel<<<INC, 256>>>(W_emb, INC);
    mgemm<0,0><<<GR, 256, MG_SMEM>>>(x, p_Bh, p_Bl, b_emb, p_h, NN, INC);

    // GCN layers: BN+ReLU of previous layer fused into mgemm A-loader
    for (int l = 0; l < 3; l++) {
        splitW_kernel<<<HD, 256>>>(W_conv + (size_t)l * HD * HD, HD);
        if (l == 0)
            mgemm<1,0><<<GR, 256, MG_SMEM>>>(p_h, p_Bh, p_Bl, nullptr, p_u, NN, HD);
        else
            mgemm<1,1><<<GR, 256, MG_SMEM>>>(p_h, p_Bh, p_Bl, nullptr, p_u, NN, HD);
        zero_stats_kernel<<<1, HD>>>();
        aggregate_kernel<<<(NN + 31) / 32, 256>>>(b_conv + (size_t)l * HD);
        bn_prep_kernel<<<1, HD>>>(bn_gamma + (size_t)l * HD,
                                  bn_beta + (size_t)l * HD, 1.0f / NN);
    }

    // pooling (applies layer-2 BN+ReLU on the fly)
    pool_kernel<<<NG, HD>>>(batch);

    // MLP head: z = pool @ W1 + b1  (M=1024, K=256)
    splitW_kernel<<<HD, 256>>>(W1, HD);
    mgemm<0,0><<<dim3(NG / 128, 2), 256, MG_SMEM>>>(p_pool, p_Bh, p_Bl, b1, p_z, NG, HD);
    zero_stats_kernel<<<1, HD>>>();
    stats_cols_kernel<<<(NG + 63) / 64, 256>>>(p_z, NG);
    bn_prep_kernel<<<1, HD>>>(g2, bt2, 1.0f / NG);
    bn_apply_relu<<<(NG * (HD / 4) + 255) / 256, 256>>>(p_z, NG * (HD / 4));
    head_kernel<<<(NG * 32 + 255) / 256, 256>>>(W2, b2, out);
}

// round 12
// speedup vs baseline: 1.6241x; 1.1374x over previous
#include <cuda_runtime.h>
#include <cuda_bf16.h>
#include <cuda_fp16.h>
#include <cstdint>

#define NN 50000
#define MPAD 50048          // 391 * 128
#define NE 800000
#define INC 128
#define HD 256
#define NG 1024
#define BN_EPS 1e-5f
#define NB 196              // ceil(NN/256)

// weight-split buffer offsets (transposed [n][k] layout per matrix)
#define WOFF_EMB  0
#define WOFF_CONV 32768            // + l*65536
#define WOFF_W1   229376
#define WTOT      294912

// ---------------- scratch (device globals: allocation-free) ----------------
__device__ int    g_deg[NN];
__device__ int    g_rowptr[NN];
__device__ int    g_cursor[NN];
__device__ int    g_bsum[NB];
__device__ int    g_srcs[NE];
__device__ float  g_dinv[NN];
__device__ float  g_h[(size_t)MPAD * HD];
__device__ __half g_uh[(size_t)MPAD * HD];
__device__ float  g_pool[NG * HD];
__device__ float  g_z[NG * HD];
__device__ float  g_sum[4 * HD];
__device__ float  g_sqs[4 * HD];
__device__ float  g_bnA[HD];
__device__ float  g_bnB[HD];
__device__ __nv_bfloat16 g_Bh[WTOT];
__device__ __nv_bfloat16 g_Bl[WTOT];

// ---------------- setup: zero deg/cursor + all BN stat slices --------------
__global__ void zero_deg_kernel() {
    int i = blockIdx.x * blockDim.x + threadIdx.x;
    if (i < NN) { g_deg[i] = 0; g_cursor[i] = 0; }
    if (i < 4 * HD) { g_sum[i] = 0.f; g_sqs[i] = 0.f; }
}
__global__ void edge_deg_kernel(const int* __restrict__ dst) {
    int e = blockIdx.x * blockDim.x + threadIdx.x;
    if (e < NE) atomicAdd(&g_deg[dst[e]], 1);
}
__global__ void make_dinv_kernel() {
    int i = blockIdx.x * blockDim.x + threadIdx.x;
    if (i < NN) g_dinv[i] = rsqrtf((float)(g_deg[i] + 1));
}
__global__ void scan1_kernel() {
    __shared__ int sh[256];
    int tid = threadIdx.x;
    int i = blockIdx.x * 256 + tid;
    int v = (i < NN) ? g_deg[i] : 0;
    sh[tid] = v;
    __syncthreads();
#pragma unroll
    for (int off = 1; off < 256; off <<= 1) {
        int t = (tid >= off) ? sh[tid - off] : 0;
        __syncthreads();
        sh[tid] += t;
        __syncthreads();
    }
    if (i < NN) g_rowptr[i] = sh[tid] - v;
    if (tid == 255) g_bsum[blockIdx.x] = sh[255];
}
__global__ void scan2_kernel() {
    __shared__ int sh[256];
    int tid = threadIdx.x;
    int v = (tid < NB) ? g_bsum[tid] : 0;
    sh[tid] = v;
    __syncthreads();
#pragma unroll
    for (int off = 1; off < 256; off <<= 1) {
        int t = (tid >= off) ? sh[tid - off] : 0;
        __syncthreads();
        sh[tid] += t;
        __syncthreads();
    }
    if (tid < NB) g_bsum[tid] = sh[tid] - v;
}
__global__ void scan3_kernel() {
    int i = blockIdx.x * 256 + threadIdx.x;
    if (i < NN) g_rowptr[i] += g_bsum[blockIdx.x];
}
__global__ void bucket_kernel(const int* __restrict__ src,
                              const int* __restrict__ dst) {
    int e = blockIdx.x * blockDim.x + threadIdx.x;
    if (e >= NE) return;
    int d = dst[e];
    int pos = atomicAdd(&g_cursor[d], 1);
    g_srcs[g_rowptr[d] + pos] = src[e];
}

// ---- split + transpose ALL weights in one kernel (input-only dependency) --
__global__ void __launch_bounds__(256) splitW_all_kernel(
    const float* __restrict__ W_emb, const float* __restrict__ W_conv,
    const float* __restrict__ W1)
{
    int idx = blockIdx.x * 256 + threadIdx.x;
    if (idx >= WTOT) return;
    const float* src;
    int K, k, n, doff;
    if (idx < WOFF_CONV) {
        K = INC; k = idx >> 8; n = idx & 255; src = W_emb; doff = WOFF_EMB;
    } else {
        int idx2 = idx - WOFF_CONV;
        int m = idx2 >> 16;            // 0..3 (3 conv + W1)
        int rem = idx2 & 65535;
        K = HD; k = rem >> 8; n = rem & 255;
        src = (m < 3) ? (W_conv + (size_t)m * HD * HD) : W1;
        doff = WOFF_CONV + m * 65536;
    }
    float v = src[k * HD + n];
    __nv_bfloat16 h = __float2bfloat16(v);
    __nv_bfloat16 l = __float2bfloat16(v - __bfloat162float(h));
    g_Bh[doff + n * K + k] = h;
    g_Bl[doff + n * K + k] = l;
}

// -------- warp-MMA GEMM: C[M,256] = A'[M,K] @ (Bh+Bl)^T -------------------
// A fp32; loader applies optional BN+ReLU and Markidis hi/lo split to smem.
// EPI 0: C(float*) = A'@B + bias    EPI 1: C(half*) = (A'@B) * g_dinv[row]
__device__ __forceinline__ void mma16816(float* d,
    uint32_t a0, uint32_t a1, uint32_t a2, uint32_t a3,
    uint32_t b0, uint32_t b1)
{
    asm volatile(
        "mma.sync.aligned.m16n8k16.row.col.f32.bf16.bf16.f32 "
        "{%0,%1,%2,%3}, {%4,%5,%6,%7}, {%8,%9}, {%0,%1,%2,%3};"
        : "+f"(d[0]), "+f"(d[1]), "+f"(d[2]), "+f"(d[3])
        : "r"(a0), "r"(a1), "r"(a2), "r"(a3), "r"(b0), "r"(b1));
}

#define SROW 72
#define MG_TS (128 * SROW)
#define MG_SMEM (4 * MG_TS * 2)        // 73728 bytes

template <int EPI, int BN_IN>
__global__ void __launch_bounds__(256) mgemm(
    const float* __restrict__ A,
    const __nv_bfloat16* __restrict__ Bh, const __nv_bfloat16* __restrict__ Bl,
    const float* __restrict__ bias, void* __restrict__ Cv, int M, int K)
{
    extern __shared__ __nv_bfloat16 sm[];
    __nv_bfloat16* sAh = sm;
    __nv_bfloat16* sAl = sm + MG_TS;
    __nv_bfloat16* sBh = sm + 2 * MG_TS;
    __nv_bfloat16* sBl = sm + 3 * MG_TS;

    const int tid  = threadIdx.x;
    const int lane = tid & 31;
    const int warp = tid >> 5;
    const int wm   = warp & 3;
    const int wn   = warp >> 2;
    const int m0   = blockIdx.x * 128;
    const int n0   = blockIdx.y * 128;
    const int lr   = lane >> 2;
    const int lc   = (lane & 3) * 2;

    float acc[2][8][4];
#pragma unroll
    for (int i = 0; i < 2; i++)
#pragma unroll
        for (int j = 0; j < 8; j++)
#pragma unroll
            for (int q = 0; q < 4; q++) acc[i][j][q] = 0.f;

    for (int k0 = 0; k0 < K; k0 += 64) {
#pragma unroll
        for (int t = 0; t < 8; t++) {
            int idx = tid + t * 256;
            int row = idx >> 4;
            int seg = idx & 15;
            int gcol = k0 + seg * 4;
            float4 v = make_float4(0.f, 0.f, 0.f, 0.f);
            if (m0 + row < M)
                v = *(const float4*)(A + (size_t)(m0 + row) * K + gcol);
            if (BN_IN) {
                float4 a = *(const float4*)&g_bnA[gcol];
                float4 b = *(const float4*)&g_bnB[gcol];
                v.x = fmaxf(fmaf(v.x, a.x, b.x), 0.f);
                v.y = fmaxf(fmaf(v.y, a.y, b.y), 0.f);
                v.z = fmaxf(fmaf(v.z, a.z, b.z), 0.f);
                v.w = fmaxf(fmaf(v.w, a.w, b.w), 0.f);
            }
            __nv_bfloat16 hx = __float2bfloat16(v.x), hy = __float2bfloat16(v.y);
            __nv_bfloat16 hz = __float2bfloat16(v.z), hw = __float2bfloat16(v.w);
            __nv_bfloat16 lx = __float2bfloat16(v.x - __bfloat162float(hx));
            __nv_bfloat16 ly = __float2bfloat16(v.y - __bfloat162float(hy));
            __nv_bfloat16 lz = __float2bfloat16(v.z - __bfloat162float(hz));
            __nv_bfloat16 lw = __float2bfloat16(v.w - __bfloat162float(hw));
            int so = row * SROW + seg * 4;
            *(__nv_bfloat162*)&sAh[so]     = __nv_bfloat162(hx, hy);
            *(__nv_bfloat162*)&sAh[so + 2] = __nv_bfloat162(hz, hw);
            *(__nv_bfloat162*)&sAl[so]     = __nv_bfloat162(lx, ly);
            *(__nv_bfloat162*)&sAl[so + 2] = __nv_bfloat162(lz, lw);
        }
#pragma unroll
        for (int t = 0; t < 4; t++) {
            int idx = tid + t * 256;
            int row = idx >> 3;
            int seg = idx & 7;
            size_t gb = (size_t)(n0 + row) * K + k0 + seg * 8;
            uint32_t so = row * (SROW * 2) + seg * 16;
            *(uint4*)((char*)sBh + so) = *(const uint4*)(Bh + gb);
            *(uint4*)((char*)sBl + so) = *(const uint4*)(Bl + gb);
        }
        __syncthreads();
#pragma unroll
        for (int ks = 0; ks < 4; ks++) {
            const int kk = ks * 16 + lc;
            uint32_t ah[2][4], al[2][4], bh[8][2], bl[8][2];
#pragma unroll
            for (int mi = 0; mi < 2; mi++) {
                int r = wm * 32 + mi * 16 + lr;
                ah[mi][0] = *(const uint32_t*)&sAh[r * SROW + kk];
                ah[mi][1] = *(const uint32_t*)&sAh[(r + 8) * SROW + kk];
                ah[mi][2] = *(const uint32_t*)&sAh[r * SROW + kk + 8];
                ah[mi][3] = *(const uint32_t*)&sAh[(r + 8) * SROW + kk + 8];
                al[mi][0] = *(const uint32_t*)&sAl[r * SROW + kk];
                al[mi][1] = *(const uint32_t*)&sAl[(r + 8) * SROW + kk];
                al[mi][2] = *(const uint32_t*)&sAl[r * SROW + kk + 8];
                al[mi][3] = *(const uint32_t*)&sAl[(r + 8) * SROW + kk + 8];
            }
#pragma unroll
            for (int ni = 0; ni < 8; ni++) {
                int n = wn * 64 + ni * 8 + lr;
                bh[ni][0] = *(const uint32_t*)&sBh[n * SROW + kk];
                bh[ni][1] = *(const uint32_t*)&sBh[n * SROW + kk + 8];
                bl[ni][0] = *(const uint32_t*)&sBl[n * SROW + kk];
                bl[ni][1] = *(const uint32_t*)&sBl[n * SROW + kk + 8];
            }
#pragma unroll
            for (int mi = 0; mi < 2; mi++)
#pragma unroll
                for (int ni = 0; ni < 8; ni++) {
                    mma16816(acc[mi][ni], ah[mi][0], ah[mi][1], ah[mi][2], ah[mi][3],
                             bh[ni][0], bh[ni][1]);
                    mma16816(acc[mi][ni], ah[mi][0], ah[mi][1], ah[mi][2], ah[mi][3],
                             bl[ni][0], bl[ni][1]);
                    mma16816(acc[mi][ni], al[mi][0], al[mi][1], al[mi][2], al[mi][3],
                             bh[ni][0], bh[ni][1]);
                }
        }
        __syncthreads();
    }

    const int rb = m0 + wm * 32;
    const int cb = n0 + wn * 64;
#pragma unroll
    for (int mi = 0; mi < 2; mi++) {
#pragma unroll
        for (int half = 0; half < 2; half++) {
            int r = rb + mi * 16 + lr + half * 8;
            if (r >= M) continue;
            float sc = (EPI == 1) ? g_dinv[r] : 0.f;
#pragma unroll
            for (int ni = 0; ni < 8; ni++) {
                int c = cb + ni * 8 + lc;
                float v0 = acc[mi][ni][half * 2 + 0];
                float v1 = acc[mi][ni][half * 2 + 1];
                if (EPI == 0) {
                    v0 += bias[c]; v1 += bias[c + 1];
                    *(float2*)((float*)Cv + (size_t)r * HD + c) = make_float2(v0, v1);
                } else {
                    v0 *= sc; v1 *= sc;
                    *(__half2*)((__half*)Cv + (size_t)r * HD + c) =
                        __floats2half2_rn(v0, v1);
                }
            }
        }
    }
}

// ---- aggregation + fused BN stats: h[d] = (u[d]+sum u[src])*dinv + b -----
// u stored fp16 (halved gather traffic); fp32 accumulation. 2 warps/node.
__global__ void __launch_bounds__(256) aggregate_kernel(
    const float* __restrict__ bias, int layer)
{
    __shared__ float ssum[HD];
    __shared__ float ssqs[HD];
    for (int i = threadIdx.x; i < HD; i += 256) { ssum[i] = 0.f; ssqs[i] = 0.f; }
    __syncthreads();

    int wp   = threadIdx.x >> 6;
    int half = (threadIdx.x >> 5) & 1;
    int lane = threadIdx.x & 31;
    int base = blockIdx.x * 32 + wp * 8;
    int coff = half * 32 + lane;          // uint2 (4-half) index within row (64/row)

    const uint2* up = (const uint2*)g_uh;  // row = 64 uint2
    float4* hp = (float4*)g_h + half * 32;
    float4 bb = ((const float4*)bias)[half * 32 + lane];
    float4 s = make_float4(0, 0, 0, 0), q = s;

    for (int nidx = 0; nidx < 8; nidx++) {
        int node = base + nidx;
        if (node >= NN) break;
        uint2 raw = up[(size_t)node * 64 + coff];
        float2 f0 = __half22float2(*(__half2*)&raw.x);
        float2 f1 = __half22float2(*(__half2*)&raw.y);
        float4 a = make_float4(f0.x, f0.y, f1.x, f1.y);
        int beg = g_rowptr[node];
        int end = beg + g_deg[node];
        int j = beg;
        for (; j + 1 < end; j += 2) {
            int s0 = g_srcs[j], s1 = g_srcs[j + 1];
            uint2 r0 = up[(size_t)s0 * 64 + coff];
            uint2 r1 = up[(size_t)s1 * 64 + coff];
            float2 a0 = __half22float2(*(__half2*)&r0.x);
            float2 a1 = __half22float2(*(__half2*)&r0.y);
            float2 b0 = __half22float2(*(__half2*)&r1.x);
            float2 b1 = __half22float2(*(__half2*)&r1.y);
            a.x += a0.x + b0.x; a.y += a0.y + b0.y;
            a.z += a1.x + b1.x; a.w += a1.y + b1.y;
        }
        if (j < end) {
            uint2 r0 = up[(size_t)g_srcs[j] * 64 + coff];
            float2 a0 = __half22float2(*(__half2*)&r0.x);
            float2 a1 = __half22float2(*(__half2*)&r0.y);
            a.x += a0.x; a.y += a0.y; a.z += a1.x; a.w += a1.y;
        }
        float dv = g_dinv[node];
        a.x = fmaf(a.x, dv, bb.x); a.y = fmaf(a.y, dv, bb.y);
        a.z = fmaf(a.z, dv, bb.z); a.w = fmaf(a.w, dv, bb.w);
        hp[(size_t)node * 64 + lane] = a;
        s.x += a.x; s.y += a.y; s.z += a.z; s.w += a.w;
        q.x += a.x*a.x; q.y += a.y*a.y; q.z += a.z*a.z; q.w += a.w*a.w;
    }

    int c = half * 128 + lane * 4;
    atomicAdd(&ssum[c+0], s.x); atomicAdd(&ssum[c+1], s.y);
    atomicAdd(&ssum[c+2], s.z); atomicAdd(&ssum[c+3], s.w);
    atomicAdd(&ssqs[c+0], q.x); atomicAdd(&ssqs[c+1], q.y);
    atomicAdd(&ssqs[c+2], q.z); atomicAdd(&ssqs[c+3], q.w);
    __syncthreads();
    atomicAdd(&g_sum[layer * HD + threadIdx.x], ssum[threadIdx.x]);
    atomicAdd(&g_sqs[layer * HD + threadIdx.x], ssqs[threadIdx.x]);
}

// ---------------- BN ----------------
__global__ void __launch_bounds__(256) stats_cols_kernel(
    const float* __restrict__ X, int rows, int layer)
{
    int c  = threadIdx.x;
    int r0 = blockIdx.x * 64;
    int r1 = min(r0 + 64, rows);
    float s = 0.f, s2 = 0.f;
    for (int r = r0; r < r1; r++) {
        float v = X[(size_t)r * HD + c];
        s += v;
        s2 += v * v;
    }
    atomicAdd(&g_sum[layer * HD + c], s);
    atomicAdd(&g_sqs[layer * HD + c], s2);
}
__global__ void bn_prep_kernel(const float* __restrict__ gamma,
                               const float* __restrict__ beta, float invN, int layer) {
    int c = threadIdx.x;
    float mu  = g_sum[layer * HD + c] * invN;
    float var = fmaxf(g_sqs[layer * HD + c] * invN - mu * mu, 0.f);
    float a   = gamma[c] * rsqrtf(var + BN_EPS);
    g_bnA[c] = a;
    g_bnB[c] = beta[c] - mu * a;
}
__global__ void __launch_bounds__(256) bn_apply_relu(float* __restrict__ X, int n4) {
    int i = blockIdx.x * 256 + threadIdx.x;
    if (i >= n4) return;
    int c4 = i & 63;
    float4 a = *(const float4*)&g_bnA[c4 * 4];
    float4 b = *(const float4*)&g_bnB[c4 * 4];
    float4 v = ((float4*)X)[i];
    v.x = fmaxf(fmaf(v.x, a.x, b.x), 0.f);
    v.y = fmaxf(fmaf(v.y, a.y, b.y), 0.f);
    v.z = fmaxf(fmaf(v.z, a.z, b.z), 0.f);
    v.w = fmaxf(fmaf(v.w, a.w, b.w), 0.f);
    ((float4*)X)[i] = v;
}

// ---- pooling with fused BN+ReLU of the last conv layer (batch sorted) ----
__global__ void __launch_bounds__(256) pool_kernel(const int* __restrict__ batch) {
    int g = blockIdx.x;
    __shared__ int s_lo, s_hi;
    if (threadIdx.x < 2) {
        int key = g + threadIdx.x;
        int lo = 0, hi = NN;
        while (lo < hi) {
            int mid = (lo + hi) >> 1;
            if (batch[mid] < key) lo = mid + 1; else hi = mid;
        }
        if (threadIdx.x == 0) s_lo = lo; else s_hi = lo;
    }
    __syncthreads();
    int lo = s_lo, hi = s_hi;
    int c = threadIdx.x;
    float a = g_bnA[c], b = g_bnB[c];
    float s = 0.f;
    for (int r = lo; r < hi; r++)
        s += fmaxf(fmaf(g_h[(size_t)r * HD + c], a, b), 0.f);
    float cnt = (float)(hi - lo);
    g_pool[g * HD + c] = s / fmaxf(cnt, 1.f);
}

// ---------------- head ----------------
__global__ void __launch_bounds__(256) head_kernel(const float* __restrict__ W2,
                                                   const float* __restrict__ b2,
                                                   float* __restrict__ out) {
    int g    = (int)((blockIdx.x * 256 + threadIdx.x) >> 5);
    int lane = threadIdx.x & 31;
    if (g >= NG) return;
    const float4* zp = (const float4*)&g_z[(size_t)g * HD];
    const float4* wp = (const float4*)W2;
    float4 z0 = zp[lane], w0 = wp[lane];
    float4 z1 = zp[lane + 32], w1 = wp[lane + 32];
    float s = z0.x * w0.x + z0.y * w0.y + z0.z * w0.z + z0.w * w0.w +
              z1.x * w1.x + z1.y * w1.y + z1.z * w1.z + z1.w * w1.w;
#pragma unroll
    for (int o = 16; o > 0; o >>= 1) s += __shfl_xor_sync(0xffffffffu, s, o);
    if (lane == 0) out[g] = s + b2[0];
}

// ---------------- launch ----------------
extern "C" void kernel_launch(void* const* d_in, const int* in_sizes, int n_in,
                              void* d_out, int out_size)
{
    (void)in_sizes; (void)n_in; (void)out_size;
    const float* x        = (const float*)d_in[0];
    const int*   ei       = (const int*)d_in[1];
    const int*   batch    = (const int*)d_in[2];
    const float* W_emb    = (const float*)d_in[3];
    const float* b_emb    = (const float*)d_in[4];
    const float* W_conv   = (const float*)d_in[5];
    const float* b_conv   = (const float*)d_in[6];
    const float* bn_gamma = (const float*)d_in[7];
    const float* bn_beta  = (const float*)d_in[8];
    const float* W1       = (const float*)d_in[9];
    const float* b1       = (const float*)d_in[10];
    const float* g2       = (const float*)d_in[11];
    const float* bt2      = (const float*)d_in[12];
    const float* W2       = (const float*)d_in[13];
    const float* b2       = (const float*)d_in[14];
    float*       out      = (float*)d_out;

    const int* src = ei;
    const int* dst = ei + NE;

    float *p_h, *p_pool, *p_z;
    __half *p_uh;
    __nv_bfloat16 *p_Bh, *p_Bl;
    cudaGetSymbolAddress((void**)&p_h,    g_h);
    cudaGetSymbolAddress((void**)&p_uh,   g_uh);
    cudaGetSymbolAddress((void**)&p_pool, g_pool);
    cudaGetSymbolAddress((void**)&p_z,    g_z);
    cudaGetSymbolAddress((void**)&p_Bh,   g_Bh);
    cudaGetSymbolAddress((void**)&p_Bl,   g_Bl);

    cudaFuncSetAttribute(mgemm<0,0>, cudaFuncAttributeMaxDynamicSharedMemorySize, MG_SMEM);
    cudaFuncSetAttribute(mgemm<1,0>, cudaFuncAttributeMaxDynamicSharedMemorySize, MG_SMEM);
    cudaFuncSetAttribute(mgemm<1,1>, cudaFuncAttributeMaxDynamicSharedMemorySize, MG_SMEM);

    // weight splits first (input-only dependency)
    splitW_all_kernel<<<(WTOT + 255) / 256, 256>>>(W_emb, W_conv, W1);

    // CSR setup (+ zero all 4 BN stat slices)
    zero_deg_kernel<<<(NN + 255) / 256, 256>>>();
    edge_deg_kernel<<<(NE + 255) / 256, 256>>>(dst);
    scan1_kernel<<<NB, 256>>>();
    scan2_kernel<<<1, 256>>>();
    scan3_kernel<<<NB, 256>>>();
    make_dinv_kernel<<<(NN + 255) / 256, 256>>>();
    bucket_kernel<<<(NE + 255) / 256, 256>>>(src, dst);

    const dim3 GR(MPAD / 128, 2);   // 391 x 2

    // embedding: h = x @ W_emb + b_emb
    mgemm<0,0><<<GR, 256, MG_SMEM>>>(x, p_Bh + WOFF_EMB, p_Bl + WOFF_EMB,
                                     b_emb, p_h, NN, INC);

    // GCN layers
    for (int l = 0; l < 3; l++) {
        const __nv_bfloat16* bh = p_Bh + WOFF_CONV + l * 65536;
        const __nv_bfloat16* bl = p_Bl + WOFF_CONV + l * 65536;
        if (l == 0)
            mgemm<1,0><<<GR, 256, MG_SMEM>>>(p_h, bh, bl, nullptr, p_uh, NN, HD);
        else
            mgemm<1,1><<<GR, 256, MG_SMEM>>>(p_h, bh, bl, nullptr, p_uh, NN, HD);
        aggregate_kernel<<<(NN + 31) / 32, 256>>>(b_conv + (size_t)l * HD, l);
        bn_prep_kernel<<<1, HD>>>(bn_gamma + (size_t)l * HD,
                                  bn_beta + (size_t)l * HD, 1.0f / NN, l);
    }

    // pooling (applies layer-2 BN+ReLU on the fly)
    pool_kernel<<<NG, HD>>>(batch);

    // MLP head
    mgemm<0,0><<<dim3(NG / 128, 2), 256, MG_SMEM>>>(
        p_pool, p_Bh + WOFF_W1, p_Bl + WOFF_W1, b1, p_z, NG, HD);
    stats_cols_kernel<<<(NG + 63) / 64, 256>>>(p_z, NG, 3);
    bn_prep_kernel<<<1, HD>>>(g2, bt2, 1.0f / NG, 3);
    bn_apply_relu<<<(NG * (HD / 4) + 255) / 256, 256>>>(p_z, NG * (HD / 4));
    head_kernel<<<(NG * 32 + 255) / 256, 256>>>(W2, b2, out);
}

// round 14
// speedup vs baseline: 1.8767x; 1.1556x over previous
#include <cuda_runtime.h>
#include <cuda_bf16.h>
#include <cuda_fp16.h>
#include <cstdint>

#define NN 50000
#define MPAD 50048          // 391 * 128
#define NE 800000
#define INC 128
#define HD 256
#define NG 1024
#define BN_EPS 1e-5f
#define NB 196              // ceil(NN/256)

// weight-split buffer offsets (transposed [n][k] layout per matrix)
#define WOFF_EMB  0
#define WOFF_CONV 32768            // + l*65536
#define WOFF_W1   229376
#define WTOT      294912

// ---------------- scratch (device globals: allocation-free) ----------------
__device__ int    g_deg[NN];
__device__ int    g_rowptr[NN];
__device__ int    g_cursor[NN];
__device__ int    g_bsum[NB];
__device__ int    g_srcs[NE];
__device__ float  g_dinv[NN];
__device__ float  g_h[(size_t)MPAD * HD];
__device__ __half g_uh[(size_t)MPAD * HD];
__device__ float  g_pool[NG * HD];
__device__ float  g_z[NG * HD];
__device__ float  g_sum[4 * HD];
__device__ float  g_sqs[4 * HD];
__device__ __nv_bfloat16 g_Bh[WTOT];
__device__ __nv_bfloat16 g_Bl[WTOT];

// ---------------- setup ----------------
__global__ void zero_deg_kernel() {
    int i = blockIdx.x * blockDim.x + threadIdx.x;
    if (i < NN) { g_deg[i] = 0; g_cursor[i] = 0; }
    if (i < 4 * HD) { g_sum[i] = 0.f; g_sqs[i] = 0.f; }
}
__global__ void edge_deg_kernel(const int* __restrict__ dst) {
    int e = blockIdx.x * blockDim.x + threadIdx.x;
    if (e < NE) atomicAdd(&g_deg[dst[e]], 1);
}
__global__ void scan1_kernel() {
    __shared__ int sh[256];
    int tid = threadIdx.x;
    int i = blockIdx.x * 256 + tid;
    int v = (i < NN) ? g_deg[i] : 0;
    sh[tid] = v;
    __syncthreads();
#pragma unroll
    for (int off = 1; off < 256; off <<= 1) {
        int t = (tid >= off) ? sh[tid - off] : 0;
        __syncthreads();
        sh[tid] += t;
        __syncthreads();
    }
    if (i < NN) g_rowptr[i] = sh[tid] - v;
    if (tid == 255) g_bsum[blockIdx.x] = sh[255];
}
__global__ void scan2_kernel() {
    __shared__ int sh[256];
    int tid = threadIdx.x;
    int v = (tid < NB) ? g_bsum[tid] : 0;
    sh[tid] = v;
    __syncthreads();
#pragma unroll
    for (int off = 1; off < 256; off <<= 1) {
        int t = (tid >= off) ? sh[tid - off] : 0;
        __syncthreads();
        sh[tid] += t;
        __syncthreads();
    }
    if (tid < NB) g_bsum[tid] = sh[tid] - v;
}
// scan3 + dinv merged
__global__ void scan3_kernel() {
    int i = blockIdx.x * 256 + threadIdx.x;
    if (i < NN) {
        g_rowptr[i] += g_bsum[blockIdx.x];
        g_dinv[i] = rsqrtf((float)(g_deg[i] + 1));
    }
}
__global__ void bucket_kernel(const int* __restrict__ src,
                              const int* __restrict__ dst) {
    int e = blockIdx.x * blockDim.x + threadIdx.x;
    if (e >= NE) return;
    int d = dst[e];
    int pos = atomicAdd(&g_cursor[d], 1);
    g_srcs[g_rowptr[d] + pos] = src[e];
}

// ---- split + transpose ALL weights in one kernel --------------------------
__global__ void __launch_bounds__(256) splitW_all_kernel(
    const float* __restrict__ W_emb, const float* __restrict__ W_conv,
    const float* __restrict__ W1)
{
    int idx = blockIdx.x * 256 + threadIdx.x;
    if (idx >= WTOT) return;
    const float* src;
    int K, k, n, doff;
    if (idx < WOFF_CONV) {
        K = INC; k = idx >> 8; n = idx & 255; src = W_emb; doff = WOFF_EMB;
    } else {
        int idx2 = idx - WOFF_CONV;
        int m = idx2 >> 16;
        int rem = idx2 & 65535;
        K = HD; k = rem >> 8; n = rem & 255;
        src = (m < 3) ? (W_conv + (size_t)m * HD * HD) : W1;
        doff = WOFF_CONV + m * 65536;
    }
    float v = src[k * HD + n];
    __nv_bfloat16 h = __float2bfloat16(v);
    __nv_bfloat16 l = __float2bfloat16(v - __bfloat162float(h));
    g_Bh[doff + n * K + k] = h;
    g_Bl[doff + n * K + k] = l;
}

// -------- warp-MMA GEMM: C[M,256] = A'[M,K] @ (Bh+Bl)^T -------------------
// A fp32; loader applies optional BN+ReLU (prep'd in prologue from raw stats)
// and Markidis hi/lo split. EPI 0: float C = A'@B + bias
//                           EPI 1: half C = (A'@B) * g_dinv[row]
__device__ __forceinline__ void mma16816(float* d,
    uint32_t a0, uint32_t a1, uint32_t a2, uint32_t a3,
    uint32_t b0, uint32_t b1)
{
    asm volatile(
        "mma.sync.aligned.m16n8k16.row.col.f32.bf16.bf16.f32 "
        "{%0,%1,%2,%3}, {%4,%5,%6,%7}, {%8,%9}, {%0,%1,%2,%3};"
        : "+f"(d[0]), "+f"(d[1]), "+f"(d[2]), "+f"(d[3])
        : "r"(a0), "r"(a1), "r"(a2), "r"(a3), "r"(b0), "r"(b1));
}

#define SROW 72
#define MG_TS (128 * SROW)
#define MG_SMEM (4 * MG_TS * 2)        // 73728 bytes dynamic

template <int EPI, int BN_IN>
__global__ void __launch_bounds__(256, 2) mgemm(
    const float* __restrict__ A,
    const __nv_bfloat16* __restrict__ Bh, const __nv_bfloat16* __restrict__ Bl,
    const float* __restrict__ bias, void* __restrict__ Cv, int M, int K,
    const float* __restrict__ gamma, const float* __restrict__ beta,
    float invN, int layer)
{
    extern __shared__ __nv_bfloat16 sm[];
    __nv_bfloat16* sAh = sm;
    __nv_bfloat16* sAl = sm + MG_TS;
    __nv_bfloat16* sBh = sm + 2 * MG_TS;
    __nv_bfloat16* sBl = sm + 3 * MG_TS;
    __shared__ float sbn[2 * HD];

    const int tid  = threadIdx.x;
    const int lane = tid & 31;
    const int warp = tid >> 5;
    const int wm   = warp & 3;
    const int wn   = warp >> 2;
    const int m0   = blockIdx.x * 128;
    const int n0   = blockIdx.y * 128;
    const int lr   = lane >> 2;
    const int lc   = (lane & 3) * 2;

    if (BN_IN) {
        if (tid < HD) {
            float mu  = g_sum[layer * HD + tid] * invN;
            float var = fmaxf(g_sqs[layer * HD + tid] * invN - mu * mu, 0.f);
            float a   = gamma[tid] * rsqrtf(var + BN_EPS);
            sbn[tid]      = a;
            sbn[HD + tid] = beta[tid] - mu * a;
        }
        __syncthreads();
    }

    float acc[2][8][4];
#pragma unroll
    for (int i = 0; i < 2; i++)
#pragma unroll
        for (int j = 0; j < 8; j++)
#pragma unroll
            for (int q = 0; q < 4; q++) acc[i][j][q] = 0.f;

    for (int k0 = 0; k0 < K; k0 += 64) {
#pragma unroll
        for (int t = 0; t < 8; t++) {
            int idx = tid + t * 256;
            int row = idx >> 4;
            int seg = idx & 15;
            int gcol = k0 + seg * 4;
            float4 v = make_float4(0.f, 0.f, 0.f, 0.f);
            if (m0 + row < M)
                v = *(const float4*)(A + (size_t)(m0 + row) * K + gcol);
            if (BN_IN) {
                float4 a = *(const float4*)&sbn[gcol];
                float4 b = *(const float4*)&sbn[HD + gcol];
                v.x = fmaxf(fmaf(v.x, a.x, b.x), 0.f);
                v.y = fmaxf(fmaf(v.y, a.y, b.y), 0.f);
                v.z = fmaxf(fmaf(v.z, a.z, b.z), 0.f);
                v.w = fmaxf(fmaf(v.w, a.w, b.w), 0.f);
            }
            __nv_bfloat16 hx = __float2bfloat16(v.x), hy = __float2bfloat16(v.y);
            __nv_bfloat16 hz = __float2bfloat16(v.z), hw = __float2bfloat16(v.w);
            __nv_bfloat16 lx = __float2bfloat16(v.x - __bfloat162float(hx));
            __nv_bfloat16 ly = __float2bfloat16(v.y - __bfloat162float(hy));
            __nv_bfloat16 lz = __float2bfloat16(v.z - __bfloat162float(hz));
            __nv_bfloat16 lw = __float2bfloat16(v.w - __bfloat162float(hw));
            int so = row * SROW + seg * 4;
            *(__nv_bfloat162*)&sAh[so]     = __nv_bfloat162(hx, hy);
            *(__nv_bfloat162*)&sAh[so + 2] = __nv_bfloat162(hz, hw);
            *(__nv_bfloat162*)&sAl[so]     = __nv_bfloat162(lx, ly);
            *(__nv_bfloat162*)&sAl[so + 2] = __nv_bfloat162(lz, lw);
        }
#pragma unroll
        for (int t = 0; t < 4; t++) {
            int idx = tid + t * 256;
            int row = idx >> 3;
            int seg = idx & 7;
            size_t gb = (size_t)(n0 + row) * K + k0 + seg * 8;
            uint32_t so = row * (SROW * 2) + seg * 16;
            *(uint4*)((char*)sBh + so) = *(const uint4*)(Bh + gb);
            *(uint4*)((char*)sBl + so) = *(const uint4*)(Bl + gb);
        }
        __syncthreads();
#pragma unroll
        for (int ks = 0; ks < 4; ks++) {
            const int kk = ks * 16 + lc;
            uint32_t ah[2][4], al[2][4];
#pragma unroll
            for (int mi = 0; mi < 2; mi++) {
                int r = wm * 32 + mi * 16 + lr;
                ah[mi][0] = *(const uint32_t*)&sAh[r * SROW + kk];
                ah[mi][1] = *(const uint32_t*)&sAh[(r + 8) * SROW + kk];
                ah[mi][2] = *(const uint32_t*)&sAh[r * SROW + kk + 8];
                ah[mi][3] = *(const uint32_t*)&sAh[(r + 8) * SROW + kk + 8];
                al[mi][0] = *(const uint32_t*)&sAl[r * SROW + kk];
                al[mi][1] = *(const uint32_t*)&sAl[(r + 8) * SROW + kk];
                al[mi][2] = *(const uint32_t*)&sAl[r * SROW + kk + 8];
                al[mi][3] = *(const uint32_t*)&sAl[(r + 8) * SROW + kk + 8];
            }
            // per-ni B fragment loads keep live regs low (2-CTA occupancy)
#pragma unroll
            for (int ni = 0; ni < 8; ni++) {
                int n = wn * 64 + ni * 8 + lr;
                uint32_t b0 = *(const uint32_t*)&sBh[n * SROW + kk];
                uint32_t b1 = *(const uint32_t*)&sBh[n * SROW + kk + 8];
                uint32_t c0 = *(const uint32_t*)&sBl[n * SROW + kk];
                uint32_t c1 = *(const uint32_t*)&sBl[n * SROW + kk + 8];
#pragma unroll
                for (int mi = 0; mi < 2; mi++) {
                    mma16816(acc[mi][ni], ah[mi][0], ah[mi][1], ah[mi][2], ah[mi][3], b0, b1);
                    mma16816(acc[mi][ni], ah[mi][0], ah[mi][1], ah[mi][2], ah[mi][3], c0, c1);
                    mma16816(acc[mi][ni], al[mi][0], al[mi][1], al[mi][2], al[mi][3], b0, b1);
                }
            }
        }
        __syncthreads();
    }

    const int rb = m0 + wm * 32;
    const int cb = n0 + wn * 64;
#pragma unroll
    for (int mi = 0; mi < 2; mi++) {
#pragma unroll
        for (int half = 0; half < 2; half++) {
            int r = rb + mi * 16 + lr + half * 8;
            if (r >= M) continue;
            float sc = (EPI == 1) ? g_dinv[r] : 0.f;
#pragma unroll
            for (int ni = 0; ni < 8; ni++) {
                int c = cb + ni * 8 + lc;
                float v0 = acc[mi][ni][half * 2 + 0];
                float v1 = acc[mi][ni][half * 2 + 1];
                if (EPI == 0) {
                    v0 += bias[c]; v1 += bias[c + 1];
                    *(float2*)((float*)Cv + (size_t)r * HD + c) = make_float2(v0, v1);
                } else {
                    v0 *= sc; v1 *= sc;
                    *(__half2*)((__half*)Cv + (size_t)r * HD + c) =
                        __floats2half2_rn(v0, v1);
                }
            }
        }
    }
}

// ---- aggregation + fused BN stats: h[d] = (u[d]+sum u[src])*dinv + b -----
__global__ void __launch_bounds__(256) aggregate_kernel(
    const float* __restrict__ bias, int layer)
{
    __shared__ float ssum[HD];
    __shared__ float ssqs[HD];
    for (int i = threadIdx.x; i < HD; i += 256) { ssum[i] = 0.f; ssqs[i] = 0.f; }
    __syncthreads();

    int wp   = threadIdx.x >> 6;
    int half = (threadIdx.x >> 5) & 1;
    int lane = threadIdx.x & 31;
    int base = blockIdx.x * 32 + wp * 8;
    int coff = half * 32 + lane;

    const uint2* up = (const uint2*)g_uh;
    float4* hp = (float4*)g_h + half * 32;
    float4 bb = ((const float4*)bias)[half * 32 + lane];
    float4 s = make_float4(0, 0, 0, 0), q = s;

    for (int nidx = 0; nidx < 8; nidx++) {
        int node = base + nidx;
        if (node >= NN) break;
        uint2 raw = up[(size_t)node * 64 + coff];
        float2 f0 = __half22float2(*(__half2*)&raw.x);
        float2 f1 = __half22float2(*(__half2*)&raw.y);
        float4 a = make_float4(f0.x, f0.y, f1.x, f1.y);
        int beg = g_rowptr[node];
        int end = beg + g_deg[node];
        int j = beg;
        for (; j + 1 < end; j += 2) {
            int s0 = g_srcs[j], s1 = g_srcs[j + 1];
            uint2 r0 = up[(size_t)s0 * 64 + coff];
            uint2 r1 = up[(size_t)s1 * 64 + coff];
            float2 a0 = __half22float2(*(__half2*)&r0.x);
            float2 a1 = __half22float2(*(__half2*)&r0.y);
            float2 b0 = __half22float2(*(__half2*)&r1.x);
            float2 b1 = __half22float2(*(__half2*)&r1.y);
            a.x += a0.x + b0.x; a.y += a0.y + b0.y;
            a.z += a1.x + b1.x; a.w += a1.y + b1.y;
        }
        if (j < end) {
            uint2 r0 = up[(size_t)g_srcs[j] * 64 + coff];
            float2 a0 = __half22float2(*(__half2*)&r0.x);
            float2 a1 = __half22float2(*(__half2*)&r0.y);
            a.x += a0.x; a.y += a0.y; a.z += a1.x; a.w += a1.y;
        }
        float dv = g_dinv[node];
        a.x = fmaf(a.x, dv, bb.x); a.y = fmaf(a.y, dv, bb.y);
        a.z = fmaf(a.z, dv, bb.z); a.w = fmaf(a.w, dv, bb.w);
        hp[(size_t)node * 64 + lane] = a;
        s.x += a.x; s.y += a.y; s.z += a.z; s.w += a.w;
        q.x += a.x*a.x; q.y += a.y*a.y; q.z += a.z*a.z; q.w += a.w*a.w;
    }

    int c = half * 128 + lane * 4;
    atomicAdd(&ssum[c+0], s.x); atomicAdd(&ssum[c+1], s.y);
    atomicAdd(&ssum[c+2], s.z); atomicAdd(&ssum[c+3], s.w);
    atomicAdd(&ssqs[c+0], q.x); atomicAdd(&ssqs[c+1], q.y);
    atomicAdd(&ssqs[c+2], q.z); atomicAdd(&ssqs[c+3], q.w);
    __syncthreads();
    atomicAdd(&g_sum[layer * HD + threadIdx.x], ssum[threadIdx.x]);
    atomicAdd(&g_sqs[layer * HD + threadIdx.x], ssqs[threadIdx.x]);
}

// ---------------- z stats ----------------
__global__ void __launch_bounds__(256) stats_cols_kernel(
    const float* __restrict__ X, int rows, int layer)
{
    int c  = threadIdx.x;
    int r0 = blockIdx.x * 64;
    int r1 = min(r0 + 64, rows);
    float s = 0.f, s2 = 0.f;
    for (int r = r0; r < r1; r++) {
        float v = X[(size_t)r * HD + c];
        s += v;
        s2 += v * v;
    }
    atomicAdd(&g_sum[layer * HD + c], s);
    atomicAdd(&g_sqs[layer * HD + c], s2);
}

// ---- pooling; applies layer-2 BN+ReLU computed inline from raw stats -----
__global__ void __launch_bounds__(256) pool_kernel(
    const int* __restrict__ batch,
    const float* __restrict__ gamma, const float* __restrict__ beta)
{
    int g = blockIdx.x;
    __shared__ int s_lo, s_hi;
    if (threadIdx.x < 2) {
        int key = g + threadIdx.x;
        int lo = 0, hi = NN;
        while (lo < hi) {
            int mid = (lo + hi) >> 1;
            if (batch[mid] < key) lo = mid + 1; else hi = mid;
        }
        if (threadIdx.x == 0) s_lo = lo; else s_hi = lo;
    }
    __syncthreads();
    int lo = s_lo, hi = s_hi;
    int c = threadIdx.x;
    float mu  = g_sum[2 * HD + c] * (1.0f / NN);
    float var = fmaxf(g_sqs[2 * HD + c] * (1.0f / NN) - mu * mu, 0.f);
    float a   = gamma[c] * rsqrtf(var + BN_EPS);
    float b   = beta[c] - mu * a;
    float s = 0.f;
    for (int r = lo; r < hi; r++)
        s += fmaxf(fmaf(g_h[(size_t)r * HD + c], a, b), 0.f);
    float cnt = (float)(hi - lo);
    g_pool[g * HD + c] = s / fmaxf(cnt, 1.f);
}

// ---- head with fused z-BN+ReLU: out[g] = relu(bn(z[g,:])) . W2 + b2 ------
__global__ void __launch_bounds__(256) head_kernel(
    const float* __restrict__ W2, const float* __restrict__ b2,
    const float* __restrict__ g2, const float* __restrict__ bt2,
    float* __restrict__ out)
{
    int g    = (int)((blockIdx.x * 256 + threadIdx.x) >> 5);
    int lane = threadIdx.x & 31;
    if (g >= NG) return;
    const float* zrow = &g_z[(size_t)g * HD];
    float s = 0.f;
#pragma unroll
    for (int t = 0; t < 2; t++) {
        int c4 = (t * 32 + lane) * 4;
        float4 z = *(const float4*)(zrow + c4);
        float4 w = *(const float4*)(W2 + c4);
        float zv[4] = {z.x, z.y, z.z, z.w};
        float wv[4] = {w.x, w.y, w.z, w.w};
#pragma unroll
        for (int qq = 0; qq < 4; qq++) {
            int c = c4 + qq;
            float mu  = g_sum[3 * HD + c] * (1.0f / NG);
            float var = fmaxf(g_sqs[3 * HD + c] * (1.0f / NG) - mu * mu, 0.f);
            float a   = g2[c] * rsqrtf(var + BN_EPS);
            float b   = bt2[c] - mu * a;
            s += fmaxf(fmaf(zv[qq], a, b), 0.f) * wv[qq];
        }
    }
#pragma unroll
    for (int o = 16; o > 0; o >>= 1) s += __shfl_xor_sync(0xffffffffu, s, o);
    if (lane == 0) out[g] = s + b2[0];
}

// ---------------- launch ----------------
extern "C" void kernel_launch(void* const* d_in, const int* in_sizes, int n_in,
                              void* d_out, int out_size)
{
    (void)in_sizes; (void)n_in; (void)out_size;
    const float* x        = (const float*)d_in[0];
    const int*   ei       = (const int*)d_in[1];
    const int*   batch    = (const int*)d_in[2];
    const float* W_emb    = (const float*)d_in[3];
    const float* b_emb    = (const float*)d_in[4];
    const float* W_conv   = (const float*)d_in[5];
    const float* b_conv   = (const float*)d_in[6];
    const float* bn_gamma = (const float*)d_in[7];
    const float* bn_beta  = (const float*)d_in[8];
    const float* W1       = (const float*)d_in[9];
    const float* b1       = (const float*)d_in[10];
    const float* g2       = (const float*)d_in[11];
    const float* bt2      = (const float*)d_in[12];
    const float* W2       = (const float*)d_in[13];
    const float* b2       = (const float*)d_in[14];
    float*       out      = (float*)d_out;

    const int* src = ei;
    const int* dst = ei + NE;

    float *p_h, *p_pool, *p_z;
    __half *p_uh;
    __nv_bfloat16 *p_Bh, *p_Bl;
    cudaGetSymbolAddress((void**)&p_h,    g_h);
    cudaGetSymbolAddress((void**)&p_uh,   g_uh);
    cudaGetSymbolAddress((void**)&p_pool, g_pool);
    cudaGetSymbolAddress((void**)&p_z,    g_z);
    cudaGetSymbolAddress((void**)&p_Bh,   g_Bh);
    cudaGetSymbolAddress((void**)&p_Bl,   g_Bl);

    cudaFuncSetAttribute(mgemm<0,0>, cudaFuncAttributeMaxDynamicSharedMemorySize, MG_SMEM);
    cudaFuncSetAttribute(mgemm<1,0>, cudaFuncAttributeMaxDynamicSharedMemorySize, MG_SMEM);
    cudaFuncSetAttribute(mgemm<1,1>, cudaFuncAttributeMaxDynamicSharedMemorySize, MG_SMEM);

    // weight splits first (input-only dependency)
    splitW_all_kernel<<<(WTOT + 255) / 256, 256>>>(W_emb, W_conv, W1);

    // CSR setup (+ zero all 4 BN stat slices)
    zero_deg_kernel<<<(NN + 255) / 256, 256>>>();
    edge_deg_kernel<<<(NE + 255) / 256, 256>>>(dst);
    scan1_kernel<<<NB, 256>>>();
    scan2_kernel<<<1, 256>>>();
    scan3_kernel<<<NB, 256>>>();
    bucket_kernel<<<(NE + 255) / 256, 256>>>(src, dst);

    const dim3 GR(MPAD / 128, 2);   // 391 x 2

    // embedding: h = x @ W_emb + b_emb
    mgemm<0,0><<<GR, 256, MG_SMEM>>>(x, p_Bh + WOFF_EMB, p_Bl + WOFF_EMB,
                                     b_emb, p_h, NN, INC,
                                     nullptr, nullptr, 0.f, 0);

    // GCN layers (BN of prev layer computed in mgemm prologue from raw stats)
    for (int l = 0; l < 3; l++) {
        const __nv_bfloat16* bh = p_Bh + WOFF_CONV + l * 65536;
        const __nv_bfloat16* bl = p_Bl + WOFF_CONV + l * 65536;
        if (l == 0)
            mgemm<1,0><<<GR, 256, MG_SMEM>>>(p_h, bh, bl, nullptr, p_uh, NN, HD,
                                             nullptr, nullptr, 0.f, 0);
        else
            mgemm<1,1><<<GR, 256, MG_SMEM>>>(p_h, bh, bl, nullptr, p_uh, NN, HD,
                                             bn_gamma + (size_t)(l - 1) * HD,
                                             bn_beta + (size_t)(l - 1) * HD,
                                             1.0f / NN, l - 1);
        aggregate_kernel<<<(NN + 31) / 32, 256>>>(b_conv + (size_t)l * HD, l);
    }

    // pooling (layer-2 BN+ReLU inline)
    pool_kernel<<<NG, HD>>>(batch, bn_gamma + 2 * HD, bn_beta + 2 * HD);

    // MLP head
    mgemm<0,0><<<dim3(NG / 128, 2), 256, MG_SMEM>>>(
        p_pool, p_Bh + WOFF_W1, p_Bl + WOFF_W1, b1, p_z, NG, HD,
        nullptr, nullptr, 0.f, 0);
    stats_cols_kernel<<<(NG + 63) / 64, 256>>>(p_z, NG, 3);
    head_kernel<<<(NG * 32 + 255) / 256, 256>>>(W2, b2, g2, bt2, out);
}

// round 15
// speedup vs baseline: 2.1497x; 1.1455x over previous
#include <cuda_runtime.h>
#include <cuda_bf16.h>
#include <cuda_fp16.h>
#include <cstdint>

#define NN 50000
#define MPAD 50048          // 391 * 128
#define NE 800000
#define INC 128
#define HD 256
#define NG 1024
#define BN_EPS 1e-5f
#define NB 196              // ceil(NN/256)

// weight-split buffer offsets (transposed [n][k] layout per matrix)
#define WOFF_EFF  0                 // W_eff = W_emb@W_conv0  (K=128)
#define WOFF_C1   32768             // conv layer 1 (K=256)
#define WOFF_C2   98304             // conv layer 2 (K=256)
#define WOFF_W1   163840            // MLP W1       (K=256)
#define WTOT      229376
#define WBIG      196608            // the 3 K=256 matrices

// ---------------- scratch (device globals: allocation-free) ----------------
__device__ int    g_deg[NN];
__device__ int    g_rowptr[NN];
__device__ int    g_cursor[NN];
__device__ int    g_bsum[NB];
__device__ int    g_srcs[NE];
__device__ float  g_dinv[NN];
__device__ float  g_h[(size_t)MPAD * HD];
__device__ __half g_uh[(size_t)MPAD * HD];
__device__ float  g_pool[NG * HD];
__device__ float  g_z[NG * HD];
__device__ float  g_sum[4 * HD];
__device__ float  g_sqs[4 * HD];
__device__ float  g_beff[HD];
__device__ __nv_bfloat16 g_Bh[WTOT];
__device__ __nv_bfloat16 g_Bl[WTOT];

// ---------------- setup ----------------
__global__ void zero_deg_kernel() {
    int i = blockIdx.x * blockDim.x + threadIdx.x;
    if (i < NN) { g_deg[i] = 0; g_cursor[i] = 0; }
    if (i < 4 * HD) { g_sum[i] = 0.f; g_sqs[i] = 0.f; }
}
__global__ void edge_deg_kernel(const int* __restrict__ dst) {
    int e = blockIdx.x * blockDim.x + threadIdx.x;
    if (e < NE) atomicAdd(&g_deg[dst[e]], 1);
}
__global__ void scan1_kernel() {
    __shared__ int sh[256];
    int tid = threadIdx.x;
    int i = blockIdx.x * 256 + tid;
    int v = (i < NN) ? g_deg[i] : 0;
    sh[tid] = v;
    __syncthreads();
#pragma unroll
    for (int off = 1; off < 256; off <<= 1) {
        int t = (tid >= off) ? sh[tid - off] : 0;
        __syncthreads();
        sh[tid] += t;
        __syncthreads();
    }
    if (i < NN) g_rowptr[i] = sh[tid] - v;
    if (tid == 255) g_bsum[blockIdx.x] = sh[255];
}
__global__ void scan2_kernel() {
    __shared__ int sh[256];
    int tid = threadIdx.x;
    int v = (tid < NB) ? g_bsum[tid] : 0;
    sh[tid] = v;
    __syncthreads();
#pragma unroll
    for (int off = 1; off < 256; off <<= 1) {
        int t = (tid >= off) ? sh[tid - off] : 0;
        __syncthreads();
        sh[tid] += t;
        __syncthreads();
    }
    if (tid < NB) g_bsum[tid] = sh[tid] - v;
}
__global__ void scan3_kernel() {
    int i = blockIdx.x * 256 + threadIdx.x;
    if (i < NN) {
        g_rowptr[i] += g_bsum[blockIdx.x];
        g_dinv[i] = rsqrtf((float)(g_deg[i] + 1));
    }
}
__global__ void bucket_kernel(const int* __restrict__ src,
                              const int* __restrict__ dst) {
    int e = blockIdx.x * blockDim.x + threadIdx.x;
    if (e >= NE) return;
    int d = dst[e];
    int pos = atomicAdd(&g_cursor[d], 1);
    g_srcs[g_rowptr[d] + pos] = src[e];
}

// ---- split + transpose the 3 K=256 weights (conv1, conv2, W1) ------------
__global__ void __launch_bounds__(256) splitW_all_kernel(
    const float* __restrict__ W_conv, const float* __restrict__ W1)
{
    int idx = blockIdx.x * 256 + threadIdx.x;
    if (idx >= WBIG) return;
    int m   = idx >> 16;          // 0,1 -> conv1/2 ; 2 -> W1
    int rem = idx & 65535;
    int k = rem >> 8;
    int n = rem & 255;
    const float* src = (m < 2) ? (W_conv + (size_t)(m + 1) * HD * HD) : W1;
    int doff = WOFF_C1 + m * 65536;
    float v = src[k * HD + n];
    __nv_bfloat16 h = __float2bfloat16(v);
    __nv_bfloat16 l = __float2bfloat16(v - __bfloat162float(h));
    g_Bh[doff + n * HD + k] = h;
    g_Bl[doff + n * HD + k] = l;
}

// ---- W_eff = W_emb @ W_conv0 (fp32), split into WOFF_EFF; b_eff = b_emb@W0
// grid 129 blocks x 256 thr: block k<128 computes row k; block 128 -> b_eff.
__global__ void __launch_bounds__(256) weff_kernel(
    const float* __restrict__ W_emb, const float* __restrict__ W0,
    const float* __restrict__ b_emb)
{
    int n = threadIdx.x;
    int k = blockIdx.x;
    if (k < INC) {
        float acc = 0.f;
        for (int c = 0; c < HD; c++)
            acc = fmaf(W_emb[k * HD + c], W0[c * HD + n], acc);
        __nv_bfloat16 h = __float2bfloat16(acc);
        __nv_bfloat16 l = __float2bfloat16(acc - __bfloat162float(h));
        g_Bh[WOFF_EFF + n * INC + k] = h;
        g_Bl[WOFF_EFF + n * INC + k] = l;
    } else {
        float acc = 0.f;
        for (int c = 0; c < HD; c++)
            acc = fmaf(b_emb[c], W0[c * HD + n], acc);
        g_beff[n] = acc;
    }
}

// -------- warp-MMA GEMM: C[M,256] = A'[M,K] @ (Bh+Bl)^T -------------------
// A fp32; loader applies optional BN+ReLU (prep'd in prologue from raw stats)
// and Markidis hi/lo split. EPI 0: float C = A'@B + bias
//                           EPI 1: half  C = (A'@B) * dinv[row]
//                           EPI 2: half  C = (A'@B + bias) * dinv[row]
__device__ __forceinline__ void mma16816(float* d,
    uint32_t a0, uint32_t a1, uint32_t a2, uint32_t a3,
    uint32_t b0, uint32_t b1)
{
    asm volatile(
        "mma.sync.aligned.m16n8k16.row.col.f32.bf16.bf16.f32 "
        "{%0,%1,%2,%3}, {%4,%5,%6,%7}, {%8,%9}, {%0,%1,%2,%3};"
        : "+f"(d[0]), "+f"(d[1]), "+f"(d[2]), "+f"(d[3])
        : "r"(a0), "r"(a1), "r"(a2), "r"(a3), "r"(b0), "r"(b1));
}

#define SROW 72
#define MG_TS (128 * SROW)
#define MG_SMEM (4 * MG_TS * 2)        // 73728 bytes dynamic

template <int EPI, int BN_IN>
__global__ void __launch_bounds__(256, 2) mgemm(
    const float* __restrict__ A,
    const __nv_bfloat16* __restrict__ Bh, const __nv_bfloat16* __restrict__ Bl,
    const float* __restrict__ bias, void* __restrict__ Cv, int M, int K,
    const float* __restrict__ gamma, const float* __restrict__ beta,
    float invN, int layer)
{
    extern __shared__ __nv_bfloat16 sm[];
    __nv_bfloat16* sAh = sm;
    __nv_bfloat16* sAl = sm + MG_TS;
    __nv_bfloat16* sBh = sm + 2 * MG_TS;
    __nv_bfloat16* sBl = sm + 3 * MG_TS;
    __shared__ float sbn[2 * HD];

    const int tid  = threadIdx.x;
    const int lane = tid & 31;
    const int warp = tid >> 5;
    const int wm   = warp & 3;
    const int wn   = warp >> 2;
    const int m0   = blockIdx.x * 128;
    const int n0   = blockIdx.y * 128;
    const int lr   = lane >> 2;
    const int lc   = (lane & 3) * 2;

    if (BN_IN) {
        if (tid < HD) {
            float mu  = g_sum[layer * HD + tid] * invN;
            float var = fmaxf(g_sqs[layer * HD + tid] * invN - mu * mu, 0.f);
            float a   = gamma[tid] * rsqrtf(var + BN_EPS);
            sbn[tid]      = a;
            sbn[HD + tid] = beta[tid] - mu * a;
        }
        __syncthreads();
    }

    float acc[2][8][4];
#pragma unroll
    for (int i = 0; i < 2; i++)
#pragma unroll
        for (int j = 0; j < 8; j++)
#pragma unroll
            for (int q = 0; q < 4; q++) acc[i][j][q] = 0.f;

    for (int k0 = 0; k0 < K; k0 += 64) {
#pragma unroll
        for (int t = 0; t < 8; t++) {
            int idx = tid + t * 256;
            int row = idx >> 4;
            int seg = idx & 15;
            int gcol = k0 + seg * 4;
            float4 v = make_float4(0.f, 0.f, 0.f, 0.f);
            if (m0 + row < M)
                v = *(const float4*)(A + (size_t)(m0 + row) * K + gcol);
            if (BN_IN) {
                float4 a = *(const float4*)&sbn[gcol];
                float4 b = *(const float4*)&sbn[HD + gcol];
                v.x = fmaxf(fmaf(v.x, a.x, b.x), 0.f);
                v.y = fmaxf(fmaf(v.y, a.y, b.y), 0.f);
                v.z = fmaxf(fmaf(v.z, a.z, b.z), 0.f);
                v.w = fmaxf(fmaf(v.w, a.w, b.w), 0.f);
            }
            __nv_bfloat16 hx = __float2bfloat16(v.x), hy = __float2bfloat16(v.y);
            __nv_bfloat16 hz = __float2bfloat16(v.z), hw = __float2bfloat16(v.w);
            __nv_bfloat16 lx = __float2bfloat16(v.x - __bfloat162float(hx));
            __nv_bfloat16 ly = __float2bfloat16(v.y - __bfloat162float(hy));
            __nv_bfloat16 lz = __float2bfloat16(v.z - __bfloat162float(hz));
            __nv_bfloat16 lw = __float2bfloat16(v.w - __bfloat162float(hw));
            int so = row * SROW + seg * 4;
            *(__nv_bfloat162*)&sAh[so]     = __nv_bfloat162(hx, hy);
            *(__nv_bfloat162*)&sAh[so + 2] = __nv_bfloat162(hz, hw);
            *(__nv_bfloat162*)&sAl[so]     = __nv_bfloat162(lx, ly);
            *(__nv_bfloat162*)&sAl[so + 2] = __nv_bfloat162(lz, lw);
        }
#pragma unroll
        for (int t = 0; t < 4; t++) {
            int idx = tid + t * 256;
            int row = idx >> 3;
            int seg = idx & 7;
            size_t gb = (size_t)(n0 + row) * K + k0 + seg * 8;
            uint32_t so = row * (SROW * 2) + seg * 16;
            *(uint4*)((char*)sBh + so) = *(const uint4*)(Bh + gb);
            *(uint4*)((char*)sBl + so) = *(const uint4*)(Bl + gb);
        }
        __syncthreads();
#pragma unroll
        for (int ks = 0; ks < 4; ks++) {
            const int kk = ks * 16 + lc;
            uint32_t ah[2][4], al[2][4];
#pragma unroll
            for (int mi = 0; mi < 2; mi++) {
                int r = wm * 32 + mi * 16 + lr;
                ah[mi][0] = *(const uint32_t*)&sAh[r * SROW + kk];
                ah[mi][1] = *(const uint32_t*)&sAh[(r + 8) * SROW + kk];
                ah[mi][2] = *(const uint32_t*)&sAh[r * SROW + kk + 8];
                ah[mi][3] = *(const uint32_t*)&sAh[(r + 8) * SROW + kk + 8];
                al[mi][0] = *(const uint32_t*)&sAl[r * SROW + kk];
                al[mi][1] = *(const uint32_t*)&sAl[(r + 8) * SROW + kk];
                al[mi][2] = *(const uint32_t*)&sAl[r * SROW + kk + 8];
                al[mi][3] = *(const uint32_t*)&sAl[(r + 8) * SROW + kk + 8];
            }
#pragma unroll
            for (int ni = 0; ni < 8; ni++) {
                int n = wn * 64 + ni * 8 + lr;
                uint32_t b0 = *(const uint32_t*)&sBh[n * SROW + kk];
                uint32_t b1 = *(const uint32_t*)&sBh[n * SROW + kk + 8];
                uint32_t c0 = *(const uint32_t*)&sBl[n * SROW + kk];
                uint32_t c1 = *(const uint32_t*)&sBl[n * SROW + kk + 8];
#pragma unroll
                for (int mi = 0; mi < 2; mi++) {
                    mma16816(acc[mi][ni], ah[mi][0], ah[mi][1], ah[mi][2], ah[mi][3], b0, b1);
                    mma16816(acc[mi][ni], ah[mi][0], ah[mi][1], ah[mi][2], ah[mi][3], c0, c1);
                    mma16816(acc[mi][ni], al[mi][0], al[mi][1], al[mi][2], al[mi][3], b0, b1);
                }
            }
        }
        __syncthreads();
    }

    const int rb = m0 + wm * 32;
    const int cb = n0 + wn * 64;
#pragma unroll
    for (int mi = 0; mi < 2; mi++) {
#pragma unroll
        for (int half = 0; half < 2; half++) {
            int r = rb + mi * 16 + lr + half * 8;
            if (r >= M) continue;
            float sc = (EPI >= 1) ? g_dinv[r] : 0.f;
#pragma unroll
            for (int ni = 0; ni < 8; ni++) {
                int c = cb + ni * 8 + lc;
                float v0 = acc[mi][ni][half * 2 + 0];
                float v1 = acc[mi][ni][half * 2 + 1];
                if (EPI == 0) {
                    v0 += bias[c]; v1 += bias[c + 1];
                    *(float2*)((float*)Cv + (size_t)r * HD + c) = make_float2(v0, v1);
                } else {
                    if (EPI == 2) { v0 += bias[c]; v1 += bias[c + 1]; }
                    v0 *= sc; v1 *= sc;
                    *(__half2*)((__half*)Cv + (size_t)r * HD + c) =
                        __floats2half2_rn(v0, v1);
                }
            }
        }
    }
}

// ---- aggregation + fused BN stats: h[d] = (u[d]+sum u[src])*dinv + b -----
// u fp16; fp32 accumulation; 4-wide edge unroll for MLP.
__global__ void __launch_bounds__(256) aggregate_kernel(
    const float* __restrict__ bias, int layer)
{
    __shared__ float ssum[HD];
    __shared__ float ssqs[HD];
    for (int i = threadIdx.x; i < HD; i += 256) { ssum[i] = 0.f; ssqs[i] = 0.f; }
    __syncthreads();

    int wp   = threadIdx.x >> 6;
    int half = (threadIdx.x >> 5) & 1;
    int lane = threadIdx.x & 31;
    int base = blockIdx.x * 32 + wp * 8;
    int coff = half * 32 + lane;

    const uint2* up = (const uint2*)g_uh;
    float4* hp = (float4*)g_h + half * 32;
    float4 bb = ((const float4*)bias)[half * 32 + lane];
    float4 s = make_float4(0, 0, 0, 0), q = s;

    for (int nidx = 0; nidx < 8; nidx++) {
        int node = base + nidx;
        if (node >= NN) break;
        uint2 raw = up[(size_t)node * 64 + coff];
        float2 f0 = __half22float2(*(__half2*)&raw.x);
        float2 f1 = __half22float2(*(__half2*)&raw.y);
        float4 a = make_float4(f0.x, f0.y, f1.x, f1.y);
        int beg = g_rowptr[node];
        int end = beg + g_deg[node];
        int j = beg;
        int n4 = beg + ((end - beg) & ~3);
        for (; j < n4; j += 4) {
            int s0 = g_srcs[j],     s1 = g_srcs[j + 1];
            int s2 = g_srcs[j + 2], s3 = g_srcs[j + 3];
            uint2 r0 = up[(size_t)s0 * 64 + coff];
            uint2 r1 = up[(size_t)s1 * 64 + coff];
            uint2 r2 = up[(size_t)s2 * 64 + coff];
            uint2 r3 = up[(size_t)s3 * 64 + coff];
            float2 p0 = __half22float2(*(__half2*)&r0.x);
            float2 p1 = __half22float2(*(__half2*)&r0.y);
            float2 p2 = __half22float2(*(__half2*)&r1.x);
            float2 p3 = __half22float2(*(__half2*)&r1.y);
            float2 p4 = __half22float2(*(__half2*)&r2.x);
            float2 p5 = __half22float2(*(__half2*)&r2.y);
            float2 p6 = __half22float2(*(__half2*)&r3.x);
            float2 p7 = __half22float2(*(__half2*)&r3.y);
            a.x += (p0.x + p2.x) + (p4.x + p6.x);
            a.y += (p0.y + p2.y) + (p4.y + p6.y);
            a.z += (p1.x + p3.x) + (p5.x + p7.x);
            a.w += (p1.y + p3.y) + (p5.y + p7.y);
        }
        for (; j < end; j++) {
            uint2 r0 = up[(size_t)g_srcs[j] * 64 + coff];
            float2 a0 = __half22float2(*(__half2*)&r0.x);
            float2 a1 = __half22float2(*(__half2*)&r0.y);
            a.x += a0.x; a.y += a0.y; a.z += a1.x; a.w += a1.y;
        }
        float dv = g_dinv[node];
        a.x = fmaf(a.x, dv, bb.x); a.y = fmaf(a.y, dv, bb.y);
        a.z = fmaf(a.z, dv, bb.z); a.w = fmaf(a.w, dv, bb.w);
        hp[(size_t)node * 64 + lane] = a;
        s.x += a.x; s.y += a.y; s.z += a.z; s.w += a.w;
        q.x += a.x*a.x; q.y += a.y*a.y; q.z += a.z*a.z; q.w += a.w*a.w;
    }

    int c = half * 128 + lane * 4;
    atomicAdd(&ssum[c+0], s.x); atomicAdd(&ssum[c+1], s.y);
    atomicAdd(&ssum[c+2], s.z); atomicAdd(&ssum[c+3], s.w);
    atomicAdd(&ssqs[c+0], q.x); atomicAdd(&ssqs[c+1], q.y);
    atomicAdd(&ssqs[c+2], q.z); atomicAdd(&ssqs[c+3], q.w);
    __syncthreads();
    atomicAdd(&g_sum[layer * HD + threadIdx.x], ssum[threadIdx.x]);
    atomicAdd(&g_sqs[layer * HD + threadIdx.x], ssqs[threadIdx.x]);
}

// ---------------- z stats ----------------
__global__ void __launch_bounds__(256) stats_cols_kernel(
    const float* __restrict__ X, int rows, int layer)
{
    int c  = threadIdx.x;
    int r0 = blockIdx.x * 64;
    int r1 = min(r0 + 64, rows);
    float s = 0.f, s2 = 0.f;
    for (int r = r0; r < r1; r++) {
        float v = X[(size_t)r * HD + c];
        s += v;
        s2 += v * v;
    }
    atomicAdd(&g_sum[layer * HD + c], s);
    atomicAdd(&g_sqs[layer * HD + c], s2);
}

// ---- pooling; applies layer-2 BN+ReLU computed inline from raw stats -----
__global__ void __launch_bounds__(256) pool_kernel(
    const int* __restrict__ batch,
    const float* __restrict__ gamma, const float* __restrict__ beta)
{
    int g = blockIdx.x;
    __shared__ int s_lo, s_hi;
    if (threadIdx.x < 2) {
        int key = g + threadIdx.x;
        int lo = 0, hi = NN;
        while (lo < hi) {
            int mid = (lo + hi) >> 1;
            if (batch[mid] < key) lo = mid + 1; else hi = mid;
        }
        if (threadIdx.x == 0) s_lo = lo; else s_hi = lo;
    }
    __syncthreads();
    int lo = s_lo, hi = s_hi;
    int c = threadIdx.x;
    float mu  = g_sum[2 * HD + c] * (1.0f / NN);
    float var = fmaxf(g_sqs[2 * HD + c] * (1.0f / NN) - mu * mu, 0.f);
    float a   = gamma[c] * rsqrtf(var + BN_EPS);
    float b   = beta[c] - mu * a;
    float s = 0.f;
    for (int r = lo; r < hi; r++)
        s += fmaxf(fmaf(g_h[(size_t)r * HD + c], a, b), 0.f);
    float cnt = (float)(hi - lo);
    g_pool[g * HD + c] = s / fmaxf(cnt, 1.f);
}

// ---- head with fused z-BN+ReLU -------------------------------------------
__global__ void __launch_bounds__(256) head_kernel(
    const float* __restrict__ W2, const float* __restrict__ b2,
    const float* __restrict__ g2, const float* __restrict__ bt2,
    float* __restrict__ out)
{
    int g    = (int)((blockIdx.x * 256 + threadIdx.x) >> 5);
    int lane = threadIdx.x & 31;
    if (g >= NG) return;
    const float* zrow = &g_z[(size_t)g * HD];
    float s = 0.f;
#pragma unroll
    for (int t = 0; t < 2; t++) {
        int c4 = (t * 32 + lane) * 4;
        float4 z = *(const float4*)(zrow + c4);
        float4 w = *(const float4*)(W2 + c4);
        float zv[4] = {z.x, z.y, z.z, z.w};
        float wv[4] = {w.x, w.y, w.z, w.w};
#pragma unroll
        for (int qq = 0; qq < 4; qq++) {
            int c = c4 + qq;
            float mu  = g_sum[3 * HD + c] * (1.0f / NG);
            float var = fmaxf(g_sqs[3 * HD + c] * (1.0f / NG) - mu * mu, 0.f);
            float a   = g2[c] * rsqrtf(var + BN_EPS);
            float b   = bt2[c] - mu * a;
            s += fmaxf(fmaf(zv[qq], a, b), 0.f) * wv[qq];
        }
    }
#pragma unroll
    for (int o = 16; o > 0; o >>= 1) s += __shfl_xor_sync(0xffffffffu, s, o);
    if (lane == 0) out[g] = s + b2[0];
}

// ---------------- launch ----------------
extern "C" void kernel_launch(void* const* d_in, const int* in_sizes, int n_in,
                              void* d_out, int out_size)
{
    (void)in_sizes; (void)n_in; (void)out_size;
    const float* x        = (const float*)d_in[0];
    const int*   ei       = (const int*)d_in[1];
    const int*   batch    = (const int*)d_in[2];
    const float* W_emb    = (const float*)d_in[3];
    const float* b_emb    = (const float*)d_in[4];
    const float* W_conv   = (const float*)d_in[5];
    const float* b_conv   = (const float*)d_in[6];
    const float* bn_gamma = (const float*)d_in[7];
    const float* bn_beta  = (const float*)d_in[8];
    const float* W1       = (const float*)d_in[9];
    const float* b1       = (const float*)d_in[10];
    const float* g2       = (const float*)d_in[11];
    const float* bt2      = (const float*)d_in[12];
    const float* W2       = (const float*)d_in[13];
    const float* b2       = (const float*)d_in[14];
    float*       out      = (float*)d_out;

    const int* src = ei;
    const int* dst = ei + NE;

    float *p_h, *p_pool, *p_z, *p_beff;
    __half *p_uh;
    __nv_bfloat16 *p_Bh, *p_Bl;
    cudaGetSymbolAddress((void**)&p_h,    g_h);
    cudaGetSymbolAddress((void**)&p_uh,   g_uh);
    cudaGetSymbolAddress((void**)&p_pool, g_pool);
    cudaGetSymbolAddress((void**)&p_z,    g_z);
    cudaGetSymbolAddress((void**)&p_beff, g_beff);
    cudaGetSymbolAddress((void**)&p_Bh,   g_Bh);
    cudaGetSymbolAddress((void**)&p_Bl,   g_Bl);

    cudaFuncSetAttribute(mgemm<0,0>, cudaFuncAttributeMaxDynamicSharedMemorySize, MG_SMEM);
    cudaFuncSetAttribute(mgemm<1,1>, cudaFuncAttributeMaxDynamicSharedMemorySize, MG_SMEM);
    cudaFuncSetAttribute(mgemm<2,0>, cudaFuncAttributeMaxDynamicSharedMemorySize, MG_SMEM);

    // weight prep (inputs only): split conv1/conv2/W1; compute+split W_eff
    splitW_all_kernel<<<(WBIG + 255) / 256, 256>>>(W_conv, W1);
    weff_kernel<<<INC + 1, 256>>>(W_emb, W_conv, b_emb);

    // CSR setup (+ zero all 4 BN stat slices)
    zero_deg_kernel<<<(NN + 255) / 256, 256>>>();
    edge_deg_kernel<<<(NE + 255) / 256, 256>>>(dst);
    scan1_kernel<<<NB, 256>>>();
    scan2_kernel<<<1, 256>>>();
    scan3_kernel<<<NB, 256>>>();
    bucket_kernel<<<(NE + 255) / 256, 256>>>(src, dst);

    const dim3 GR(MPAD / 128, 2);   // 391 x 2

    // layer 0 (embedding fused): u0 = (x @ W_eff + b_eff) * dinv
    mgemm<2,0><<<GR, 256, MG_SMEM>>>(x, p_Bh + WOFF_EFF, p_Bl + WOFF_EFF,
                                     p_beff, p_uh, NN, INC,
                                     nullptr, nullptr, 0.f, 0);
    aggregate_kernel<<<(NN + 31) / 32, 256>>>(b_conv, 0);

    // layers 1..2 (BN of prev layer in mgemm prologue)
    for (int l = 1; l < 3; l++) {
        int woff = (l == 1) ? WOFF_C1 : WOFF_C2;
        mgemm<1,1><<<GR, 256, MG_SMEM>>>(p_h, p_Bh + woff, p_Bl + woff,
                                         nullptr, p_uh, NN, HD,
                                         bn_gamma + (size_t)(l - 1) * HD,
                                         bn_beta + (size_t)(l - 1) * HD,
                                         1.0f / NN, l - 1);
        aggregate_kernel<<<(NN + 31) / 32, 256>>>(b_conv + (size_t)l * HD, l);
    }

    // pooling (layer-2 BN+ReLU inline)
    pool_kernel<<<NG, HD>>>(batch, bn_gamma + 2 * HD, bn_beta + 2 * HD);

    // MLP head
    mgemm<0,0><<<dim3(NG / 128, 2), 256, MG_SMEM>>>(
        p_pool, p_Bh + WOFF_W1, p_Bl + WOFF_W1, b1, p_z, NG, HD,
        nullptr, nullptr, 0.f, 0);
    stats_cols_kernel<<<(NG + 63) / 64, 256>>>(p_z, NG, 3);
    head_kernel<<<(NG * 32 + 255) / 256, 256>>>(W2, b2, g2, bt2, out);
}

// round 16
// speedup vs baseline: 2.2116x; 1.0288x over previous
#include <cuda_runtime.h>
#include <cuda_bf16.h>
#include <cuda_fp16.h>
#include <cstdint>

#define NN 50000
#define MPAD 50048          // 391 * 128
#define NE 800000
#define INC 128
#define HD 256
#define NG 1024
#define BN_EPS 1e-5f
#define NB 196              // ceil(NN/256)

// weight-split buffer offsets (transposed [n][k] layout per matrix)
#define WOFF_EFF  0                 // W_eff = W_emb@W_conv0  (K=128)
#define WOFF_C1   32768             // conv layer 1 (K=256)
#define WOFF_C2   98304             // conv layer 2 (K=256)
#define WOFF_W1   163840            // MLP W1       (K=256)
#define WTOT      229376
#define WBIG      196608            // the 3 K=256 matrices

// ---------------- scratch (device globals: allocation-free) ----------------
__device__ int    g_deg[NN];
__device__ int    g_rowptr[NN];
__device__ int    g_cursor[NN];
__device__ int    g_bsum[NB];
__device__ int    g_srcs[NE];
__device__ float  g_dinv[NN];
__device__ float  g_h[(size_t)MPAD * HD];
__device__ __half g_uh[(size_t)MPAD * HD];
__device__ float  g_pool[NG * HD];
__device__ float  g_z[NG * HD];
__device__ float  g_sum[4 * HD];
__device__ float  g_sqs[4 * HD];
__device__ float  g_beff[HD];
__device__ __nv_bfloat16 g_Bh[WTOT];
__device__ __nv_bfloat16 g_Bl[WTOT];

// ---------------- setup ----------------
__global__ void zero_deg_kernel() {
    int i = blockIdx.x * blockDim.x + threadIdx.x;
    if (i < NN) g_deg[i] = 0;
    if (i < 4 * HD) { g_sum[i] = 0.f; g_sqs[i] = 0.f; }
}
// 4 edges per thread: MLP=4 hides DRAM latency
__global__ void __launch_bounds__(256) edge_deg_kernel(const int4* __restrict__ dst4) {
    int i = blockIdx.x * blockDim.x + threadIdx.x;
    if (i >= NE / 4) return;
    int4 d = dst4[i];
    atomicAdd(&g_deg[d.x], 1);
    atomicAdd(&g_deg[d.y], 1);
    atomicAdd(&g_deg[d.z], 1);
    atomicAdd(&g_deg[d.w], 1);
}
__global__ void scan1_kernel() {
    __shared__ int sh[256];
    int tid = threadIdx.x;
    int i = blockIdx.x * 256 + tid;
    int v = (i < NN) ? g_deg[i] : 0;
    sh[tid] = v;
    __syncthreads();
#pragma unroll
    for (int off = 1; off < 256; off <<= 1) {
        int t = (tid >= off) ? sh[tid - off] : 0;
        __syncthreads();
        sh[tid] += t;
        __syncthreads();
    }
    if (i < NN) g_rowptr[i] = sh[tid] - v;
    if (tid == 255) g_bsum[blockIdx.x] = sh[255];
}
__global__ void scan2_kernel() {
    __shared__ int sh[256];
    int tid = threadIdx.x;
    int v = (tid < NB) ? g_bsum[tid] : 0;
    sh[tid] = v;
    __syncthreads();
#pragma unroll
    for (int off = 1; off < 256; off <<= 1) {
        int t = (tid >= off) ? sh[tid - off] : 0;
        __syncthreads();
        sh[tid] += t;
        __syncthreads();
    }
    if (tid < NB) g_bsum[tid] = sh[tid] - v;
}
// scan3 + dinv + cursor-init merged (cursor starts at rowptr: bucket writes
// absolute slots, no rowptr load per edge)
__global__ void scan3_kernel() {
    int i = blockIdx.x * 256 + threadIdx.x;
    if (i < NN) {
        int rp = g_rowptr[i] + g_bsum[blockIdx.x];
        g_rowptr[i] = rp;
        g_cursor[i] = rp;
        g_dinv[i] = rsqrtf((float)(g_deg[i] + 1));
    }
}
// 4 edges per thread; cursor holds absolute positions
__global__ void __launch_bounds__(256) bucket_kernel(const int4* __restrict__ src4,
                                                     const int4* __restrict__ dst4) {
    int i = blockIdx.x * blockDim.x + threadIdx.x;
    if (i >= NE / 4) return;
    int4 s = src4[i];
    int4 d = dst4[i];
    g_srcs[atomicAdd(&g_cursor[d.x], 1)] = s.x;
    g_srcs[atomicAdd(&g_cursor[d.y], 1)] = s.y;
    g_srcs[atomicAdd(&g_cursor[d.z], 1)] = s.z;
    g_srcs[atomicAdd(&g_cursor[d.w], 1)] = s.w;
}

// ---- split + transpose the 3 K=256 weights (conv1, conv2, W1) ------------
__global__ void __launch_bounds__(256) splitW_all_kernel(
    const float* __restrict__ W_conv, const float* __restrict__ W1)
{
    int idx = blockIdx.x * 256 + threadIdx.x;
    if (idx >= WBIG) return;
    int m   = idx >> 16;          // 0,1 -> conv1/2 ; 2 -> W1
    int rem = idx & 65535;
    int k = rem >> 8;
    int n = rem & 255;
    const float* src = (m < 2) ? (W_conv + (size_t)(m + 1) * HD * HD) : W1;
    int doff = WOFF_C1 + m * 65536;
    float v = src[k * HD + n];
    __nv_bfloat16 h = __float2bfloat16(v);
    __nv_bfloat16 l = __float2bfloat16(v - __bfloat162float(h));
    g_Bh[doff + n * HD + k] = h;
    g_Bl[doff + n * HD + k] = l;
}

// ---- W_eff = W_emb @ W_conv0 (fp32), split into WOFF_EFF; b_eff = b_emb@W0
__global__ void __launch_bounds__(256) weff_kernel(
    const float* __restrict__ W_emb, const float* __restrict__ W0,
    const float* __restrict__ b_emb)
{
    int n = threadIdx.x;
    int k = blockIdx.x;
    if (k < INC) {
        float acc = 0.f;
        for (int c = 0; c < HD; c++)
            acc = fmaf(W_emb[k * HD + c], W0[c * HD + n], acc);
        __nv_bfloat16 h = __float2bfloat16(acc);
        __nv_bfloat16 l = __float2bfloat16(acc - __bfloat162float(h));
        g_Bh[WOFF_EFF + n * INC + k] = h;
        g_Bl[WOFF_EFF + n * INC + k] = l;
    } else {
        float acc = 0.f;
        for (int c = 0; c < HD; c++)
            acc = fmaf(b_emb[c], W0[c * HD + n], acc);
        g_beff[n] = acc;
    }
}

// -------- warp-MMA GEMM: C[M,256] = A'[M,K] @ (Bh+Bl)^T -------------------
__device__ __forceinline__ void mma16816(float* d,
    uint32_t a0, uint32_t a1, uint32_t a2, uint32_t a3,
    uint32_t b0, uint32_t b1)
{
    asm volatile(
        "mma.sync.aligned.m16n8k16.row.col.f32.bf16.bf16.f32 "
        "{%0,%1,%2,%3}, {%4,%5,%6,%7}, {%8,%9}, {%0,%1,%2,%3};"
        : "+f"(d[0]), "+f"(d[1]), "+f"(d[2]), "+f"(d[3])
        : "r"(a0), "r"(a1), "r"(a2), "r"(a3), "r"(b0), "r"(b1));
}
// packed rn conversion: {bf16(hi_y), bf16(hi_x)} in one cvt
__device__ __forceinline__ uint32_t bf16x2_rn(float y, float x) {
    uint32_t r;
    asm("cvt.rn.bf16x2.f32 %0, %1, %2;" : "=r"(r) : "f"(y), "f"(x));
    return r;
}

#define SROW 72
#define MG_TS (128 * SROW)
#define MG_SMEM (4 * MG_TS * 2)        // 73728 bytes dynamic

template <int EPI, int BN_IN>
__global__ void __launch_bounds__(256, 2) mgemm(
    const float* __restrict__ A,
    const __nv_bfloat16* __restrict__ Bh, const __nv_bfloat16* __restrict__ Bl,
    const float* __restrict__ bias, void* __restrict__ Cv, int M, int K,
    const float* __restrict__ gamma, const float* __restrict__ beta,
    float invN, int layer)
{
    extern __shared__ __nv_bfloat16 sm[];
    __nv_bfloat16* sAh = sm;
    __nv_bfloat16* sAl = sm + MG_TS;
    __nv_bfloat16* sBh = sm + 2 * MG_TS;
    __nv_bfloat16* sBl = sm + 3 * MG_TS;
    __shared__ float sbn[2 * HD];

    const int tid  = threadIdx.x;
    const int lane = tid & 31;
    const int warp = tid >> 5;
    const int wm   = warp & 3;
    const int wn   = warp >> 2;
    const int m0   = blockIdx.x * 128;
    const int n0   = blockIdx.y * 128;
    const int lr   = lane >> 2;
    const int lc   = (lane & 3) * 2;

    if (BN_IN) {
        if (tid < HD) {
            float mu  = g_sum[layer * HD + tid] * invN;
            float var = fmaxf(g_sqs[layer * HD + tid] * invN - mu * mu, 0.f);
            float a   = gamma[tid] * rsqrtf(var + BN_EPS);
            sbn[tid]      = a;
            sbn[HD + tid] = beta[tid] - mu * a;
        }
        __syncthreads();
    }

    float acc[2][8][4];
#pragma unroll
    for (int i = 0; i < 2; i++)
#pragma unroll
        for (int j = 0; j < 8; j++)
#pragma unroll
            for (int q = 0; q < 4; q++) acc[i][j][q] = 0.f;

    for (int k0 = 0; k0 < K; k0 += 64) {
#pragma unroll
        for (int t = 0; t < 8; t++) {
            int idx = tid + t * 256;
            int row = idx >> 4;
            int seg = idx & 15;
            int gcol = k0 + seg * 4;
            float4 v = make_float4(0.f, 0.f, 0.f, 0.f);
            if (m0 + row < M)
                v = *(const float4*)(A + (size_t)(m0 + row) * K + gcol);
            if (BN_IN) {
                float4 a = *(const float4*)&sbn[gcol];
                float4 b = *(const float4*)&sbn[HD + gcol];
                v.x = fmaxf(fmaf(v.x, a.x, b.x), 0.f);
                v.y = fmaxf(fmaf(v.y, a.y, b.y), 0.f);
                v.z = fmaxf(fmaf(v.z, a.z, b.z), 0.f);
                v.w = fmaxf(fmaf(v.w, a.w, b.w), 0.f);
            }
            // packed hi split (rn, identical rounding to scalar path)
            uint32_t h01 = bf16x2_rn(v.y, v.x);
            uint32_t h23 = bf16x2_rn(v.w, v.z);
            float hx = __uint_as_float(h01 << 16);
            float hy = __uint_as_float(h01 & 0xffff0000u);
            float hz = __uint_as_float(h23 << 16);
            float hw = __uint_as_float(h23 & 0xffff0000u);
            uint32_t l01 = bf16x2_rn(v.y - hy, v.x - hx);
            uint32_t l23 = bf16x2_rn(v.w - hw, v.z - hz);
            int so = row * SROW + seg * 4;
            *(uint32_t*)&sAh[so]     = h01;
            *(uint32_t*)&sAh[so + 2] = h23;
            *(uint32_t*)&sAl[so]     = l01;
            *(uint32_t*)&sAl[so + 2] = l23;
        }
#pragma unroll
        for (int t = 0; t < 4; t++) {
            int idx = tid + t * 256;
            int row = idx >> 3;
            int seg = idx & 7;
            size_t gb = (size_t)(n0 + row) * K + k0 + seg * 8;
            uint32_t so = row * (SROW * 2) + seg * 16;
            *(uint4*)((char*)sBh + so) = *(const uint4*)(Bh + gb);
            *(uint4*)((char*)sBl + so) = *(const uint4*)(Bl + gb);
        }
        __syncthreads();
#pragma unroll
        for (int ks = 0; ks < 4; ks++) {
            const int kk = ks * 16 + lc;
            uint32_t ah[2][4], al[2][4];
#pragma unroll
            for (int mi = 0; mi < 2; mi++) {
                int r = wm * 32 + mi * 16 + lr;
                ah[mi][0] = *(const uint32_t*)&sAh[r * SROW + kk];
                ah[mi][1] = *(const uint32_t*)&sAh[(r + 8) * SROW + kk];
                ah[mi][2] = *(const uint32_t*)&sAh[r * SROW + kk + 8];
                ah[mi][3] = *(const uint32_t*)&sAh[(r + 8) * SROW + kk + 8];
                al[mi][0] = *(const uint32_t*)&sAl[r * SROW + kk];
                al[mi][1] = *(const uint32_t*)&sAl[(r + 8) * SROW + kk];
                al[mi][2] = *(const uint32_t*)&sAl[r * SROW + kk + 8];
                al[mi][3] = *(const uint32_t*)&sAl[(r + 8) * SROW + kk + 8];
            }
#pragma unroll
            for (int ni = 0; ni < 8; ni++) {
                int n = wn * 64 + ni * 8 + lr;
                uint32_t b0 = *(const uint32_t*)&sBh[n * SROW + kk];
                uint32_t b1 = *(const uint32_t*)&sBh[n * SROW + kk + 8];
                uint32_t c0 = *(const uint32_t*)&sBl[n * SROW + kk];
                uint32_t c1 = *(const uint32_t*)&sBl[n * SROW + kk + 8];
#pragma unroll
                for (int mi = 0; mi < 2; mi++) {
                    mma16816(acc[mi][ni], ah[mi][0], ah[mi][1], ah[mi][2], ah[mi][3], b0, b1);
                    mma16816(acc[mi][ni], ah[mi][0], ah[mi][1], ah[mi][2], ah[mi][3], c0, c1);
                    mma16816(acc[mi][ni], al[mi][0], al[mi][1], al[mi][2], al[mi][3], b0, b1);
                }
            }
        }
        __syncthreads();
    }

    const int rb = m0 + wm * 32;
    const int cb = n0 + wn * 64;
#pragma unroll
    for (int mi = 0; mi < 2; mi++) {
#pragma unroll
        for (int half = 0; half < 2; half++) {
            int r = rb + mi * 16 + lr + half * 8;
            if (r >= M) continue;
            float sc = (EPI >= 1) ? g_dinv[r] : 0.f;
#pragma unroll
            for (int ni = 0; ni < 8; ni++) {
                int c = cb + ni * 8 + lc;
                float v0 = acc[mi][ni][half * 2 + 0];
                float v1 = acc[mi][ni][half * 2 + 1];
                if (EPI == 0) {
                    v0 += bias[c]; v1 += bias[c + 1];
                    *(float2*)((float*)Cv + (size_t)r * HD + c) = make_float2(v0, v1);
                } else {
                    if (EPI == 2) { v0 += bias[c]; v1 += bias[c + 1]; }
                    v0 *= sc; v1 *= sc;
                    *(__half2*)((__half*)Cv + (size_t)r * HD + c) =
                        __floats2half2_rn(v0, v1);
                }
            }
        }
    }
}

// ---- aggregation + fused BN stats: h[d] = (u[d]+sum u[src])*dinv + b -----
__global__ void __launch_bounds__(256) aggregate_kernel(
    const float* __restrict__ bias, int layer)
{
    __shared__ float ssum[HD];
    __shared__ float ssqs[HD];
    for (int i = threadIdx.x; i < HD; i += 256) { ssum[i] = 0.f; ssqs[i] = 0.f; }
    __syncthreads();

    int wp   = threadIdx.x >> 6;
    int half = (threadIdx.x >> 5) & 1;
    int lane = threadIdx.x & 31;
    int base = blockIdx.x * 32 + wp * 8;
    int coff = half * 32 + lane;

    const uint2* up = (const uint2*)g_uh;
    float4* hp = (float4*)g_h + half * 32;
    float4 bb = ((const float4*)bias)[half * 32 + lane];
    float4 s = make_float4(0, 0, 0, 0), q = s;

    for (int nidx = 0; nidx < 8; nidx++) {
        int node = base + nidx;
        if (node >= NN) break;
        uint2 raw = up[(size_t)node * 64 + coff];
        float2 f0 = __half22float2(*(__half2*)&raw.x);
        float2 f1 = __half22float2(*(__half2*)&raw.y);
        float4 a = make_float4(f0.x, f0.y, f1.x, f1.y);
        int beg = g_rowptr[node];
        int end = beg + g_deg[node];
        int j = beg;
        int n4 = beg + ((end - beg) & ~3);
        for (; j < n4; j += 4) {
            int s0 = g_srcs[j],     s1 = g_srcs[j + 1];
            int s2 = g_srcs[j + 2], s3 = g_srcs[j + 3];
            uint2 r0 = up[(size_t)s0 * 64 + coff];
            uint2 r1 = up[(size_t)s1 * 64 + coff];
            uint2 r2 = up[(size_t)s2 * 64 + coff];
            uint2 r3 = up[(size_t)s3 * 64 + coff];
            float2 p0 = __half22float2(*(__half2*)&r0.x);
            float2 p1 = __half22float2(*(__half2*)&r0.y);
            float2 p2 = __half22float2(*(__half2*)&r1.x);
            float2 p3 = __half22float2(*(__half2*)&r1.y);
            float2 p4 = __half22float2(*(__half2*)&r2.x);
            float2 p5 = __half22float2(*(__half2*)&r2.y);
            float2 p6 = __half22float2(*(__half2*)&r3.x);
            float2 p7 = __half22float2(*(__half2*)&r3.y);
            a.x += (p0.x + p2.x) + (p4.x + p6.x);
            a.y += (p0.y + p2.y) + (p4.y + p6.y);
            a.z += (p1.x + p3.x) + (p5.x + p7.x);
            a.w += (p1.y + p3.y) + (p5.y + p7.y);
        }
        for (; j < end; j++) {
            uint2 r0 = up[(size_t)g_srcs[j] * 64 + coff];
            float2 a0 = __half22float2(*(__half2*)&r0.x);
            float2 a1 = __half22float2(*(__half2*)&r0.y);
            a.x += a0.x; a.y += a0.y; a.z += a1.x; a.w += a1.y;
        }
        float dv = g_dinv[node];
        a.x = fmaf(a.x, dv, bb.x); a.y = fmaf(a.y, dv, bb.y);
        a.z = fmaf(a.z, dv, bb.z); a.w = fmaf(a.w, dv, bb.w);
        hp[(size_t)node * 64 + lane] = a;
        s.x += a.x; s.y += a.y; s.z += a.z; s.w += a.w;
        q.x += a.x*a.x; q.y += a.y*a.y; q.z += a.z*a.z; q.w += a.w*a.w;
    }

    int c = half * 128 + lane * 4;
    atomicAdd(&ssum[c+0], s.x); atomicAdd(&ssum[c+1], s.y);
    atomicAdd(&ssum[c+2], s.z); atomicAdd(&ssum[c+3], s.w);
    atomicAdd(&ssqs[c+0], q.x); atomicAdd(&ssqs[c+1], q.y);
    atomicAdd(&ssqs[c+2], q.z); atomicAdd(&ssqs[c+3], q.w);
    __syncthreads();
    atomicAdd(&g_sum[layer * HD + threadIdx.x], ssum[threadIdx.x]);
    atomicAdd(&g_sqs[layer * HD + threadIdx.x], ssqs[threadIdx.x]);
}

// ---------------- z stats ----------------
__global__ void __launch_bounds__(256) stats_cols_kernel(
    const float* __restrict__ X, int rows, int layer)
{
    int c  = threadIdx.x;
    int r0 = blockIdx.x * 64;
    int r1 = min(r0 + 64, rows);
    float s = 0.f, s2 = 0.f;
    for (int r = r0; r < r1; r++) {
        float v = X[(size_t)r * HD + c];
        s += v;
        s2 += v * v;
    }
    atomicAdd(&g_sum[layer * HD + c], s);
    atomicAdd(&g_sqs[layer * HD + c], s2);
}

// ---- pooling; applies layer-2 BN+ReLU computed inline from raw stats -----
__global__ void __launch_bounds__(256) pool_kernel(
    const int* __restrict__ batch,
    const float* __restrict__ gamma, const float* __restrict__ beta)
{
    int g = blockIdx.x;
    __shared__ int s_lo, s_hi;
    if (threadIdx.x < 2) {
        int key = g + threadIdx.x;
        int lo = 0, hi = NN;
        while (lo < hi) {
            int mid = (lo + hi) >> 1;
            if (batch[mid] < key) lo = mid + 1; else hi = mid;
        }
        if (threadIdx.x == 0) s_lo = lo; else s_hi = lo;
    }
    __syncthreads();
    int lo = s_lo, hi = s_hi;
    int c = threadIdx.x;
    float mu  = g_sum[2 * HD + c] * (1.0f / NN);
    float var = fmaxf(g_sqs[2 * HD + c] * (1.0f / NN) - mu * mu, 0.f);
    float a   = gamma[c] * rsqrtf(var + BN_EPS);
    float b   = beta[c] - mu * a;
    float s = 0.f;
    for (int r = lo; r < hi; r++)
        s += fmaxf(fmaf(g_h[(size_t)r * HD + c], a, b), 0.f);
    float cnt = (float)(hi - lo);
    g_pool[g * HD + c] = s / fmaxf(cnt, 1.f);
}

// ---- head with fused z-BN+ReLU -------------------------------------------
__global__ void __launch_bounds__(256) head_kernel(
    const float* __restrict__ W2, const float* __restrict__ b2,
    const float* __restrict__ g2, const float* __restrict__ bt2,
    float* __restrict__ out)
{
    int g    = (int)((blockIdx.x * 256 + threadIdx.x) >> 5);
    int lane = threadIdx.x & 31;
    if (g >= NG) return;
    const float* zrow = &g_z[(size_t)g * HD];
    float s = 0.f;
#pragma unroll
    for (int t = 0; t < 2; t++) {
        int c4 = (t * 32 + lane) * 4;
        float4 z = *(const float4*)(zrow + c4);
        float4 w = *(const float4*)(W2 + c4);
        float zv[4] = {z.x, z.y, z.z, z.w};
        float wv[4] = {w.x, w.y, w.z, w.w};
#pragma unroll
        for (int qq = 0; qq < 4; qq++) {
            int c = c4 + qq;
            float mu  = g_sum[3 * HD + c] * (1.0f / NG);
            float var = fmaxf(g_sqs[3 * HD + c] * (1.0f / NG) - mu * mu, 0.f);
            float a   = g2[c] * rsqrtf(var + BN_EPS);
            float b   = bt2[c] - mu * a;
            s += fmaxf(fmaf(zv[qq], a, b), 0.f) * wv[qq];
        }
    }
#pragma unroll
    for (int o = 16; o > 0; o >>= 1) s += __shfl_xor_sync(0xffffffffu, s, o);
    if (lane == 0) out[g] = s + b2[0];
}

// ---------------- launch ----------------
extern "C" void kernel_launch(void* const* d_in, const int* in_sizes, int n_in,
                              void* d_out, int out_size)
{
    (void)in_sizes; (void)n_in; (void)out_size;
    const float* x        = (const float*)d_in[0];
    const int*   ei       = (const int*)d_in[1];
    const int*   batch    = (const int*)d_in[2];
    const float* W_emb    = (const float*)d_in[3];
    const float* b_emb    = (const float*)d_in[4];
    const float* W_conv   = (const float*)d_in[5];
    const float* b_conv   = (const float*)d_in[6];
    const float* bn_gamma = (const float*)d_in[7];
    const float* bn_beta  = (const float*)d_in[8];
    const float* W1       = (const float*)d_in[9];
    const float* b1       = (const float*)d_in[10];
    const float* g2       = (const float*)d_in[11];
    const float* bt2      = (const float*)d_in[12];
    const float* W2       = (const float*)d_in[13];
    const float* b2       = (const float*)d_in[14];
    float*       out      = (float*)d_out;

    const int4* src4 = (const int4*)ei;
    const int4* dst4 = (const int4*)(ei + NE);

    float *p_h, *p_pool, *p_z, *p_beff;
    __half *p_uh;
    __nv_bfloat16 *p_Bh, *p_Bl;
    cudaGetSymbolAddress((void**)&p_h,    g_h);
    cudaGetSymbolAddress((void**)&p_uh,   g_uh);
    cudaGetSymbolAddress((void**)&p_pool, g_pool);
    cudaGetSymbolAddress((void**)&p_z,    g_z);
    cudaGetSymbolAddress((void**)&p_beff, g_beff);
    cudaGetSymbolAddress((void**)&p_Bh,   g_Bh);
    cudaGetSymbolAddress((void**)&p_Bl,   g_Bl);

    cudaFuncSetAttribute(mgemm<0,0>, cudaFuncAttributeMaxDynamicSharedMemorySize, MG_SMEM);
    cudaFuncSetAttribute(mgemm<1,1>, cudaFuncAttributeMaxDynamicSharedMemorySize, MG_SMEM);
    cudaFuncSetAttribute(mgemm<2,0>, cudaFuncAttributeMaxDynamicSharedMemorySize, MG_SMEM);

    // weight prep (inputs only)
    splitW_all_kernel<<<(WBIG + 255) / 256, 256>>>(W_conv, W1);
    weff_kernel<<<INC + 1, 256>>>(W_emb, W_conv, b_emb);

    // CSR setup
    zero_deg_kernel<<<(NN + 255) / 256, 256>>>();
    edge_deg_kernel<<<(NE / 4 + 255) / 256, 256>>>(dst4);
    scan1_kernel<<<NB, 256>>>();
    scan2_kernel<<<1, 256>>>();
    scan3_kernel<<<NB, 256>>>();
    bucket_kernel<<<(NE / 4 + 255) / 256, 256>>>(src4, dst4);

    const dim3 GR(MPAD / 128, 2);   // 391 x 2

    // layer 0 (embedding fused): u0 = (x @ W_eff + b_eff) * dinv
    mgemm<2,0><<<GR, 256, MG_SMEM>>>(x, p_Bh + WOFF_EFF, p_Bl + WOFF_EFF,
                                     p_beff, p_uh, NN, INC,
                                     nullptr, nullptr, 0.f, 0);
    aggregate_kernel<<<(NN + 31) / 32, 256>>>(b_conv, 0);

    // layers 1..2
    for (int l = 1; l < 3; l++) {
        int woff = (l == 1) ? WOFF_C1 : WOFF_C2;
        mgemm<1,1><<<GR, 256, MG_SMEM>>>(p_h, p_Bh + woff, p_Bl + woff,
                                         nullptr, p_uh, NN, HD,
                                         bn_gamma + (size_t)(l - 1) * HD,
                                         bn_beta + (size_t)(l - 1) * HD,
                                         1.0f / NN, l - 1);
        aggregate_kernel<<<(NN + 31) / 32, 256>>>(b_conv + (size_t)l * HD, l);
    }

    // pooling (layer-2 BN+ReLU inline)
    pool_kernel<<<NG, HD>>>(batch, bn_gamma + 2 * HD, bn_beta + 2 * HD);

    // MLP head
    mgemm<0,0><<<dim3(NG / 128, 2), 256, MG_SMEM>>>(
        p_pool, p_Bh + WOFF_W1, p_Bl + WOFF_W1, b1, p_z, NG, HD,
        nullptr, nullptr, 0.f, 0);
    stats_cols_kernel<<<(NG + 63) / 64, 256>>>(p_z, NG, 3);
    head_kernel<<<(NG * 32 + 255) / 256, 256>>>(W2, b2, g2, bt2, out);
}

// round 17
// speedup vs baseline: 2.2284x; 1.0076x over previous
#include <cuda_runtime.h>
#include <cuda_bf16.h>
#include <cuda_fp16.h>
#include <cstdint>

#define NN 50000
#define MPAD 50048          // 391 * 128
#define NE 800000
#define INC 128
#define HD 256
#define NG 1024
#define BN_EPS 1e-5f
#define NB 196              // ceil(NN/256)

// weight-split buffer offsets (transposed [n][k] layout per matrix)
#define WOFF_EFF  0                 // W_eff = W_emb@W_conv0  (K=128)
#define WOFF_C1   32768             // conv layer 1 (K=256)
#define WOFF_C2   98304             // conv layer 2 (K=256)
#define WOFF_W1   163840            // MLP W1       (K=256)
#define WTOT      229376
#define WBIG      196608            // the 3 K=256 matrices

// ---------------- scratch (device globals: allocation-free) ----------------
__device__ int    g_deg[NN];
__device__ int    g_rowptr[NN];
__device__ int    g_cursor[NN];
__device__ int    g_bsum[NB];
__device__ int    g_srcs[NE];
__device__ float  g_dinv[NN];
__device__ float  g_h[(size_t)MPAD * HD];
__device__ __half g_uh[(size_t)MPAD * HD];
__device__ float  g_pool[NG * HD];
__device__ float  g_z[NG * HD];
__device__ float  g_sum[4 * HD];
__device__ float  g_sqs[4 * HD];
__device__ float  g_beff[HD];
__device__ __nv_bfloat16 g_Bh[WTOT];
__device__ __nv_bfloat16 g_Bl[WTOT];

// ---------------- setup ----------------
__global__ void zero_deg_kernel() {
    int i = blockIdx.x * blockDim.x + threadIdx.x;
    if (i < NN) g_deg[i] = 0;
    if (i < 4 * HD) { g_sum[i] = 0.f; g_sqs[i] = 0.f; }
}
// 4 edges per thread
__global__ void __launch_bounds__(256) edge_deg_kernel(const int4* __restrict__ dst4) {
    int i = blockIdx.x * blockDim.x + threadIdx.x;
    if (i >= NE / 4) return;
    int4 d = dst4[i];
    atomicAdd(&g_deg[d.x], 1);
    atomicAdd(&g_deg[d.y], 1);
    atomicAdd(&g_deg[d.z], 1);
    atomicAdd(&g_deg[d.w], 1);
}
// early dinv: only needs deg -> unblocks the L0 GEMM before scans/bucket
__global__ void make_dinv_kernel() {
    int i = blockIdx.x * blockDim.x + threadIdx.x;
    if (i < NN) g_dinv[i] = rsqrtf((float)(g_deg[i] + 1));
}
__global__ void scan1_kernel() {
    __shared__ int sh[256];
    int tid = threadIdx.x;
    int i = blockIdx.x * 256 + tid;
    int v = (i < NN) ? g_deg[i] : 0;
    sh[tid] = v;
    __syncthreads();
#pragma unroll
    for (int off = 1; off < 256; off <<= 1) {
        int t = (tid >= off) ? sh[tid - off] : 0;
        __syncthreads();
        sh[tid] += t;
        __syncthreads();
    }
    if (i < NN) g_rowptr[i] = sh[tid] - v;
    if (tid == 255) g_bsum[blockIdx.x] = sh[255];
}
__global__ void scan2_kernel() {
    __shared__ int sh[256];
    int tid = threadIdx.x;
    int v = (tid < NB) ? g_bsum[tid] : 0;
    sh[tid] = v;
    __syncthreads();
#pragma unroll
    for (int off = 1; off < 256; off <<= 1) {
        int t = (tid >= off) ? sh[tid - off] : 0;
        __syncthreads();
        sh[tid] += t;
        __syncthreads();
    }
    if (tid < NB) g_bsum[tid] = sh[tid] - v;
}
// scan3 + cursor-init merged (cursor starts at rowptr -> absolute slots)
__global__ void scan3_kernel() {
    int i = blockIdx.x * 256 + threadIdx.x;
    if (i < NN) {
        int rp = g_rowptr[i] + g_bsum[blockIdx.x];
        g_rowptr[i] = rp;
        g_cursor[i] = rp;
    }
}
// 4 edges per thread; cursor holds absolute positions
__global__ void __launch_bounds__(256) bucket_kernel(const int4* __restrict__ src4,
                                                     const int4* __restrict__ dst4) {
    int i = blockIdx.x * blockDim.x + threadIdx.x;
    if (i >= NE / 4) return;
    int4 s = src4[i];
    int4 d = dst4[i];
    g_srcs[atomicAdd(&g_cursor[d.x], 1)] = s.x;
    g_srcs[atomicAdd(&g_cursor[d.y], 1)] = s.y;
    g_srcs[atomicAdd(&g_cursor[d.z], 1)] = s.z;
    g_srcs[atomicAdd(&g_cursor[d.w], 1)] = s.w;
}

// ---- split + transpose the 3 K=256 weights (conv1, conv2, W1) ------------
__global__ void __launch_bounds__(256) splitW_all_kernel(
    const float* __restrict__ W_conv, const float* __restrict__ W1)
{
    int idx = blockIdx.x * 256 + threadIdx.x;
    if (idx >= WBIG) return;
    int m   = idx >> 16;          // 0,1 -> conv1/2 ; 2 -> W1
    int rem = idx & 65535;
    int k = rem >> 8;
    int n = rem & 255;
    const float* src = (m < 2) ? (W_conv + (size_t)(m + 1) * HD * HD) : W1;
    int doff = WOFF_C1 + m * 65536;
    float v = src[k * HD + n];
    __nv_bfloat16 h = __float2bfloat16(v);
    __nv_bfloat16 l = __float2bfloat16(v - __bfloat162float(h));
    g_Bh[doff + n * HD + k] = h;
    g_Bl[doff + n * HD + k] = l;
}

// ---- W_eff = W_emb @ W_conv0 (fp32), split into WOFF_EFF; b_eff = b_emb@W0
__global__ void __launch_bounds__(256) weff_kernel(
    const float* __restrict__ W_emb, const float* __restrict__ W0,
    const float* __restrict__ b_emb)
{
    int n = threadIdx.x;
    int k = blockIdx.x;
    if (k < INC) {
        float acc = 0.f;
        for (int c = 0; c < HD; c++)
            acc = fmaf(W_emb[k * HD + c], W0[c * HD + n], acc);
        __nv_bfloat16 h = __float2bfloat16(acc);
        __nv_bfloat16 l = __float2bfloat16(acc - __bfloat162float(h));
        g_Bh[WOFF_EFF + n * INC + k] = h;
        g_Bl[WOFF_EFF + n * INC + k] = l;
    } else {
        float acc = 0.f;
        for (int c = 0; c < HD; c++)
            acc = fmaf(b_emb[c], W0[c * HD + n], acc);
        g_beff[n] = acc;
    }
}

// -------- warp-MMA GEMM: C[M,256] = A'[M,K] @ (Bh+Bl)^T -------------------
__device__ __forceinline__ void mma16816(float* d,
    uint32_t a0, uint32_t a1, uint32_t a2, uint32_t a3,
    uint32_t b0, uint32_t b1)
{
    asm volatile(
        "mma.sync.aligned.m16n8k16.row.col.f32.bf16.bf16.f32 "
        "{%0,%1,%2,%3}, {%4,%5,%6,%7}, {%8,%9}, {%0,%1,%2,%3};"
        : "+f"(d[0]), "+f"(d[1]), "+f"(d[2]), "+f"(d[3])
        : "r"(a0), "r"(a1), "r"(a2), "r"(a3), "r"(b0), "r"(b1));
}
__device__ __forceinline__ uint32_t bf16x2_rn(float y, float x) {
    uint32_t r;
    asm("cvt.rn.bf16x2.f32 %0, %1, %2;" : "=r"(r) : "f"(y), "f"(x));
    return r;
}

#define SROW 72
#define MG_TS (128 * SROW)
#define MG_SMEM (4 * MG_TS * 2)        // 73728 bytes dynamic

template <int EPI, int BN_IN>
__global__ void __launch_bounds__(256, 2) mgemm(
    const float* __restrict__ A,
    const __nv_bfloat16* __restrict__ Bh, const __nv_bfloat16* __restrict__ Bl,
    const float* __restrict__ bias, void* __restrict__ Cv, int M, int K,
    const float* __restrict__ gamma, const float* __restrict__ beta,
    float invN, int layer)
{
    extern __shared__ __nv_bfloat16 sm[];
    __nv_bfloat16* sAh = sm;
    __nv_bfloat16* sAl = sm + MG_TS;
    __nv_bfloat16* sBh = sm + 2 * MG_TS;
    __nv_bfloat16* sBl = sm + 3 * MG_TS;
    __shared__ float sbn[2 * HD];

    const int tid  = threadIdx.x;
    const int lane = tid & 31;
    const int warp = tid >> 5;
    const int wm   = warp & 3;
    const int wn   = warp >> 2;
    const int m0   = blockIdx.x * 128;
    const int n0   = blockIdx.y * 128;
    const int lr   = lane >> 2;
    const int lc   = (lane & 3) * 2;

    if (BN_IN) {
        if (tid < HD) {
            float mu  = g_sum[layer * HD + tid] * invN;
            float var = fmaxf(g_sqs[layer * HD + tid] * invN - mu * mu, 0.f);
            float a   = gamma[tid] * rsqrtf(var + BN_EPS);
            sbn[tid]      = a;
            sbn[HD + tid] = beta[tid] - mu * a;
        }
        __syncthreads();
    }

    float acc[2][8][4];
#pragma unroll
    for (int i = 0; i < 2; i++)
#pragma unroll
        for (int j = 0; j < 8; j++)
#pragma unroll
            for (int q = 0; q < 4; q++) acc[i][j][q] = 0.f;

    for (int k0 = 0; k0 < K; k0 += 64) {
#pragma unroll
        for (int t = 0; t < 8; t++) {
            int idx = tid + t * 256;
            int row = idx >> 4;
            int seg = idx & 15;
            int gcol = k0 + seg * 4;
            float4 v = make_float4(0.f, 0.f, 0.f, 0.f);
            if (m0 + row < M)
                v = *(const float4*)(A + (size_t)(m0 + row) * K + gcol);
            if (BN_IN) {
                float4 a = *(const float4*)&sbn[gcol];
                float4 b = *(const float4*)&sbn[HD + gcol];
                v.x = fmaxf(fmaf(v.x, a.x, b.x), 0.f);
                v.y = fmaxf(fmaf(v.y, a.y, b.y), 0.f);
                v.z = fmaxf(fmaf(v.z, a.z, b.z), 0.f);
                v.w = fmaxf(fmaf(v.w, a.w, b.w), 0.f);
            }
            uint32_t h01 = bf16x2_rn(v.y, v.x);
            uint32_t h23 = bf16x2_rn(v.w, v.z);
            float hx = __uint_as_float(h01 << 16);
            float hy = __uint_as_float(h01 & 0xffff0000u);
            float hz = __uint_as_float(h23 << 16);
            float hw = __uint_as_float(h23 & 0xffff0000u);
            uint32_t l01 = bf16x2_rn(v.y - hy, v.x - hx);
            uint32_t l23 = bf16x2_rn(v.w - hw, v.z - hz);
            int so = row * SROW + seg * 4;
            *(uint32_t*)&sAh[so]     = h01;
            *(uint32_t*)&sAh[so + 2] = h23;
            *(uint32_t*)&sAl[so]     = l01;
            *(uint32_t*)&sAl[so + 2] = l23;
        }
#pragma unroll
        for (int t = 0; t < 4; t++) {
            int idx = tid + t * 256;
            int row = idx >> 3;
            int seg = idx & 7;
            size_t gb = (size_t)(n0 + row) * K + k0 + seg * 8;
            uint32_t so = row * (SROW * 2) + seg * 16;
            *(uint4*)((char*)sBh + so) = *(const uint4*)(Bh + gb);
            *(uint4*)((char*)sBl + so) = *(const uint4*)(Bl + gb);
        }
        __syncthreads();
#pragma unroll
        for (int ks = 0; ks < 4; ks++) {
            const int kk = ks * 16 + lc;
            uint32_t ah[2][4], al[2][4];
#pragma unroll
            for (int mi = 0; mi < 2; mi++) {
                int r = wm * 32 + mi * 16 + lr;
                ah[mi][0] = *(const uint32_t*)&sAh[r * SROW + kk];
                ah[mi][1] = *(const uint32_t*)&sAh[(r + 8) * SROW + kk];
                ah[mi][2] = *(const uint32_t*)&sAh[r * SROW + kk + 8];
                ah[mi][3] = *(const uint32_t*)&sAh[(r + 8) * SROW + kk + 8];
                al[mi][0] = *(const uint32_t*)&sAl[r * SROW + kk];
                al[mi][1] = *(const uint32_t*)&sAl[(r + 8) * SROW + kk];
                al[mi][2] = *(const uint32_t*)&sAl[r * SROW + kk + 8];
                al[mi][3] = *(const uint32_t*)&sAl[(r + 8) * SROW + kk + 8];
            }
#pragma unroll
            for (int ni = 0; ni < 8; ni++) {
                int n = wn * 64 + ni * 8 + lr;
                uint32_t b0 = *(const uint32_t*)&sBh[n * SROW + kk];
                uint32_t b1 = *(const uint32_t*)&sBh[n * SROW + kk + 8];
                uint32_t c0 = *(const uint32_t*)&sBl[n * SROW + kk];
                uint32_t c1 = *(const uint32_t*)&sBl[n * SROW + kk + 8];
#pragma unroll
                for (int mi = 0; mi < 2; mi++) {
                    mma16816(acc[mi][ni], ah[mi][0], ah[mi][1], ah[mi][2], ah[mi][3], b0, b1);
                    mma16816(acc[mi][ni], ah[mi][0], ah[mi][1], ah[mi][2], ah[mi][3], c0, c1);
                    mma16816(acc[mi][ni], al[mi][0], al[mi][1], al[mi][2], al[mi][3], b0, b1);
                }
            }
        }
        __syncthreads();
    }

    const int rb = m0 + wm * 32;
    const int cb = n0 + wn * 64;
#pragma unroll
    for (int mi = 0; mi < 2; mi++) {
#pragma unroll
        for (int half = 0; half < 2; half++) {
            int r = rb + mi * 16 + lr + half * 8;
            if (r >= M) continue;
            float sc = (EPI >= 1) ? g_dinv[r] : 0.f;
#pragma unroll
            for (int ni = 0; ni < 8; ni++) {
                int c = cb + ni * 8 + lc;
                float v0 = acc[mi][ni][half * 2 + 0];
                float v1 = acc[mi][ni][half * 2 + 1];
                if (EPI == 0) {
                    v0 += bias[c]; v1 += bias[c + 1];
                    *(float2*)((float*)Cv + (size_t)r * HD + c) = make_float2(v0, v1);
                } else {
                    if (EPI == 2) { v0 += bias[c]; v1 += bias[c + 1]; }
                    v0 *= sc; v1 *= sc;
                    *(__half2*)((__half*)Cv + (size_t)r * HD + c) =
                        __floats2half2_rn(v0, v1);
                }
            }
        }
    }
}

// ---- aggregation + fused BN stats: h[d] = (u[d]+sum u[src])*dinv + b -----
__global__ void __launch_bounds__(256) aggregate_kernel(
    const float* __restrict__ bias, int layer)
{
    __shared__ float ssum[HD];
    __shared__ float ssqs[HD];
    for (int i = threadIdx.x; i < HD; i += 256) { ssum[i] = 0.f; ssqs[i] = 0.f; }
    __syncthreads();

    int wp   = threadIdx.x >> 6;
    int half = (threadIdx.x >> 5) & 1;
    int lane = threadIdx.x & 31;
    int base = blockIdx.x * 32 + wp * 8;
    int coff = half * 32 + lane;

    const uint2* up = (const uint2*)g_uh;
    float4* hp = (float4*)g_h + half * 32;
    float4 bb = ((const float4*)bias)[half * 32 + lane];
    float4 s = make_float4(0, 0, 0, 0), q = s;

    for (int nidx = 0; nidx < 8; nidx++) {
        int node = base + nidx;
        if (node >= NN) break;
        uint2 raw = up[(size_t)node * 64 + coff];
        float2 f0 = __half22float2(*(__half2*)&raw.x);
        float2 f1 = __half22float2(*(__half2*)&raw.y);
        float4 a = make_float4(f0.x, f0.y, f1.x, f1.y);
        int beg = g_rowptr[node];
        int end = beg + g_deg[node];
        int j = beg;
        int n4 = beg + ((end - beg) & ~3);
        for (; j < n4; j += 4) {
            int s0 = g_srcs[j],     s1 = g_srcs[j + 1];
            int s2 = g_srcs[j + 2], s3 = g_srcs[j + 3];
            uint2 r0 = up[(size_t)s0 * 64 + coff];
            uint2 r1 = up[(size_t)s1 * 64 + coff];
            uint2 r2 = up[(size_t)s2 * 64 + coff];
            uint2 r3 = up[(size_t)s3 * 64 + coff];
            float2 p0 = __half22float2(*(__half2*)&r0.x);
            float2 p1 = __half22float2(*(__half2*)&r0.y);
            float2 p2 = __half22float2(*(__half2*)&r1.x);
            float2 p3 = __half22float2(*(__half2*)&r1.y);
            float2 p4 = __half22float2(*(__half2*)&r2.x);
            float2 p5 = __half22float2(*(__half2*)&r2.y);
            float2 p6 = __half22float2(*(__half2*)&r3.x);
            float2 p7 = __half22float2(*(__half2*)&r3.y);
            a.x += (p0.x + p2.x) + (p4.x + p6.x);
            a.y += (p0.y + p2.y) + (p4.y + p6.y);
            a.z += (p1.x + p3.x) + (p5.x + p7.x);
            a.w += (p1.y + p3.y) + (p5.y + p7.y);
        }
        for (; j < end; j++) {
            uint2 r0 = up[(size_t)g_srcs[j] * 64 + coff];
            float2 a0 = __half22float2(*(__half2*)&r0.x);
            float2 a1 = __half22float2(*(__half2*)&r0.y);
            a.x += a0.x; a.y += a0.y; a.z += a1.x; a.w += a1.y;
        }
        float dv = g_dinv[node];
        a.x = fmaf(a.x, dv, bb.x); a.y = fmaf(a.y, dv, bb.y);
        a.z = fmaf(a.z, dv, bb.z); a.w = fmaf(a.w, dv, bb.w);
        hp[(size_t)node * 64 + lane] = a;
        s.x += a.x; s.y += a.y; s.z += a.z; s.w += a.w;
        q.x += a.x*a.x; q.y += a.y*a.y; q.z += a.z*a.z; q.w += a.w*a.w;
    }

    int c = half * 128 + lane * 4;
    atomicAdd(&ssum[c+0], s.x); atomicAdd(&ssum[c+1], s.y);
    atomicAdd(&ssum[c+2], s.z); atomicAdd(&ssum[c+3], s.w);
    atomicAdd(&ssqs[c+0], q.x); atomicAdd(&ssqs[c+1], q.y);
    atomicAdd(&ssqs[c+2], q.z); atomicAdd(&ssqs[c+3], q.w);
    __syncthreads();
    atomicAdd(&g_sum[layer * HD + threadIdx.x], ssum[threadIdx.x]);
    atomicAdd(&g_sqs[layer * HD + threadIdx.x], ssqs[threadIdx.x]);
}

// ---------------- z stats ----------------
__global__ void __launch_bounds__(256) stats_cols_kernel(
    const float* __restrict__ X, int rows, int layer)
{
    int c  = threadIdx.x;
    int r0 = blockIdx.x * 64;
    int r1 = min(r0 + 64, rows);
    float s = 0.f, s2 = 0.f;
    for (int r = r0; r < r1; r++) {
        float v = X[(size_t)r * HD + c];
        s += v;
        s2 += v * v;
    }
    atomicAdd(&g_sum[layer * HD + c], s);
    atomicAdd(&g_sqs[layer * HD + c], s2);
}

// ---- pooling; applies layer-2 BN+ReLU computed inline from raw stats -----
__global__ void __launch_bounds__(256) pool_kernel(
    const int* __restrict__ batch,
    const float* __restrict__ gamma, const float* __restrict__ beta)
{
    int g = blockIdx.x;
    __shared__ int s_lo, s_hi;
    if (threadIdx.x < 2) {
        int key = g + threadIdx.x;
        int lo = 0, hi = NN;
        while (lo < hi) {
            int mid = (lo + hi) >> 1;
            if (batch[mid] < key) lo = mid + 1; else hi = mid;
        }
        if (threadIdx.x == 0) s_lo = lo; else s_hi = lo;
    }
    __syncthreads();
    int lo = s_lo, hi = s_hi;
    int c = threadIdx.x;
    float mu  = g_sum[2 * HD + c] * (1.0f / NN);
    float var = fmaxf(g_sqs[2 * HD + c] * (1.0f / NN) - mu * mu, 0.f);
    float a   = gamma[c] * rsqrtf(var + BN_EPS);
    float b   = beta[c] - mu * a;
    float s = 0.f;
    for (int r = lo; r < hi; r++)
        s += fmaxf(fmaf(g_h[(size_t)r * HD + c], a, b), 0.f);
    float cnt = (float)(hi - lo);
    g_pool[g * HD + c] = s / fmaxf(cnt, 1.f);
}

// ---- head with fused z-BN+ReLU -------------------------------------------
__global__ void __launch_bounds__(256) head_kernel(
    const float* __restrict__ W2, const float* __restrict__ b2,
    const float* __restrict__ g2, const float* __restrict__ bt2,
    float* __restrict__ out)
{
    int g    = (int)((blockIdx.x * 256 + threadIdx.x) >> 5);
    int lane = threadIdx.x & 31;
    if (g >= NG) return;
    const float* zrow = &g_z[(size_t)g * HD];
    float s = 0.f;
#pragma unroll
    for (int t = 0; t < 2; t++) {
        int c4 = (t * 32 + lane) * 4;
        float4 z = *(const float4*)(zrow + c4);
        float4 w = *(const float4*)(W2 + c4);
        float zv[4] = {z.x, z.y, z.z, z.w};
        float wv[4] = {w.x, w.y, w.z, w.w};
#pragma unroll
        for (int qq = 0; qq < 4; qq++) {
            int c = c4 + qq;
            float mu  = g_sum[3 * HD + c] * (1.0f / NG);
            float var = fmaxf(g_sqs[3 * HD + c] * (1.0f / NG) - mu * mu, 0.f);
            float a   = g2[c] * rsqrtf(var + BN_EPS);
            float b   = bt2[c] - mu * a;
            s += fmaxf(fmaf(zv[qq], a, b), 0.f) * wv[qq];
        }
    }
#pragma unroll
    for (int o = 16; o > 0; o >>= 1) s += __shfl_xor_sync(0xffffffffu, s, o);
    if (lane == 0) out[g] = s + b2[0];
}

// ---------------- launch ----------------
extern "C" void kernel_launch(void* const* d_in, const int* in_sizes, int n_in,
                              void* d_out, int out_size)
{
    (void)in_sizes; (void)n_in; (void)out_size;
    const float* x        = (const float*)d_in[0];
    const int*   ei       = (const int*)d_in[1];
    const int*   batch    = (const int*)d_in[2];
    const float* W_emb    = (const float*)d_in[3];
    const float* b_emb    = (const float*)d_in[4];
    const float* W_conv   = (const float*)d_in[5];
    const float* b_conv   = (const float*)d_in[6];
    const float* bn_gamma = (const float*)d_in[7];
    const float* bn_beta  = (const float*)d_in[8];
    const float* W1       = (const float*)d_in[9];
    const float* b1       = (const float*)d_in[10];
    const float* g2       = (const float*)d_in[11];
    const float* bt2      = (const float*)d_in[12];
    const float* W2       = (const float*)d_in[13];
    const float* b2       = (const float*)d_in[14];
    float*       out      = (float*)d_out;

    const int4* src4 = (const int4*)ei;
    const int4* dst4 = (const int4*)(ei + NE);

    float *p_h, *p_pool, *p_z, *p_beff;
    __half *p_uh;
    __nv_bfloat16 *p_Bh, *p_Bl;
    cudaGetSymbolAddress((void**)&p_h,    g_h);
    cudaGetSymbolAddress((void**)&p_uh,   g_uh);
    cudaGetSymbolAddress((void**)&p_pool, g_pool);
    cudaGetSymbolAddress((void**)&p_z,    g_z);
    cudaGetSymbolAddress((void**)&p_beff, g_beff);
    cudaGetSymbolAddress((void**)&p_Bh,   g_Bh);
    cudaGetSymbolAddress((void**)&p_Bl,   g_Bl);

    cudaFuncSetAttribute(mgemm<0,0>, cudaFuncAttributeMaxDynamicSharedMemorySize, MG_SMEM);
    cudaFuncSetAttribute(mgemm<1,1>, cudaFuncAttributeMaxDynamicSharedMemorySize, MG_SMEM);
    cudaFuncSetAttribute(mgemm<2,0>, cudaFuncAttributeMaxDynamicSharedMemorySize, MG_SMEM);

    // persistent side stream + fork/join events (host-side resources only;
    // created once — captured work is identical on every call)
    static cudaStream_t s2 = nullptr;
    static cudaEvent_t evRoot = nullptr, evDinv = nullptr, evCsr = nullptr;
    if (!s2) {
        cudaStreamCreateWithFlags(&s2, cudaStreamNonBlocking);
        cudaEventCreateWithFlags(&evRoot, cudaEventDisableTiming);
        cudaEventCreateWithFlags(&evDinv, cudaEventDisableTiming);
        cudaEventCreateWithFlags(&evCsr, cudaEventDisableTiming);
    }

    // fork: CSR chain on side stream, weight prep + L0 GEMM on main
    cudaEventRecord(evRoot, 0);
    cudaStreamWaitEvent(s2, evRoot, 0);

    zero_deg_kernel<<<(NN + 255) / 256, 256, 0, s2>>>();
    edge_deg_kernel<<<(NE / 4 + 255) / 256, 256, 0, s2>>>(dst4);
    make_dinv_kernel<<<(NN + 255) / 256, 256, 0, s2>>>();
    cudaEventRecord(evDinv, s2);
    scan1_kernel<<<NB, 256, 0, s2>>>();
    scan2_kernel<<<1, 256, 0, s2>>>();
    scan3_kernel<<<NB, 256, 0, s2>>>();
    bucket_kernel<<<(NE / 4 + 255) / 256, 256, 0, s2>>>(src4, dst4);
    cudaEventRecord(evCsr, s2);

    // main: weight prep (independent of CSR chain)
    splitW_all_kernel<<<(WBIG + 255) / 256, 256>>>(W_conv, W1);
    weff_kernel<<<INC + 1, 256>>>(W_emb, W_conv, b_emb);

    const dim3 GR(MPAD / 128, 2);   // 391 x 2

    // layer 0 (embedding fused): u0 = (x @ W_eff + b_eff) * dinv
    cudaStreamWaitEvent(0, evDinv, 0);
    mgemm<2,0><<<GR, 256, MG_SMEM>>>(x, p_Bh + WOFF_EFF, p_Bl + WOFF_EFF,
                                     p_beff, p_uh, NN, INC,
                                     nullptr, nullptr, 0.f, 0);
    cudaStreamWaitEvent(0, evCsr, 0);   // join: CSR + stat-zero done
    aggregate_kernel<<<(NN + 31) / 32, 256>>>(b_conv, 0);

    // layers 1..2
    for (int l = 1; l < 3; l++) {
        int woff = (l == 1) ? WOFF_C1 : WOFF_C2;
        mgemm<1,1><<<GR, 256, MG_SMEM>>>(p_h, p_Bh + woff, p_Bl + woff,
                                         nullptr, p_uh, NN, HD,
                                         bn_gamma + (size_t)(l - 1) * HD,
                                         bn_beta + (size_t)(l - 1) * HD,
                                         1.0f / NN, l - 1);
        aggregate_kernel<<<(NN + 31) / 32, 256>>>(b_conv + (size_t)l * HD, l);
    }

    // pooling (layer-2 BN+ReLU inline)
    pool_kernel<<<NG, HD>>>(batch, bn_gamma + 2 * HD, bn_beta + 2 * HD);

    // MLP head
    mgemm<0,0><<<dim3(NG / 128, 2), 256, MG_SMEM>>>(
        p_pool, p_Bh + WOFF_W1, p_Bl + WOFF_W1, b1, p_z, NG, HD,
        nullptr, nullptr, 0.f, 0);
    stats_cols_kernel<<<(NG + 63) / 64, 256>>>(p_z, NG, 3);
    head_kernel<<<(NG * 32 + 255) / 256, 256>>>(W2, b2, g2, bt2, out);
}